// round 7
// baseline (speedup 1.0000x reference)
#include <cuda_runtime.h>
#include <cuda_bf16.h>
#include <cstdint>

#define Nn   50000
#define Ee   800000
#define F_IN 512
#define H1   256
#define H2   32
#define Cc   16

// ---------------- scratch (device globals; no allocations allowed) ----------
static __device__ float g_h1[(size_t)Nn * H1];
static __device__ float g_x2[(size_t)Nn * H1];
static __device__ float g_h2[(size_t)Nn * H2];
static __device__ float g_x3[(size_t)Nn * H2];
static __device__ float g_h3[(size_t)Nn * Cc];
static __device__ float g_dinv[Nn];
static __device__ int   g_deg[Nn];
static __device__ int   g_incl[Nn];
static __device__ int   g_rowstart[Nn];
static __device__ int   g_fill[Nn];
static __device__ int   g_col[Ee];
static __device__ int   g_blocksums[64];
static __device__ int   g_is64;
// W1^T split-bf16: [256 n][512 k] (K contiguous = mma "col" B layout)
static __device__ __nv_bfloat16 g_Bh[(size_t)H1 * F_IN];
static __device__ __nv_bfloat16 g_Bl[(size_t)H1 * F_IN];

// ---------------- helpers ----------------------------------------------------
__device__ __forceinline__ uint32_t smem_u32(const void* p) {
    uint32_t a;
    asm("{ .reg .u64 t; cvta.to.shared.u64 t, %1; cvt.u32.u64 %0, t; }" : "=r"(a) : "l"(p));
    return a;
}
__device__ __forceinline__ unsigned pack_bf2(float a, float b) {
    __nv_bfloat162 t(__float2bfloat16(a), __float2bfloat16(b));
    return *(unsigned*)&t;
}
__device__ __forceinline__ void ldm_x4(unsigned* r, uint32_t addr) {
    asm volatile("ldmatrix.sync.aligned.m8n8.x4.shared.b16 {%0,%1,%2,%3}, [%4];"
                 : "=r"(r[0]), "=r"(r[1]), "=r"(r[2]), "=r"(r[3]) : "r"(addr));
}
__device__ __forceinline__ void mma_bf16(float* c, const unsigned* a, const unsigned* b) {
    asm volatile(
        "mma.sync.aligned.m16n8k16.row.col.f32.bf16.bf16.f32 "
        "{%0,%1,%2,%3},{%4,%5,%6,%7},{%8,%9},{%0,%1,%2,%3};"
        : "+f"(c[0]), "+f"(c[1]), "+f"(c[2]), "+f"(c[3])
        : "r"(a[0]), "r"(a[1]), "r"(a[2]), "r"(a[3]), "r"(b[0]), "r"(b[1]));
}

// ---------------- edge-index dtype detection --------------------------------
__global__ void k_detect(const unsigned int* __restrict__ w) {
    if (threadIdx.x == 0 && blockIdx.x == 0) {
        int is64 = 1;
        for (int i = 1; i < 512; i += 2) {
            if (w[i] != 0u) { is64 = 0; break; }
        }
        g_is64 = is64;
    }
}
__device__ __forceinline__ int load_idx(const void* __restrict__ ei, long long idx) {
    if (g_is64) return (int)((const long long*)ei)[idx];
    return ((const int*)ei)[idx];
}

// ---------------- CSR build --------------------------------------------------
__global__ void k_zero_deg() {
    int i = blockIdx.x * blockDim.x + threadIdx.x;
    if (i < Nn) g_deg[i] = 0;
}
__global__ void k_count(const void* __restrict__ ei) {
    int e = blockIdx.x * blockDim.x + threadIdx.x;
    if (e < Ee) atomicAdd(&g_deg[load_idx(ei, (long long)Ee + e)], 1);
}
__global__ void k_scan1() {
    __shared__ int s[1024];
    int t = threadIdx.x;
    int i = blockIdx.x * 1024 + t;
    s[t] = (i < Nn) ? g_deg[i] : 0;
    __syncthreads();
    for (int off = 1; off < 1024; off <<= 1) {
        int add = (t >= off) ? s[t - off] : 0;
        __syncthreads();
        s[t] += add;
        __syncthreads();
    }
    if (i < Nn) g_incl[i] = s[t];
    if (t == 1023) g_blocksums[blockIdx.x] = s[1023];
}
__global__ void k_scan2(int nblocks) {
    if (threadIdx.x == 0) {
        int run = 0;
        for (int i = 0; i < nblocks; i++) { int v = g_blocksums[i]; g_blocksums[i] = run; run += v; }
    }
}
__global__ void k_scan3() {
    int i = blockIdx.x * blockDim.x + threadIdx.x;
    if (i < Nn) {
        int deg = g_deg[i];
        int start = g_incl[i] - deg + g_blocksums[i >> 10];
        g_rowstart[i] = start;
        g_fill[i] = start;
        g_dinv[i] = rsqrtf((float)(deg + 1));
    }
}
__global__ void k_scatter(const void* __restrict__ ei) {
    int e = blockIdx.x * blockDim.x + threadIdx.x;
    if (e < Ee) {
        int s = load_idx(ei, e);
        int d = load_idx(ei, (long long)Ee + e);
        int pos = atomicAdd(&g_fill[d], 1);
        g_col[pos] = s;
    }
}

// ---------------- W1 transpose + split-bf16 ----------------------------------
__global__ void k_cvtW(const float* __restrict__ W1) {
    int i = blockIdx.x * blockDim.x + threadIdx.x;
    if (i < F_IN * H1) {
        int k = i >> 8;
        int n = i & 255;
        float v = W1[i];
        __nv_bfloat16 h = __float2bfloat16(v);
        __nv_bfloat16 l = __float2bfloat16(v - __bfloat162float(h));
        g_Bh[(size_t)n * F_IN + k] = h;
        g_Bl[(size_t)n * F_IN + k] = l;
    }
}

// ---------------- GEMM1: mma.sync split-bf16, full-row blocks ----------------
// Block 128x256 (A staged ONCE), 512 threads = 16 warps (4x4), warp 32x64.
// K chunks of 64. Smem: [row][seg] 16B segs, phys seg = seg ^ (row&7).
#define SM1_AH 0
#define SM1_AL 16384
#define SM1_BH 32768
#define SM1_BL 65536
#define SM1_SZ 98304

__global__ void __launch_bounds__(512, 1) k_gemm1_mma(const float* __restrict__ A) {
    extern __shared__ char sm[];
    uint4* sAh = (uint4*)(sm + SM1_AH);
    uint4* sAl = (uint4*)(sm + SM1_AL);
    uint4* sBh = (uint4*)(sm + SM1_BH);
    uint4* sBl = (uint4*)(sm + SM1_BL);

    int tid = threadIdx.x;
    int wid = tid >> 5;
    int lane = tid & 31;
    int warp_m = wid & 3;           // 4 row slices of 32
    int warp_n = wid >> 2;          // 4 col slices of 64
    int row0 = blockIdx.x * 128;

    float acc[2][8][4];
#pragma unroll
    for (int mt = 0; mt < 2; mt++)
#pragma unroll
        for (int nt = 0; nt < 8; nt++)
#pragma unroll
            for (int q = 0; q < 4; q++) acc[mt][nt][q] = 0.f;

    uint32_t baseAh = smem_u32(sAh), baseAl = smem_u32(sAl);
    uint32_t baseBh = smem_u32(sBh), baseBl = smem_u32(sBl);

    for (int k0 = 0; k0 < F_IN; k0 += 64) {
        // stage A: 128 rows x 8 segs, fp32 -> hi/lo bf16 (done ONCE per chunk)
        for (int i = tid; i < 1024; i += 512) {
            int r = i >> 3;
            int seg = i & 7;
            int gr = row0 + r;
            if (gr >= Nn) gr = Nn - 1;
            const float4* p = (const float4*)(A + (size_t)gr * F_IN + k0 + seg * 8);
            float4 v0 = p[0], v1 = p[1];
            uint4 hi, lo;
            hi.x = pack_bf2(v0.x, v0.y); hi.y = pack_bf2(v0.z, v0.w);
            hi.z = pack_bf2(v1.x, v1.y); hi.w = pack_bf2(v1.z, v1.w);
            float lx = v0.x - __bfloat162float(__float2bfloat16(v0.x));
            float ly = v0.y - __bfloat162float(__float2bfloat16(v0.y));
            float lz = v0.z - __bfloat162float(__float2bfloat16(v0.z));
            float lw = v0.w - __bfloat162float(__float2bfloat16(v0.w));
            lo.x = pack_bf2(lx, ly); lo.y = pack_bf2(lz, lw);
            lx = v1.x - __bfloat162float(__float2bfloat16(v1.x));
            ly = v1.y - __bfloat162float(__float2bfloat16(v1.y));
            lz = v1.z - __bfloat162float(__float2bfloat16(v1.z));
            lw = v1.w - __bfloat162float(__float2bfloat16(v1.w));
            lo.z = pack_bf2(lx, ly); lo.w = pack_bf2(lz, lw);
            int ps = seg ^ (r & 7);
            sAh[r * 8 + ps] = hi;
            sAl[r * 8 + ps] = lo;
        }
        // stage B: all 256 n-rows x 8 segs (bf16 16B copies)
        for (int i = tid; i < 2048; i += 512) {
            int n = i >> 3;
            int seg = i & 7;
            size_t src = ((size_t)n * F_IN + k0 + seg * 8) * 2;
            int ps = seg ^ (n & 7);
            sBh[n * 8 + ps] = *(const uint4*)((const char*)g_Bh + src);
            sBl[n * 8 + ps] = *(const uint4*)((const char*)g_Bl + src);
        }
        __syncthreads();

#pragma unroll
        for (int s = 0; s < 4; s++) {
            unsigned ah[2][4], al[2][4];
#pragma unroll
            for (int mt = 0; mt < 2; mt++) {
                int q = lane >> 3;
                int r = warp_m * 32 + mt * 16 + (q & 1) * 8 + (lane & 7);
                int seg = s * 2 + (q >> 1);
                uint32_t off = (uint32_t)(r * 8 + (seg ^ (r & 7))) * 16;
                ldm_x4(ah[mt], baseAh + off);
                ldm_x4(al[mt], baseAl + off);
            }
#pragma unroll
            for (int jp = 0; jp < 4; jp++) {      // each jp = 2 n8-tiles
                unsigned bh4[4], bl4[4];
                int q = lane >> 3;
                int n = warp_n * 64 + (jp * 2 + (q >> 1)) * 8 + (lane & 7);
                int seg = s * 2 + (q & 1);
                uint32_t off = (uint32_t)(n * 8 + (seg ^ (n & 7))) * 16;
                ldm_x4(bh4, baseBh + off);
                ldm_x4(bl4, baseBl + off);
#pragma unroll
                for (int mt = 0; mt < 2; mt++) {
                    mma_bf16(acc[mt][jp * 2], ah[mt], &bh4[0]);
                    mma_bf16(acc[mt][jp * 2], ah[mt], &bl4[0]);
                    mma_bf16(acc[mt][jp * 2], al[mt], &bh4[0]);
                    mma_bf16(acc[mt][jp * 2 + 1], ah[mt], &bh4[2]);
                    mma_bf16(acc[mt][jp * 2 + 1], ah[mt], &bl4[2]);
                    mma_bf16(acc[mt][jp * 2 + 1], al[mt], &bh4[2]);
                }
            }
        }
        __syncthreads();
    }

    // epilogue
#pragma unroll
    for (int mt = 0; mt < 2; mt++)
#pragma unroll
        for (int nt = 0; nt < 8; nt++) {
            int r = row0 + warp_m * 32 + mt * 16 + (lane >> 2);
            int col = warp_n * 64 + nt * 8 + (lane & 3) * 2;
            if (r < Nn)
                *(float2*)(g_h1 + (size_t)r * H1 + col) =
                    make_float2(acc[mt][nt][0], acc[mt][nt][1]);
            if (r + 8 < Nn)
                *(float2*)(g_h1 + (size_t)(r + 8) * H1 + col) =
                    make_float2(acc[mt][nt][2], acc[mt][nt][3]);
        }
}

// ---------------- GEMM2: g_x2 [Nn,256] x W2 [256,32] -> g_h2 ----------------
__global__ void k_gemm2(const float* __restrict__ W) {
    __shared__ float sA[32][64];
    __shared__ float sW[64][32];
    int tid = threadIdx.x;
    int r = tid >> 3;
    int c4 = (tid & 7) * 4;
    int row0 = blockIdx.x * 32;
    float acc[4] = {0.f, 0.f, 0.f, 0.f};
    for (int k0 = 0; k0 < H1; k0 += 64) {
        for (int i = tid; i < 32 * 16; i += 256) {
            int rr = i >> 4;
            int kk4 = (i & 15) * 4;
            int grow = row0 + rr;
            float4 v = make_float4(0.f, 0.f, 0.f, 0.f);
            if (grow < Nn) v = *(const float4*)(g_x2 + (size_t)grow * H1 + k0 + kk4);
            *(float4*)(&sA[rr][kk4]) = v;
        }
        for (int i = tid; i < 512; i += 256) {
            int kk = i >> 3;
            int cc4 = (i & 7) * 4;
            *(float4*)(&sW[kk][cc4]) = *(const float4*)(W + (size_t)(k0 + kk) * H2 + cc4);
        }
        __syncthreads();
#pragma unroll
        for (int kk = 0; kk < 64; kk++) {
            float a = sA[r][kk];
            acc[0] += a * sW[kk][c4 + 0];
            acc[1] += a * sW[kk][c4 + 1];
            acc[2] += a * sW[kk][c4 + 2];
            acc[3] += a * sW[kk][c4 + 3];
        }
        __syncthreads();
    }
    int row = row0 + r;
    if (row < Nn) {
        float4 v = make_float4(acc[0], acc[1], acc[2], acc[3]);
        *(float4*)(g_h2 + (size_t)row * H2 + c4) = v;
    }
}

// ---------------- GEMM3: g_x3 [Nn,32] x W3 [32,16] -> g_h3 ------------------
__global__ void k_gemm3(const float* __restrict__ W) {
    __shared__ float sW[32 * 16];
    int tid = threadIdx.x;
    for (int i = tid; i < 32 * 16; i += 256) sW[i] = W[i];
    __syncthreads();
    int row = blockIdx.x * 256 + tid;
    if (row >= Nn) return;
    float acc[16];
#pragma unroll
    for (int c = 0; c < 16; c++) acc[c] = 0.f;
    const float4* ap = (const float4*)(g_x3 + (size_t)row * H2);
#pragma unroll
    for (int k4 = 0; k4 < 8; k4++) {
        float4 a = ap[k4];
        int k = k4 * 4;
#pragma unroll
        for (int c = 0; c < 16; c++) {
            acc[c] += a.x * sW[(k + 0) * 16 + c];
            acc[c] += a.y * sW[(k + 1) * 16 + c];
            acc[c] += a.z * sW[(k + 2) * 16 + c];
            acc[c] += a.w * sW[(k + 3) * 16 + c];
        }
    }
    float* op = g_h3 + (size_t)row * Cc;
#pragma unroll
    for (int c4 = 0; c4 < 4; c4++) {
        float4 v = make_float4(acc[c4 * 4 + 0], acc[c4 * 4 + 1], acc[c4 * 4 + 2], acc[c4 * 4 + 3]);
        *(float4*)(op + c4 * 4) = v;
    }
}

// ---------------- Aggregation ------------------------------------------------
__global__ void k_agg256(const float* __restrict__ bias) {
    int warp = threadIdx.x >> 5;
    int lane = threadIdx.x & 31;
    int node = blockIdx.x * 8 + warp;
    if (node >= Nn) return;
    float wd = g_dinv[node];
    const float4* hp = (const float4*)(g_h1 + (size_t)node * 256);
    float4 a0 = hp[lane];
    float4 a1 = hp[32 + lane];
    float4 acc0 = make_float4(a0.x * wd, a0.y * wd, a0.z * wd, a0.w * wd);
    float4 acc1 = make_float4(a1.x * wd, a1.y * wd, a1.z * wd, a1.w * wd);
    int beg = g_rowstart[node];
    int cnt = g_deg[node];
    for (int j = 0; j < cnt; j++) {
        int s = g_col[beg + j];
        float w = g_dinv[s];
        const float4* sp = (const float4*)(g_h1 + (size_t)s * 256);
        float4 v0 = sp[lane];
        float4 v1 = sp[32 + lane];
        acc0.x += w * v0.x; acc0.y += w * v0.y; acc0.z += w * v0.z; acc0.w += w * v0.w;
        acc1.x += w * v1.x; acc1.y += w * v1.y; acc1.z += w * v1.z; acc1.w += w * v1.w;
    }
    float4 b0 = ((const float4*)bias)[lane];
    float4 b1 = ((const float4*)bias)[32 + lane];
    float4 r0 = make_float4(fmaxf(acc0.x * wd + b0.x, 0.f), fmaxf(acc0.y * wd + b0.y, 0.f),
                            fmaxf(acc0.z * wd + b0.z, 0.f), fmaxf(acc0.w * wd + b0.w, 0.f));
    float4 r1 = make_float4(fmaxf(acc1.x * wd + b1.x, 0.f), fmaxf(acc1.y * wd + b1.y, 0.f),
                            fmaxf(acc1.z * wd + b1.z, 0.f), fmaxf(acc1.w * wd + b1.w, 0.f));
    float4* op = (float4*)(g_x2 + (size_t)node * 256);
    op[lane] = r0;
    op[32 + lane] = r1;
}

__global__ void k_agg32(const float* __restrict__ bias) {
    int warp = threadIdx.x >> 5;
    int lane = threadIdx.x & 31;
    int node = blockIdx.x * 8 + warp;
    if (node >= Nn) return;
    float wd = g_dinv[node];
    float acc = wd * g_h2[(size_t)node * 32 + lane];
    int beg = g_rowstart[node];
    int cnt = g_deg[node];
    for (int j = 0; j < cnt; j++) {
        int s = g_col[beg + j];
        acc += g_dinv[s] * g_h2[(size_t)s * 32 + lane];
    }
    float r = acc * wd + bias[lane];
    g_x3[(size_t)node * 32 + lane] = fmaxf(r, 0.f);
}

__global__ void k_agg16(const float* __restrict__ bias, float* __restrict__ out) {
    int tid = threadIdx.x;
    int local = tid & 15;
    int node = blockIdx.x * 16 + (tid >> 4);
    if (node >= Nn) return;
    float wd = g_dinv[node];
    float acc = wd * g_h3[(size_t)node * 16 + local];
    int beg = g_rowstart[node];
    int cnt = g_deg[node];
    for (int j = 0; j < cnt; j++) {
        int s = g_col[beg + j];
        acc += g_dinv[s] * g_h3[(size_t)s * 16 + local];
    }
    out[(size_t)node * 16 + local] = acc * wd + bias[local];
}

// ---------------- launch -----------------------------------------------------
extern "C" void kernel_launch(void* const* d_in, const int* in_sizes, int n_in,
                              void* d_out, int out_size) {
    const float* x   = (const float*)d_in[0];
    const void*  ei  = (const void*)d_in[1];
    const float* W1  = (const float*)d_in[2];
    const float* b1  = (const float*)d_in[3];
    const float* W2  = (const float*)d_in[4];
    const float* b2  = (const float*)d_in[5];
    const float* W3  = (const float*)d_in[6];
    const float* b3  = (const float*)d_in[7];
    float* out       = (float*)d_out;

    cudaFuncSetAttribute(k_gemm1_mma, cudaFuncAttributeMaxDynamicSharedMemorySize, SM1_SZ);

    const int scanBlocks = (Nn + 1023) / 1024;   // 49

    k_detect<<<1, 32>>>((const unsigned int*)ei);
    k_zero_deg<<<(Nn + 255) / 256, 256>>>();
    k_count<<<(Ee + 255) / 256, 256>>>(ei);
    k_scan1<<<scanBlocks, 1024>>>();
    k_scan2<<<1, 32>>>(scanBlocks);
    k_scan3<<<(Nn + 255) / 256, 256>>>();
    k_scatter<<<(Ee + 255) / 256, 256>>>(ei);

    // Layer 1 (HMMA split-bf16, full-row blocks)
    k_cvtW<<<(F_IN * H1 + 255) / 256, 256>>>(W1);
    k_gemm1_mma<<<(Nn + 127) / 128, 512, SM1_SZ>>>(x);
    k_agg256<<<(Nn + 7) / 8, 256>>>(b1);

    // Layer 2
    k_gemm2<<<(Nn + 31) / 32, 256>>>(W2);
    k_agg32<<<(Nn + 7) / 8, 256>>>(b2);

    // Layer 3
    k_gemm3<<<(Nn + 255) / 256, 256>>>(W3);
    k_agg16<<<(Nn + 15) / 16, 256>>>(b3, out);
}

// round 8
// speedup vs baseline: 1.1379x; 1.1379x over previous
#include <cuda_runtime.h>
#include <cuda_bf16.h>
#include <cstdint>

#define Nn   50000
#define Ee   800000
#define F_IN 512
#define H1   256
#define H2   32
#define Cc   16

// ---------------- scratch (device globals; no allocations allowed) ----------
static __device__ float g_h1[(size_t)Nn * H1];
static __device__ float g_x2[(size_t)Nn * H1];
static __device__ float g_h2[(size_t)Nn * H2];
static __device__ float g_x3[(size_t)Nn * H2];
static __device__ float g_h3[(size_t)Nn * Cc];
static __device__ float g_dinv[Nn];
static __device__ int   g_deg[Nn];
static __device__ int   g_incl[Nn];
static __device__ int   g_rowstart[Nn];
static __device__ int   g_fill[Nn];
static __device__ int   g_col[Ee];
static __device__ int   g_blocksums[64];
static __device__ int   g_is64;
// W1^T split-bf16: [256 n][512 k] (K contiguous = mma "col" B layout)
static __device__ __nv_bfloat16 g_Bh[(size_t)H1 * F_IN];
static __device__ __nv_bfloat16 g_Bl[(size_t)H1 * F_IN];

// ---------------- helpers ----------------------------------------------------
__device__ __forceinline__ uint32_t smem_u32(const void* p) {
    uint32_t a;
    asm("{ .reg .u64 t; cvta.to.shared.u64 t, %1; cvt.u32.u64 %0, t; }" : "=r"(a) : "l"(p));
    return a;
}
__device__ __forceinline__ unsigned pack_bf2(float a, float b) {
    __nv_bfloat162 t(__float2bfloat16(a), __float2bfloat16(b));
    return *(unsigned*)&t;
}
__device__ __forceinline__ void ldm_x4(unsigned* r, uint32_t addr) {
    asm volatile("ldmatrix.sync.aligned.m8n8.x4.shared.b16 {%0,%1,%2,%3}, [%4];"
                 : "=r"(r[0]), "=r"(r[1]), "=r"(r[2]), "=r"(r[3]) : "r"(addr));
}
__device__ __forceinline__ void mma_bf16(float* c, const unsigned* a, const unsigned* b) {
    asm volatile(
        "mma.sync.aligned.m16n8k16.row.col.f32.bf16.bf16.f32 "
        "{%0,%1,%2,%3},{%4,%5,%6,%7},{%8,%9},{%0,%1,%2,%3};"
        : "+f"(c[0]), "+f"(c[1]), "+f"(c[2]), "+f"(c[3])
        : "r"(a[0]), "r"(a[1]), "r"(a[2]), "r"(a[3]), "r"(b[0]), "r"(b[1]));
}
__device__ __forceinline__ void cpa16(uint32_t dst, const void* src) {
    asm volatile("cp.async.cg.shared.global [%0], [%1], 16;" :: "r"(dst), "l"(src));
}
#define CPA_COMMIT() asm volatile("cp.async.commit_group;" ::: "memory")
#define CPA_WAIT1()  asm volatile("cp.async.wait_group 1;" ::: "memory")

// ---------------- edge-index dtype detection --------------------------------
__global__ void k_detect(const unsigned int* __restrict__ w) {
    if (threadIdx.x == 0 && blockIdx.x == 0) {
        int is64 = 1;
        for (int i = 1; i < 512; i += 2) {
            if (w[i] != 0u) { is64 = 0; break; }
        }
        g_is64 = is64;
    }
}
__device__ __forceinline__ int load_idx(const void* __restrict__ ei, long long idx) {
    if (g_is64) return (int)((const long long*)ei)[idx];
    return ((const int*)ei)[idx];
}

// ---------------- CSR build --------------------------------------------------
__global__ void k_zero_deg() {
    int i = blockIdx.x * blockDim.x + threadIdx.x;
    if (i < Nn) g_deg[i] = 0;
}
__global__ void k_count(const void* __restrict__ ei) {
    int e = blockIdx.x * blockDim.x + threadIdx.x;
    if (e < Ee) atomicAdd(&g_deg[load_idx(ei, (long long)Ee + e)], 1);
}
__global__ void k_scan1() {
    __shared__ int s[1024];
    int t = threadIdx.x;
    int i = blockIdx.x * 1024 + t;
    s[t] = (i < Nn) ? g_deg[i] : 0;
    __syncthreads();
    for (int off = 1; off < 1024; off <<= 1) {
        int add = (t >= off) ? s[t - off] : 0;
        __syncthreads();
        s[t] += add;
        __syncthreads();
    }
    if (i < Nn) g_incl[i] = s[t];
    if (t == 1023) g_blocksums[blockIdx.x] = s[1023];
}
__global__ void k_scan2(int nblocks) {
    if (threadIdx.x == 0) {
        int run = 0;
        for (int i = 0; i < nblocks; i++) { int v = g_blocksums[i]; g_blocksums[i] = run; run += v; }
    }
}
__global__ void k_scan3() {
    int i = blockIdx.x * blockDim.x + threadIdx.x;
    if (i < Nn) {
        int deg = g_deg[i];
        int start = g_incl[i] - deg + g_blocksums[i >> 10];
        g_rowstart[i] = start;
        g_fill[i] = start;
        g_dinv[i] = rsqrtf((float)(deg + 1));
    }
}
__global__ void k_scatter(const void* __restrict__ ei) {
    int e = blockIdx.x * blockDim.x + threadIdx.x;
    if (e < Ee) {
        int s = load_idx(ei, e);
        int d = load_idx(ei, (long long)Ee + e);
        int pos = atomicAdd(&g_fill[d], 1);
        g_col[pos] = s;
    }
}

// ---------------- W1 transpose + split-bf16 ----------------------------------
__global__ void k_cvtW(const float* __restrict__ W1) {
    int i = blockIdx.x * blockDim.x + threadIdx.x;
    if (i < F_IN * H1) {
        int k = i >> 8;
        int n = i & 255;
        float v = W1[i];
        __nv_bfloat16 h = __float2bfloat16(v);
        __nv_bfloat16 l = __float2bfloat16(v - __bfloat162float(h));
        g_Bh[(size_t)n * F_IN + k] = h;
        g_Bl[(size_t)n * F_IN + k] = l;
    }
}

// ---------------- GEMM1: mma.sync split-bf16, double-buffered ---------------
// Block 128x256, 512 threads = 16 warps (4x4), warp 32x64. K chunks of 64,
// 2-stage pipeline: B via cp.async, A prefetched to regs / stored after MMA.
// Stage layout (96KB): AH[16K] AL[16K] BH[32K] BL[32K].
#define ST_AH 0
#define ST_AL 16384
#define ST_BH 32768
#define ST_BL 65536
#define ST_SZ 98304
#define SM1_SZ (2 * ST_SZ)

struct APref { float4 v[2][2]; };   // [j][half]

__device__ __forceinline__ void loadA_regs(const float* __restrict__ A, int row0,
                                           int k0, int tid, APref& ap) {
#pragma unroll
    for (int j = 0; j < 2; j++) {
        int i = tid + j * 512;
        int r = i >> 3;
        int seg = i & 7;
        int gr = row0 + r;
        if (gr >= Nn) gr = Nn - 1;
        const float4* p = (const float4*)(A + (size_t)gr * F_IN + k0 + seg * 8);
        ap.v[j][0] = p[0];
        ap.v[j][1] = p[1];
    }
}
__device__ __forceinline__ void storeA_smem(char* sm, int boff, int tid, const APref& ap) {
#pragma unroll
    for (int j = 0; j < 2; j++) {
        int i = tid + j * 512;
        int r = i >> 3;
        int seg = i & 7;
        float4 v0 = ap.v[j][0], v1 = ap.v[j][1];
        uint4 hi, lo;
        hi.x = pack_bf2(v0.x, v0.y); hi.y = pack_bf2(v0.z, v0.w);
        hi.z = pack_bf2(v1.x, v1.y); hi.w = pack_bf2(v1.z, v1.w);
        float lx = v0.x - __bfloat162float(__float2bfloat16(v0.x));
        float ly = v0.y - __bfloat162float(__float2bfloat16(v0.y));
        float lz = v0.z - __bfloat162float(__float2bfloat16(v0.z));
        float lw = v0.w - __bfloat162float(__float2bfloat16(v0.w));
        lo.x = pack_bf2(lx, ly); lo.y = pack_bf2(lz, lw);
        lx = v1.x - __bfloat162float(__float2bfloat16(v1.x));
        ly = v1.y - __bfloat162float(__float2bfloat16(v1.y));
        lz = v1.z - __bfloat162float(__float2bfloat16(v1.z));
        lw = v1.w - __bfloat162float(__float2bfloat16(v1.w));
        lo.z = pack_bf2(lx, ly); lo.w = pack_bf2(lz, lw);
        int ps = seg ^ (r & 7);
        *(uint4*)(sm + boff + ST_AH + (r * 8 + ps) * 16) = hi;
        *(uint4*)(sm + boff + ST_AL + (r * 8 + ps) * 16) = lo;
    }
}
__device__ __forceinline__ void issueB_cpasync(uint32_t sbase, int boff, int k0, int tid) {
#pragma unroll
    for (int j = 0; j < 4; j++) {
        int i = tid + j * 512;       // 0..2047
        int n = i >> 3;
        int seg = i & 7;
        int ps = seg ^ (n & 7);
        size_t src = ((size_t)n * F_IN + k0 + seg * 8) * 2;
        uint32_t doff = (uint32_t)((n * 8 + ps) * 16);
        cpa16(sbase + boff + ST_BH + doff, (const char*)g_Bh + src);
        cpa16(sbase + boff + ST_BL + doff, (const char*)g_Bl + src);
    }
}

__global__ void __launch_bounds__(512, 1) k_gemm1_mma(const float* __restrict__ A) {
    extern __shared__ char sm[];
    uint32_t sbase = smem_u32(sm);
    int tid = threadIdx.x;
    int wid = tid >> 5;
    int lane = tid & 31;
    int warp_m = wid & 3;
    int warp_n = wid >> 2;
    int row0 = blockIdx.x * 128;

    float acc[2][8][4];
#pragma unroll
    for (int mt = 0; mt < 2; mt++)
#pragma unroll
        for (int nt = 0; nt < 8; nt++)
#pragma unroll
            for (int q = 0; q < 4; q++) acc[mt][nt][q] = 0.f;

    // prologue: stage chunk 0 into buf 0
    APref ap;
    loadA_regs(A, row0, 0, tid, ap);
    issueB_cpasync(sbase, 0, 0, tid);
    CPA_COMMIT();
    storeA_smem(sm, 0, tid, ap);

#pragma unroll 1
    for (int ck = 0; ck < 8; ck++) {
        int cur = ck & 1;
        int boff_cur = cur * ST_SZ;
        int boff_nxt = (cur ^ 1) * ST_SZ;
        if (ck < 7) {
            loadA_regs(A, row0, (ck + 1) * 64, tid, ap);
            issueB_cpasync(sbase, boff_nxt, (ck + 1) * 64, tid);
        }
        CPA_COMMIT();          // empty group on last iter keeps counts aligned
        CPA_WAIT1();           // B(ck) arrived
        __syncthreads();       // A(ck) stores visible to all warps

        uint32_t baseAh = sbase + boff_cur + ST_AH;
        uint32_t baseAl = sbase + boff_cur + ST_AL;
        uint32_t baseBh = sbase + boff_cur + ST_BH;
        uint32_t baseBl = sbase + boff_cur + ST_BL;
#pragma unroll
        for (int s = 0; s < 4; s++) {
            unsigned ah[2][4], al[2][4];
#pragma unroll
            for (int mt = 0; mt < 2; mt++) {
                int q = lane >> 3;
                int r = warp_m * 32 + mt * 16 + (q & 1) * 8 + (lane & 7);
                int seg = s * 2 + (q >> 1);
                uint32_t off = (uint32_t)(r * 8 + (seg ^ (r & 7))) * 16;
                ldm_x4(ah[mt], baseAh + off);
                ldm_x4(al[mt], baseAl + off);
            }
#pragma unroll
            for (int jp = 0; jp < 4; jp++) {
                unsigned bh4[4], bl4[4];
                int q = lane >> 3;
                int n = warp_n * 64 + (jp * 2 + (q >> 1)) * 8 + (lane & 7);
                int seg = s * 2 + (q & 1);
                uint32_t off = (uint32_t)(n * 8 + (seg ^ (n & 7))) * 16;
                ldm_x4(bh4, baseBh + off);
                ldm_x4(bl4, baseBl + off);
#pragma unroll
                for (int mt = 0; mt < 2; mt++) {
                    mma_bf16(acc[mt][jp * 2], ah[mt], &bh4[0]);
                    mma_bf16(acc[mt][jp * 2], ah[mt], &bl4[0]);
                    mma_bf16(acc[mt][jp * 2], al[mt], &bh4[0]);
                    mma_bf16(acc[mt][jp * 2 + 1], ah[mt], &bh4[2]);
                    mma_bf16(acc[mt][jp * 2 + 1], ah[mt], &bl4[2]);
                    mma_bf16(acc[mt][jp * 2 + 1], al[mt], &bh4[2]);
                }
            }
        }
        if (ck < 7) storeA_smem(sm, boff_nxt, tid, ap);
        __syncthreads();       // all reads of cur done before it is re-staged
    }

    // epilogue
#pragma unroll
    for (int mt = 0; mt < 2; mt++)
#pragma unroll
        for (int nt = 0; nt < 8; nt++) {
            int r = row0 + warp_m * 32 + mt * 16 + (lane >> 2);
            int col = warp_n * 64 + nt * 8 + (lane & 3) * 2;
            if (r < Nn)
                *(float2*)(g_h1 + (size_t)r * H1 + col) =
                    make_float2(acc[mt][nt][0], acc[mt][nt][1]);
            if (r + 8 < Nn)
                *(float2*)(g_h1 + (size_t)(r + 8) * H1 + col) =
                    make_float2(acc[mt][nt][2], acc[mt][nt][3]);
        }
}

// ---------------- GEMM2: g_x2 [Nn,256] x W2 [256,32] -> g_h2 ----------------
__global__ void k_gemm2(const float* __restrict__ W) {
    __shared__ float sA[32][64];
    __shared__ float sW[64][32];
    int tid = threadIdx.x;
    int r = tid >> 3;
    int c4 = (tid & 7) * 4;
    int row0 = blockIdx.x * 32;
    float acc[4] = {0.f, 0.f, 0.f, 0.f};
    for (int k0 = 0; k0 < H1; k0 += 64) {
        for (int i = tid; i < 32 * 16; i += 256) {
            int rr = i >> 4;
            int kk4 = (i & 15) * 4;
            int grow = row0 + rr;
            float4 v = make_float4(0.f, 0.f, 0.f, 0.f);
            if (grow < Nn) v = *(const float4*)(g_x2 + (size_t)grow * H1 + k0 + kk4);
            *(float4*)(&sA[rr][kk4]) = v;
        }
        for (int i = tid; i < 512; i += 256) {
            int kk = i >> 3;
            int cc4 = (i & 7) * 4;
            *(float4*)(&sW[kk][cc4]) = *(const float4*)(W + (size_t)(k0 + kk) * H2 + cc4);
        }
        __syncthreads();
#pragma unroll
        for (int kk = 0; kk < 64; kk++) {
            float a = sA[r][kk];
            acc[0] += a * sW[kk][c4 + 0];
            acc[1] += a * sW[kk][c4 + 1];
            acc[2] += a * sW[kk][c4 + 2];
            acc[3] += a * sW[kk][c4 + 3];
        }
        __syncthreads();
    }
    int row = row0 + r;
    if (row < Nn) {
        float4 v = make_float4(acc[0], acc[1], acc[2], acc[3]);
        *(float4*)(g_h2 + (size_t)row * H2 + c4) = v;
    }
}

// ---------------- GEMM3: g_x3 [Nn,32] x W3 [32,16] -> g_h3 ------------------
__global__ void k_gemm3(const float* __restrict__ W) {
    __shared__ float sW[32 * 16];
    int tid = threadIdx.x;
    for (int i = tid; i < 32 * 16; i += 256) sW[i] = W[i];
    __syncthreads();
    int row = blockIdx.x * 256 + tid;
    if (row >= Nn) return;
    float acc[16];
#pragma unroll
    for (int c = 0; c < 16; c++) acc[c] = 0.f;
    const float4* ap = (const float4*)(g_x3 + (size_t)row * H2);
#pragma unroll
    for (int k4 = 0; k4 < 8; k4++) {
        float4 a = ap[k4];
        int k = k4 * 4;
#pragma unroll
        for (int c = 0; c < 16; c++) {
            acc[c] += a.x * sW[(k + 0) * 16 + c];
            acc[c] += a.y * sW[(k + 1) * 16 + c];
            acc[c] += a.z * sW[(k + 2) * 16 + c];
            acc[c] += a.w * sW[(k + 3) * 16 + c];
        }
    }
    float* op = g_h3 + (size_t)row * Cc;
#pragma unroll
    for (int c4 = 0; c4 < 4; c4++) {
        float4 v = make_float4(acc[c4 * 4 + 0], acc[c4 * 4 + 1], acc[c4 * 4 + 2], acc[c4 * 4 + 3]);
        *(float4*)(op + c4 * 4) = v;
    }
}

// ---------------- Aggregation ------------------------------------------------
__global__ void k_agg256(const float* __restrict__ bias) {
    int warp = threadIdx.x >> 5;
    int lane = threadIdx.x & 31;
    int node = blockIdx.x * 8 + warp;
    if (node >= Nn) return;
    float wd = g_dinv[node];
    const float4* hp = (const float4*)(g_h1 + (size_t)node * 256);
    float4 a0 = hp[lane];
    float4 a1 = hp[32 + lane];
    float4 acc0 = make_float4(a0.x * wd, a0.y * wd, a0.z * wd, a0.w * wd);
    float4 acc1 = make_float4(a1.x * wd, a1.y * wd, a1.z * wd, a1.w * wd);
    int beg = g_rowstart[node];
    int cnt = g_deg[node];
    for (int j = 0; j < cnt; j++) {
        int s = g_col[beg + j];
        float w = g_dinv[s];
        const float4* sp = (const float4*)(g_h1 + (size_t)s * 256);
        float4 v0 = sp[lane];
        float4 v1 = sp[32 + lane];
        acc0.x += w * v0.x; acc0.y += w * v0.y; acc0.z += w * v0.z; acc0.w += w * v0.w;
        acc1.x += w * v1.x; acc1.y += w * v1.y; acc1.z += w * v1.z; acc1.w += w * v1.w;
    }
    float4 b0 = ((const float4*)bias)[lane];
    float4 b1 = ((const float4*)bias)[32 + lane];
    float4 r0 = make_float4(fmaxf(acc0.x * wd + b0.x, 0.f), fmaxf(acc0.y * wd + b0.y, 0.f),
                            fmaxf(acc0.z * wd + b0.z, 0.f), fmaxf(acc0.w * wd + b0.w, 0.f));
    float4 r1 = make_float4(fmaxf(acc1.x * wd + b1.x, 0.f), fmaxf(acc1.y * wd + b1.y, 0.f),
                            fmaxf(acc1.z * wd + b1.z, 0.f), fmaxf(acc1.w * wd + b1.w, 0.f));
    float4* op = (float4*)(g_x2 + (size_t)node * 256);
    op[lane] = r0;
    op[32 + lane] = r1;
}

__global__ void k_agg32(const float* __restrict__ bias) {
    int warp = threadIdx.x >> 5;
    int lane = threadIdx.x & 31;
    int node = blockIdx.x * 8 + warp;
    if (node >= Nn) return;
    float wd = g_dinv[node];
    float acc = wd * g_h2[(size_t)node * 32 + lane];
    int beg = g_rowstart[node];
    int cnt = g_deg[node];
    for (int j = 0; j < cnt; j++) {
        int s = g_col[beg + j];
        acc += g_dinv[s] * g_h2[(size_t)s * 32 + lane];
    }
    float r = acc * wd + bias[lane];
    g_x3[(size_t)node * 32 + lane] = fmaxf(r, 0.f);
}

__global__ void k_agg16(const float* __restrict__ bias, float* __restrict__ out) {
    int tid = threadIdx.x;
    int local = tid & 15;
    int node = blockIdx.x * 16 + (tid >> 4);
    if (node >= Nn) return;
    float wd = g_dinv[node];
    float acc = wd * g_h3[(size_t)node * 16 + local];
    int beg = g_rowstart[node];
    int cnt = g_deg[node];
    for (int j = 0; j < cnt; j++) {
        int s = g_col[beg + j];
        acc += g_dinv[s] * g_h3[(size_t)s * 16 + local];
    }
    out[(size_t)node * 16 + local] = acc * wd + bias[local];
}

// ---------------- launch -----------------------------------------------------
extern "C" void kernel_launch(void* const* d_in, const int* in_sizes, int n_in,
                              void* d_out, int out_size) {
    const float* x   = (const float*)d_in[0];
    const void*  ei  = (const void*)d_in[1];
    const float* W1  = (const float*)d_in[2];
    const float* b1  = (const float*)d_in[3];
    const float* W2  = (const float*)d_in[4];
    const float* b2  = (const float*)d_in[5];
    const float* W3  = (const float*)d_in[6];
    const float* b3  = (const float*)d_in[7];
    float* out       = (float*)d_out;

    cudaFuncSetAttribute(k_gemm1_mma, cudaFuncAttributeMaxDynamicSharedMemorySize, SM1_SZ);

    const int scanBlocks = (Nn + 1023) / 1024;   // 49

    // Launch order arranged so ncu (-s 5 -c 1) captures k_gemm1_mma (#6).
    k_detect<<<1, 32>>>((const unsigned int*)ei);                 // 1
    k_zero_deg<<<(Nn + 255) / 256, 256>>>();                      // 2
    k_count<<<(Ee + 255) / 256, 256>>>(ei);                       // 3
    k_scan1<<<scanBlocks, 1024>>>();                              // 4
    k_cvtW<<<(F_IN * H1 + 255) / 256, 256>>>(W1);                 // 5
    k_gemm1_mma<<<(Nn + 127) / 128, 512, SM1_SZ>>>(x);            // 6  <- profiled
    k_scan2<<<1, 32>>>(scanBlocks);                               // 7
    k_scan3<<<(Nn + 255) / 256, 256>>>();                         // 8
    k_scatter<<<(Ee + 255) / 256, 256>>>(ei);                     // 9
    k_agg256<<<(Nn + 7) / 8, 256>>>(b1);                          // 10
    k_gemm2<<<(Nn + 31) / 32, 256>>>(W2);                         // 11
    k_agg32<<<(Nn + 7) / 8, 256>>>(b2);                           // 12
    k_gemm3<<<(Nn + 255) / 256, 256>>>(W3);                       // 13
    k_agg16<<<(Nn + 15) / 16, 256>>>(b3, out);                    // 14
}

// round 9
// speedup vs baseline: 1.1452x; 1.0064x over previous
#include <cuda_runtime.h>
#include <cuda_bf16.h>
#include <cstdint>

#define Nn   50000
#define Ee   800000
#define F_IN 512
#define H1   256
#define H2   32
#define Cc   16

// ---------------- scratch (device globals; no allocations allowed) ----------
static __device__ float g_h1[(size_t)Nn * H1];
static __device__ float g_x2[(size_t)Nn * H1];
static __device__ float g_h2[(size_t)Nn * H2];
static __device__ float g_x3[(size_t)Nn * H2];
static __device__ float g_h3[(size_t)Nn * Cc];
static __device__ float g_dinv[Nn];
static __device__ int   g_deg[Nn];
static __device__ int   g_incl[Nn];
static __device__ int   g_rowstart[Nn];
static __device__ int   g_fill[Nn];
static __device__ int   g_col[Ee];
static __device__ int   g_blocksums[64];
static __device__ int   g_is64;
// W1^T split-bf16: [256 n][512 k] (K contiguous = mma "col" B layout)
static __device__ __nv_bfloat16 g_Bh[(size_t)H1 * F_IN];
static __device__ __nv_bfloat16 g_Bl[(size_t)H1 * F_IN];

// ---------------- helpers ----------------------------------------------------
__device__ __forceinline__ uint32_t smem_u32(const void* p) {
    uint32_t a;
    asm("{ .reg .u64 t; cvta.to.shared.u64 t, %1; cvt.u32.u64 %0, t; }" : "=r"(a) : "l"(p));
    return a;
}
__device__ __forceinline__ unsigned pack_bf2(float a, float b) {
    __nv_bfloat162 t(__float2bfloat16(a), __float2bfloat16(b));
    return *(unsigned*)&t;
}
__device__ __forceinline__ void ldm_x4(unsigned* r, uint32_t addr) {
    asm volatile("ldmatrix.sync.aligned.m8n8.x4.shared.b16 {%0,%1,%2,%3}, [%4];"
                 : "=r"(r[0]), "=r"(r[1]), "=r"(r[2]), "=r"(r[3]) : "r"(addr));
}
__device__ __forceinline__ void mma_bf16(float* c, const unsigned* a, const unsigned* b) {
    asm volatile(
        "mma.sync.aligned.m16n8k16.row.col.f32.bf16.bf16.f32 "
        "{%0,%1,%2,%3},{%4,%5,%6,%7},{%8,%9},{%0,%1,%2,%3};"
        : "+f"(c[0]), "+f"(c[1]), "+f"(c[2]), "+f"(c[3])
        : "r"(a[0]), "r"(a[1]), "r"(a[2]), "r"(a[3]), "r"(b[0]), "r"(b[1]));
}
__device__ __forceinline__ void cpa16(uint32_t dst, const void* src) {
    asm volatile("cp.async.cg.shared.global [%0], [%1], 16;" :: "r"(dst), "l"(src));
}
#define CPA_COMMIT() asm volatile("cp.async.commit_group;" ::: "memory")
#define CPA_WAIT1()  asm volatile("cp.async.wait_group 1;" ::: "memory")

// ---------------- edge-index dtype detection --------------------------------
__global__ void k_detect(const unsigned int* __restrict__ w) {
    if (threadIdx.x == 0 && blockIdx.x == 0) {
        int is64 = 1;
        for (int i = 1; i < 512; i += 2) {
            if (w[i] != 0u) { is64 = 0; break; }
        }
        g_is64 = is64;
    }
}
__device__ __forceinline__ int load_idx(const void* __restrict__ ei, long long idx) {
    if (g_is64) return (int)((const long long*)ei)[idx];
    return ((const int*)ei)[idx];
}

// ---------------- CSR build --------------------------------------------------
__global__ void k_zero_deg() {
    int i = blockIdx.x * blockDim.x + threadIdx.x;
    if (i < Nn) g_deg[i] = 0;
}
__global__ void k_count(const void* __restrict__ ei) {
    int e = blockIdx.x * blockDim.x + threadIdx.x;
    if (e < Ee) atomicAdd(&g_deg[load_idx(ei, (long long)Ee + e)], 1);
}
__global__ void k_scan1() {
    __shared__ int s[1024];
    int t = threadIdx.x;
    int i = blockIdx.x * 1024 + t;
    s[t] = (i < Nn) ? g_deg[i] : 0;
    __syncthreads();
    for (int off = 1; off < 1024; off <<= 1) {
        int add = (t >= off) ? s[t - off] : 0;
        __syncthreads();
        s[t] += add;
        __syncthreads();
    }
    if (i < Nn) g_incl[i] = s[t];
    if (t == 1023) g_blocksums[blockIdx.x] = s[1023];
}
__global__ void k_scan2(int nblocks) {
    if (threadIdx.x == 0) {
        int run = 0;
        for (int i = 0; i < nblocks; i++) { int v = g_blocksums[i]; g_blocksums[i] = run; run += v; }
    }
}
__global__ void k_scan3() {
    int i = blockIdx.x * blockDim.x + threadIdx.x;
    if (i < Nn) {
        int deg = g_deg[i];
        int start = g_incl[i] - deg + g_blocksums[i >> 10];
        g_rowstart[i] = start;
        g_fill[i] = start;
        g_dinv[i] = rsqrtf((float)(deg + 1));
    }
}
__global__ void k_scatter(const void* __restrict__ ei) {
    int e = blockIdx.x * blockDim.x + threadIdx.x;
    if (e < Ee) {
        int s = load_idx(ei, e);
        int d = load_idx(ei, (long long)Ee + e);
        int pos = atomicAdd(&g_fill[d], 1);
        g_col[pos] = s;
    }
}

// ---------------- W1 transpose + split-bf16 ----------------------------------
__global__ void k_cvtW(const float* __restrict__ W1) {
    int i = blockIdx.x * blockDim.x + threadIdx.x;
    if (i < F_IN * H1) {
        int k = i >> 8;
        int n = i & 255;
        float v = W1[i];
        __nv_bfloat16 h = __float2bfloat16(v);
        __nv_bfloat16 l = __float2bfloat16(v - __bfloat162float(h));
        g_Bh[(size_t)n * F_IN + k] = h;
        g_Bl[(size_t)n * F_IN + k] = l;
    }
}

// ---------------- GEMM1: mma.sync split-bf16, double-buffered ---------------
#define ST_AH 0
#define ST_AL 16384
#define ST_BH 32768
#define ST_BL 65536
#define ST_SZ 98304
#define SM1_SZ (2 * ST_SZ)

struct APref { float4 v[2][2]; };

__device__ __forceinline__ void loadA_regs(const float* __restrict__ A, int row0,
                                           int k0, int tid, APref& ap) {
#pragma unroll
    for (int j = 0; j < 2; j++) {
        int i = tid + j * 512;
        int r = i >> 3;
        int seg = i & 7;
        int gr = row0 + r;
        if (gr >= Nn) gr = Nn - 1;
        const float4* p = (const float4*)(A + (size_t)gr * F_IN + k0 + seg * 8);
        ap.v[j][0] = p[0];
        ap.v[j][1] = p[1];
    }
}
__device__ __forceinline__ void storeA_smem(char* sm, int boff, int tid, const APref& ap) {
#pragma unroll
    for (int j = 0; j < 2; j++) {
        int i = tid + j * 512;
        int r = i >> 3;
        int seg = i & 7;
        float4 v0 = ap.v[j][0], v1 = ap.v[j][1];
        uint4 hi, lo;
        hi.x = pack_bf2(v0.x, v0.y); hi.y = pack_bf2(v0.z, v0.w);
        hi.z = pack_bf2(v1.x, v1.y); hi.w = pack_bf2(v1.z, v1.w);
        float lx = v0.x - __bfloat162float(__float2bfloat16(v0.x));
        float ly = v0.y - __bfloat162float(__float2bfloat16(v0.y));
        float lz = v0.z - __bfloat162float(__float2bfloat16(v0.z));
        float lw = v0.w - __bfloat162float(__float2bfloat16(v0.w));
        lo.x = pack_bf2(lx, ly); lo.y = pack_bf2(lz, lw);
        lx = v1.x - __bfloat162float(__float2bfloat16(v1.x));
        ly = v1.y - __bfloat162float(__float2bfloat16(v1.y));
        lz = v1.z - __bfloat162float(__float2bfloat16(v1.z));
        lw = v1.w - __bfloat162float(__float2bfloat16(v1.w));
        lo.z = pack_bf2(lx, ly); lo.w = pack_bf2(lz, lw);
        int ps = seg ^ (r & 7);
        *(uint4*)(sm + boff + ST_AH + (r * 8 + ps) * 16) = hi;
        *(uint4*)(sm + boff + ST_AL + (r * 8 + ps) * 16) = lo;
    }
}
__device__ __forceinline__ void issueB_cpasync(uint32_t sbase, int boff, int k0, int tid) {
#pragma unroll
    for (int j = 0; j < 4; j++) {
        int i = tid + j * 512;
        int n = i >> 3;
        int seg = i & 7;
        int ps = seg ^ (n & 7);
        size_t src = ((size_t)n * F_IN + k0 + seg * 8) * 2;
        uint32_t doff = (uint32_t)((n * 8 + ps) * 16);
        cpa16(sbase + boff + ST_BH + doff, (const char*)g_Bh + src);
        cpa16(sbase + boff + ST_BL + doff, (const char*)g_Bl + src);
    }
}

__global__ void __launch_bounds__(512, 1) k_gemm1_mma(const float* __restrict__ A) {
    extern __shared__ char sm[];
    uint32_t sbase = smem_u32(sm);
    int tid = threadIdx.x;
    int wid = tid >> 5;
    int lane = tid & 31;
    int warp_m = wid & 3;
    int warp_n = wid >> 2;
    int row0 = blockIdx.x * 128;

    float acc[2][8][4];
#pragma unroll
    for (int mt = 0; mt < 2; mt++)
#pragma unroll
        for (int nt = 0; nt < 8; nt++)
#pragma unroll
            for (int q = 0; q < 4; q++) acc[mt][nt][q] = 0.f;

    APref ap;
    loadA_regs(A, row0, 0, tid, ap);
    issueB_cpasync(sbase, 0, 0, tid);
    CPA_COMMIT();
    storeA_smem(sm, 0, tid, ap);

#pragma unroll 1
    for (int ck = 0; ck < 8; ck++) {
        int cur = ck & 1;
        int boff_cur = cur * ST_SZ;
        int boff_nxt = (cur ^ 1) * ST_SZ;
        if (ck < 7) {
            loadA_regs(A, row0, (ck + 1) * 64, tid, ap);
            issueB_cpasync(sbase, boff_nxt, (ck + 1) * 64, tid);
        }
        CPA_COMMIT();
        CPA_WAIT1();
        __syncthreads();

        uint32_t baseAh = sbase + boff_cur + ST_AH;
        uint32_t baseAl = sbase + boff_cur + ST_AL;
        uint32_t baseBh = sbase + boff_cur + ST_BH;
        uint32_t baseBl = sbase + boff_cur + ST_BL;
#pragma unroll
        for (int s = 0; s < 4; s++) {
            unsigned ah[2][4], al[2][4];
#pragma unroll
            for (int mt = 0; mt < 2; mt++) {
                int q = lane >> 3;
                int r = warp_m * 32 + mt * 16 + (q & 1) * 8 + (lane & 7);
                int seg = s * 2 + (q >> 1);
                uint32_t off = (uint32_t)(r * 8 + (seg ^ (r & 7))) * 16;
                ldm_x4(ah[mt], baseAh + off);
                ldm_x4(al[mt], baseAl + off);
            }
#pragma unroll
            for (int jp = 0; jp < 4; jp++) {
                unsigned bh4[4], bl4[4];
                int q = lane >> 3;
                int n = warp_n * 64 + (jp * 2 + (q >> 1)) * 8 + (lane & 7);
                int seg = s * 2 + (q & 1);
                uint32_t off = (uint32_t)(n * 8 + (seg ^ (n & 7))) * 16;
                ldm_x4(bh4, baseBh + off);
                ldm_x4(bl4, baseBl + off);
                // pass-ordered: same-acc reuse gap = 4 independent MMAs
                mma_bf16(acc[0][jp * 2],     ah[0], &bh4[0]);
                mma_bf16(acc[1][jp * 2],     ah[1], &bh4[0]);
                mma_bf16(acc[0][jp * 2 + 1], ah[0], &bh4[2]);
                mma_bf16(acc[1][jp * 2 + 1], ah[1], &bh4[2]);
                mma_bf16(acc[0][jp * 2],     ah[0], &bl4[0]);
                mma_bf16(acc[1][jp * 2],     ah[1], &bl4[0]);
                mma_bf16(acc[0][jp * 2 + 1], ah[0], &bl4[2]);
                mma_bf16(acc[1][jp * 2 + 1], ah[1], &bl4[2]);
                mma_bf16(acc[0][jp * 2],     al[0], &bh4[0]);
                mma_bf16(acc[1][jp * 2],     al[1], &bh4[0]);
                mma_bf16(acc[0][jp * 2 + 1], al[0], &bh4[2]);
                mma_bf16(acc[1][jp * 2 + 1], al[1], &bh4[2]);
            }
        }
        if (ck < 7) storeA_smem(sm, boff_nxt, tid, ap);
        __syncthreads();
    }

#pragma unroll
    for (int mt = 0; mt < 2; mt++)
#pragma unroll
        for (int nt = 0; nt < 8; nt++) {
            int r = row0 + warp_m * 32 + mt * 16 + (lane >> 2);
            int col = warp_n * 64 + nt * 8 + (lane & 3) * 2;
            if (r < Nn)
                *(float2*)(g_h1 + (size_t)r * H1 + col) =
                    make_float2(acc[mt][nt][0], acc[mt][nt][1]);
            if (r + 8 < Nn)
                *(float2*)(g_h1 + (size_t)(r + 8) * H1 + col) =
                    make_float2(acc[mt][nt][2], acc[mt][nt][3]);
        }
}

// ---------------- GEMM2: g_x2 [Nn,256] x W2 [256,32] -> g_h2 ----------------
__global__ void k_gemm2(const float* __restrict__ W) {
    __shared__ float sA[32][64];
    __shared__ float sW[64][32];
    int tid = threadIdx.x;
    int r = tid >> 3;
    int c4 = (tid & 7) * 4;
    int row0 = blockIdx.x * 32;
    float acc[4] = {0.f, 0.f, 0.f, 0.f};
    for (int k0 = 0; k0 < H1; k0 += 64) {
        for (int i = tid; i < 32 * 16; i += 256) {
            int rr = i >> 4;
            int kk4 = (i & 15) * 4;
            int grow = row0 + rr;
            float4 v = make_float4(0.f, 0.f, 0.f, 0.f);
            if (grow < Nn) v = *(const float4*)(g_x2 + (size_t)grow * H1 + k0 + kk4);
            *(float4*)(&sA[rr][kk4]) = v;
        }
        for (int i = tid; i < 512; i += 256) {
            int kk = i >> 3;
            int cc4 = (i & 7) * 4;
            *(float4*)(&sW[kk][cc4]) = *(const float4*)(W + (size_t)(k0 + kk) * H2 + cc4);
        }
        __syncthreads();
#pragma unroll
        for (int kk = 0; kk < 64; kk++) {
            float a = sA[r][kk];
            acc[0] += a * sW[kk][c4 + 0];
            acc[1] += a * sW[kk][c4 + 1];
            acc[2] += a * sW[kk][c4 + 2];
            acc[3] += a * sW[kk][c4 + 3];
        }
        __syncthreads();
    }
    int row = row0 + r;
    if (row < Nn) {
        float4 v = make_float4(acc[0], acc[1], acc[2], acc[3]);
        *(float4*)(g_h2 + (size_t)row * H2 + c4) = v;
    }
}

// ---------------- GEMM3: g_x3 [Nn,32] x W3 [32,16] -> g_h3 ------------------
__global__ void k_gemm3(const float* __restrict__ W) {
    __shared__ float sW[32 * 16];
    int tid = threadIdx.x;
    for (int i = tid; i < 32 * 16; i += 256) sW[i] = W[i];
    __syncthreads();
    int row = blockIdx.x * 256 + tid;
    if (row >= Nn) return;
    float acc[16];
#pragma unroll
    for (int c = 0; c < 16; c++) acc[c] = 0.f;
    const float4* ap = (const float4*)(g_x3 + (size_t)row * H2);
#pragma unroll
    for (int k4 = 0; k4 < 8; k4++) {
        float4 a = ap[k4];
        int k = k4 * 4;
#pragma unroll
        for (int c = 0; c < 16; c++) {
            acc[c] += a.x * sW[(k + 0) * 16 + c];
            acc[c] += a.y * sW[(k + 1) * 16 + c];
            acc[c] += a.z * sW[(k + 2) * 16 + c];
            acc[c] += a.w * sW[(k + 3) * 16 + c];
        }
    }
    float* op = g_h3 + (size_t)row * Cc;
#pragma unroll
    for (int c4 = 0; c4 < 4; c4++) {
        float4 v = make_float4(acc[c4 * 4 + 0], acc[c4 * 4 + 1], acc[c4 * 4 + 2], acc[c4 * 4 + 3]);
        *(float4*)(op + c4 * 4) = v;
    }
}

// ---------------- Aggregation ------------------------------------------------
__global__ void k_agg256(const float* __restrict__ bias) {
    int warp = threadIdx.x >> 5;
    int lane = threadIdx.x & 31;
    int node = blockIdx.x * 8 + warp;
    if (node >= Nn) return;
    float wd = g_dinv[node];
    const float4* hp = (const float4*)(g_h1 + (size_t)node * 256);
    float4 a0 = hp[lane];
    float4 a1 = hp[32 + lane];
    float4 acc0 = make_float4(a0.x * wd, a0.y * wd, a0.z * wd, a0.w * wd);
    float4 acc1 = make_float4(a1.x * wd, a1.y * wd, a1.z * wd, a1.w * wd);
    int beg = g_rowstart[node];
    int cnt = g_deg[node];
    int j = 0;
    for (; j + 2 <= cnt; j += 2) {
        int s0 = g_col[beg + j];
        int s1 = g_col[beg + j + 1];
        float w0 = g_dinv[s0];
        float w1 = g_dinv[s1];
        const float4* p0 = (const float4*)(g_h1 + (size_t)s0 * 256);
        const float4* p1 = (const float4*)(g_h1 + (size_t)s1 * 256);
        float4 u0 = p0[lane];
        float4 u1 = p0[32 + lane];
        float4 v0 = p1[lane];
        float4 v1 = p1[32 + lane];
        acc0.x += w0 * u0.x; acc0.y += w0 * u0.y; acc0.z += w0 * u0.z; acc0.w += w0 * u0.w;
        acc1.x += w0 * u1.x; acc1.y += w0 * u1.y; acc1.z += w0 * u1.z; acc1.w += w0 * u1.w;
        acc0.x += w1 * v0.x; acc0.y += w1 * v0.y; acc0.z += w1 * v0.z; acc0.w += w1 * v0.w;
        acc1.x += w1 * v1.x; acc1.y += w1 * v1.y; acc1.z += w1 * v1.z; acc1.w += w1 * v1.w;
    }
    if (j < cnt) {
        int s = g_col[beg + j];
        float w = g_dinv[s];
        const float4* sp = (const float4*)(g_h1 + (size_t)s * 256);
        float4 v0 = sp[lane];
        float4 v1 = sp[32 + lane];
        acc0.x += w * v0.x; acc0.y += w * v0.y; acc0.z += w * v0.z; acc0.w += w * v0.w;
        acc1.x += w * v1.x; acc1.y += w * v1.y; acc1.z += w * v1.z; acc1.w += w * v1.w;
    }
    float4 b0 = ((const float4*)bias)[lane];
    float4 b1 = ((const float4*)bias)[32 + lane];
    float4 r0 = make_float4(fmaxf(acc0.x * wd + b0.x, 0.f), fmaxf(acc0.y * wd + b0.y, 0.f),
                            fmaxf(acc0.z * wd + b0.z, 0.f), fmaxf(acc0.w * wd + b0.w, 0.f));
    float4 r1 = make_float4(fmaxf(acc1.x * wd + b1.x, 0.f), fmaxf(acc1.y * wd + b1.y, 0.f),
                            fmaxf(acc1.z * wd + b1.z, 0.f), fmaxf(acc1.w * wd + b1.w, 0.f));
    float4* op = (float4*)(g_x2 + (size_t)node * 256);
    op[lane] = r0;
    op[32 + lane] = r1;
}

__global__ void k_agg32(const float* __restrict__ bias) {
    int warp = threadIdx.x >> 5;
    int lane = threadIdx.x & 31;
    int node = blockIdx.x * 8 + warp;
    if (node >= Nn) return;
    float wd = g_dinv[node];
    float acc = wd * g_h2[(size_t)node * 32 + lane];
    int beg = g_rowstart[node];
    int cnt = g_deg[node];
    int j = 0;
    for (; j + 2 <= cnt; j += 2) {
        int s0 = g_col[beg + j];
        int s1 = g_col[beg + j + 1];
        float w0 = g_dinv[s0];
        float w1 = g_dinv[s1];
        float u = g_h2[(size_t)s0 * 32 + lane];
        float v = g_h2[(size_t)s1 * 32 + lane];
        acc += w0 * u + w1 * v;
    }
    if (j < cnt) {
        int s = g_col[beg + j];
        acc += g_dinv[s] * g_h2[(size_t)s * 32 + lane];
    }
    float r = acc * wd + bias[lane];
    g_x3[(size_t)node * 32 + lane] = fmaxf(r, 0.f);
}

__global__ void k_agg16(const float* __restrict__ bias, float* __restrict__ out) {
    int tid = threadIdx.x;
    int local = tid & 15;
    int node = blockIdx.x * 16 + (tid >> 4);
    if (node >= Nn) return;
    float wd = g_dinv[node];
    float acc = wd * g_h3[(size_t)node * 16 + local];
    int beg = g_rowstart[node];
    int cnt = g_deg[node];
    for (int j = 0; j < cnt; j++) {
        int s = g_col[beg + j];
        acc += g_dinv[s] * g_h3[(size_t)s * 16 + local];
    }
    out[(size_t)node * 16 + local] = acc * wd + bias[local];
}

// ---------------- launch -----------------------------------------------------
extern "C" void kernel_launch(void* const* d_in, const int* in_sizes, int n_in,
                              void* d_out, int out_size) {
    const float* x   = (const float*)d_in[0];
    const void*  ei  = (const void*)d_in[1];
    const float* W1  = (const float*)d_in[2];
    const float* b1  = (const float*)d_in[3];
    const float* W2  = (const float*)d_in[4];
    const float* b2  = (const float*)d_in[5];
    const float* W3  = (const float*)d_in[6];
    const float* b3  = (const float*)d_in[7];
    float* out       = (float*)d_out;

    cudaFuncSetAttribute(k_gemm1_mma, cudaFuncAttributeMaxDynamicSharedMemorySize, SM1_SZ);

    const int scanBlocks = (Nn + 1023) / 1024;   // 49

    // Launch order arranged so ncu (-s 5 -c 1) captures k_gemm1_mma (#6).
    k_detect<<<1, 32>>>((const unsigned int*)ei);                 // 1
    k_zero_deg<<<(Nn + 255) / 256, 256>>>();                      // 2
    k_count<<<(Ee + 255) / 256, 256>>>(ei);                       // 3
    k_scan1<<<scanBlocks, 1024>>>();                              // 4
    k_cvtW<<<(F_IN * H1 + 255) / 256, 256>>>(W1);                 // 5
    k_gemm1_mma<<<(Nn + 127) / 128, 512, SM1_SZ>>>(x);            // 6  <- profiled
    k_scan2<<<1, 32>>>(scanBlocks);                               // 7
    k_scan3<<<(Nn + 255) / 256, 256>>>();                         // 8
    k_scatter<<<(Ee + 255) / 256, 256>>>(ei);                     // 9
    k_agg256<<<(Nn + 7) / 8, 256>>>(b1);                          // 10
    k_gemm2<<<(Nn + 31) / 32, 256>>>(W2);                         // 11
    k_agg32<<<(Nn + 7) / 8, 256>>>(b2);                           // 12
    k_gemm3<<<(Nn + 255) / 256, 256>>>(W3);                       // 13
    k_agg16<<<(Nn + 15) / 16, 256>>>(b3, out);                    // 14
}

// round 10
// speedup vs baseline: 1.3320x; 1.1631x over previous
#include <cuda_runtime.h>
#include <cuda_bf16.h>
#include <cuda_fp16.h>
#include <cstdint>

#define Nn   50000
#define Ee   800000
#define F_IN 512
#define H1   256
#define H2   32
#define Cc   16

// ---------------- scratch (device globals; no allocations allowed) ----------
static __device__ __half g_h1h[(size_t)Nn * H1];   // x @ W1 in fp16
static __device__ float g_x2[(size_t)Nn * H1];
static __device__ float g_h2[(size_t)Nn * H2];
static __device__ float g_x3[(size_t)Nn * H2];
static __device__ float g_h3[(size_t)Nn * Cc];
static __device__ float g_dinv[Nn];
static __device__ int   g_deg[Nn];
static __device__ int   g_incl[Nn];
static __device__ int   g_rowstart[Nn];
static __device__ int   g_fill[Nn];
static __device__ int   g_col[Ee];
static __device__ int   g_blocksums[64];
static __device__ int   g_is64;
static __device__ __nv_bfloat16 g_Bh[(size_t)H1 * F_IN];
static __device__ __nv_bfloat16 g_Bl[(size_t)H1 * F_IN];

// ---------------- helpers ----------------------------------------------------
__device__ __forceinline__ uint32_t smem_u32(const void* p) {
    uint32_t a;
    asm("{ .reg .u64 t; cvta.to.shared.u64 t, %1; cvt.u32.u64 %0, t; }" : "=r"(a) : "l"(p));
    return a;
}
__device__ __forceinline__ unsigned pack_bf2(float a, float b) {
    __nv_bfloat162 t(__float2bfloat16(a), __float2bfloat16(b));
    return *(unsigned*)&t;
}
__device__ __forceinline__ void ldm_x4(unsigned* r, uint32_t addr) {
    asm volatile("ldmatrix.sync.aligned.m8n8.x4.shared.b16 {%0,%1,%2,%3}, [%4];"
                 : "=r"(r[0]), "=r"(r[1]), "=r"(r[2]), "=r"(r[3]) : "r"(addr));
}
__device__ __forceinline__ void mma_bf16(float* c, const unsigned* a, const unsigned* b) {
    asm volatile(
        "mma.sync.aligned.m16n8k16.row.col.f32.bf16.bf16.f32 "
        "{%0,%1,%2,%3},{%4,%5,%6,%7},{%8,%9},{%0,%1,%2,%3};"
        : "+f"(c[0]), "+f"(c[1]), "+f"(c[2]), "+f"(c[3])
        : "r"(a[0]), "r"(a[1]), "r"(a[2]), "r"(a[3]), "r"(b[0]), "r"(b[1]));
}
__device__ __forceinline__ void cpa16(uint32_t dst, const void* src) {
    asm volatile("cp.async.cg.shared.global [%0], [%1], 16;" :: "r"(dst), "l"(src));
}
#define CPA_COMMIT() asm volatile("cp.async.commit_group;" ::: "memory")
#define CPA_WAIT1()  asm volatile("cp.async.wait_group 1;" ::: "memory")

// fp16 row-slice fused accumulate: acc[0..7] += w * h8(u)
__device__ __forceinline__ void h8_fma(uint4 u, float w, float* acc) {
    const __half2* h = (const __half2*)&u;
#pragma unroll
    for (int i = 0; i < 4; i++) {
        float2 f = __half22float2(h[i]);
        acc[2 * i]     += w * f.x;
        acc[2 * i + 1] += w * f.y;
    }
}

// ---------------- edge-index dtype detection --------------------------------
__global__ void k_detect(const unsigned int* __restrict__ w) {
    if (threadIdx.x == 0 && blockIdx.x == 0) {
        int is64 = 1;
        for (int i = 1; i < 512; i += 2) {
            if (w[i] != 0u) { is64 = 0; break; }
        }
        g_is64 = is64;
    }
}
__device__ __forceinline__ int load_idx(const void* __restrict__ ei, long long idx) {
    if (g_is64) return (int)((const long long*)ei)[idx];
    return ((const int*)ei)[idx];
}

// ---------------- CSR build --------------------------------------------------
__global__ void k_zero_deg() {
    int i = blockIdx.x * blockDim.x + threadIdx.x;
    if (i < Nn) g_deg[i] = 0;
}
__global__ void k_count(const void* __restrict__ ei) {
    int e = blockIdx.x * blockDim.x + threadIdx.x;
    if (e < Ee) atomicAdd(&g_deg[load_idx(ei, (long long)Ee + e)], 1);
}
__global__ void k_scan1() {
    __shared__ int s[1024];
    int t = threadIdx.x;
    int i = blockIdx.x * 1024 + t;
    s[t] = (i < Nn) ? g_deg[i] : 0;
    __syncthreads();
    for (int off = 1; off < 1024; off <<= 1) {
        int add = (t >= off) ? s[t - off] : 0;
        __syncthreads();
        s[t] += add;
        __syncthreads();
    }
    if (i < Nn) g_incl[i] = s[t];
    if (t == 1023) g_blocksums[blockIdx.x] = s[1023];
}
__global__ void k_scan2(int nblocks) {
    if (threadIdx.x == 0) {
        int run = 0;
        for (int i = 0; i < nblocks; i++) { int v = g_blocksums[i]; g_blocksums[i] = run; run += v; }
    }
}
__global__ void k_scan3() {
    int i = blockIdx.x * blockDim.x + threadIdx.x;
    if (i < Nn) {
        int deg = g_deg[i];
        int start = g_incl[i] - deg + g_blocksums[i >> 10];
        g_rowstart[i] = start;
        g_fill[i] = start;
        g_dinv[i] = rsqrtf((float)(deg + 1));
    }
}
__global__ void k_scatter(const void* __restrict__ ei) {
    int e = blockIdx.x * blockDim.x + threadIdx.x;
    if (e < Ee) {
        int s = load_idx(ei, e);
        int d = load_idx(ei, (long long)Ee + e);
        int pos = atomicAdd(&g_fill[d], 1);
        g_col[pos] = s;
    }
}

// ---------------- W1 transpose + split-bf16 ----------------------------------
__global__ void k_cvtW(const float* __restrict__ W1) {
    int i = blockIdx.x * blockDim.x + threadIdx.x;
    if (i < F_IN * H1) {
        int k = i >> 8;
        int n = i & 255;
        float v = W1[i];
        __nv_bfloat16 h = __float2bfloat16(v);
        __nv_bfloat16 l = __float2bfloat16(v - __bfloat162float(h));
        g_Bh[(size_t)n * F_IN + k] = h;
        g_Bl[(size_t)n * F_IN + k] = l;
    }
}

// ---------------- GEMM1: mma.sync split-bf16, double-buffered ---------------
#define ST_AH 0
#define ST_AL 16384
#define ST_BH 32768
#define ST_BL 65536
#define ST_SZ 98304
#define SM1_SZ (2 * ST_SZ)

struct APref { float4 v[2][2]; };

__device__ __forceinline__ void loadA_regs(const float* __restrict__ A, int row0,
                                           int k0, int tid, APref& ap) {
#pragma unroll
    for (int j = 0; j < 2; j++) {
        int i = tid + j * 512;
        int r = i >> 3;
        int seg = i & 7;
        int gr = row0 + r;
        if (gr >= Nn) gr = Nn - 1;
        const float4* p = (const float4*)(A + (size_t)gr * F_IN + k0 + seg * 8);
        ap.v[j][0] = p[0];
        ap.v[j][1] = p[1];
    }
}
__device__ __forceinline__ void storeA_smem(char* sm, int boff, int tid, const APref& ap) {
#pragma unroll
    for (int j = 0; j < 2; j++) {
        int i = tid + j * 512;
        int r = i >> 3;
        int seg = i & 7;
        float4 v0 = ap.v[j][0], v1 = ap.v[j][1];
        uint4 hi, lo;
        hi.x = pack_bf2(v0.x, v0.y); hi.y = pack_bf2(v0.z, v0.w);
        hi.z = pack_bf2(v1.x, v1.y); hi.w = pack_bf2(v1.z, v1.w);
        float lx = v0.x - __bfloat162float(__float2bfloat16(v0.x));
        float ly = v0.y - __bfloat162float(__float2bfloat16(v0.y));
        float lz = v0.z - __bfloat162float(__float2bfloat16(v0.z));
        float lw = v0.w - __bfloat162float(__float2bfloat16(v0.w));
        lo.x = pack_bf2(lx, ly); lo.y = pack_bf2(lz, lw);
        lx = v1.x - __bfloat162float(__float2bfloat16(v1.x));
        ly = v1.y - __bfloat162float(__float2bfloat16(v1.y));
        lz = v1.z - __bfloat162float(__float2bfloat16(v1.z));
        lw = v1.w - __bfloat162float(__float2bfloat16(v1.w));
        lo.z = pack_bf2(lx, ly); lo.w = pack_bf2(lz, lw);
        int ps = seg ^ (r & 7);
        *(uint4*)(sm + boff + ST_AH + (r * 8 + ps) * 16) = hi;
        *(uint4*)(sm + boff + ST_AL + (r * 8 + ps) * 16) = lo;
    }
}
__device__ __forceinline__ void issueB_cpasync(uint32_t sbase, int boff, int k0, int tid) {
#pragma unroll
    for (int j = 0; j < 4; j++) {
        int i = tid + j * 512;
        int n = i >> 3;
        int seg = i & 7;
        int ps = seg ^ (n & 7);
        size_t src = ((size_t)n * F_IN + k0 + seg * 8) * 2;
        uint32_t doff = (uint32_t)((n * 8 + ps) * 16);
        cpa16(sbase + boff + ST_BH + doff, (const char*)g_Bh + src);
        cpa16(sbase + boff + ST_BL + doff, (const char*)g_Bl + src);
    }
}

__global__ void __launch_bounds__(512, 1) k_gemm1_mma(const float* __restrict__ A) {
    extern __shared__ char sm[];
    uint32_t sbase = smem_u32(sm);
    int tid = threadIdx.x;
    int wid = tid >> 5;
    int lane = tid & 31;
    int warp_m = wid & 3;
    int warp_n = wid >> 2;
    int row0 = blockIdx.x * 128;

    float acc[2][8][4];
#pragma unroll
    for (int mt = 0; mt < 2; mt++)
#pragma unroll
        for (int nt = 0; nt < 8; nt++)
#pragma unroll
            for (int q = 0; q < 4; q++) acc[mt][nt][q] = 0.f;

    APref ap;
    loadA_regs(A, row0, 0, tid, ap);
    issueB_cpasync(sbase, 0, 0, tid);
    CPA_COMMIT();
    storeA_smem(sm, 0, tid, ap);

#pragma unroll 1
    for (int ck = 0; ck < 8; ck++) {
        int cur = ck & 1;
        int boff_cur = cur * ST_SZ;
        int boff_nxt = (cur ^ 1) * ST_SZ;
        if (ck < 7) {
            loadA_regs(A, row0, (ck + 1) * 64, tid, ap);
            issueB_cpasync(sbase, boff_nxt, (ck + 1) * 64, tid);
        }
        CPA_COMMIT();
        CPA_WAIT1();
        __syncthreads();

        uint32_t baseAh = sbase + boff_cur + ST_AH;
        uint32_t baseAl = sbase + boff_cur + ST_AL;
        uint32_t baseBh = sbase + boff_cur + ST_BH;
        uint32_t baseBl = sbase + boff_cur + ST_BL;
#pragma unroll
        for (int s = 0; s < 4; s++) {
            unsigned ah[2][4], al[2][4];
#pragma unroll
            for (int mt = 0; mt < 2; mt++) {
                int q = lane >> 3;
                int r = warp_m * 32 + mt * 16 + (q & 1) * 8 + (lane & 7);
                int seg = s * 2 + (q >> 1);
                uint32_t off = (uint32_t)(r * 8 + (seg ^ (r & 7))) * 16;
                ldm_x4(ah[mt], baseAh + off);
                ldm_x4(al[mt], baseAl + off);
            }
#pragma unroll
            for (int jp = 0; jp < 4; jp++) {
                unsigned bh4[4], bl4[4];
                int q = lane >> 3;
                int n = warp_n * 64 + (jp * 2 + (q >> 1)) * 8 + (lane & 7);
                int seg = s * 2 + (q & 1);
                uint32_t off = (uint32_t)(n * 8 + (seg ^ (n & 7))) * 16;
                ldm_x4(bh4, baseBh + off);
                ldm_x4(bl4, baseBl + off);
                mma_bf16(acc[0][jp * 2],     ah[0], &bh4[0]);
                mma_bf16(acc[1][jp * 2],     ah[1], &bh4[0]);
                mma_bf16(acc[0][jp * 2 + 1], ah[0], &bh4[2]);
                mma_bf16(acc[1][jp * 2 + 1], ah[1], &bh4[2]);
                mma_bf16(acc[0][jp * 2],     ah[0], &bl4[0]);
                mma_bf16(acc[1][jp * 2],     ah[1], &bl4[0]);
                mma_bf16(acc[0][jp * 2 + 1], ah[0], &bl4[2]);
                mma_bf16(acc[1][jp * 2 + 1], ah[1], &bl4[2]);
                mma_bf16(acc[0][jp * 2],     al[0], &bh4[0]);
                mma_bf16(acc[1][jp * 2],     al[1], &bh4[0]);
                mma_bf16(acc[0][jp * 2 + 1], al[0], &bh4[2]);
                mma_bf16(acc[1][jp * 2 + 1], al[1], &bh4[2]);
            }
        }
        if (ck < 7) storeA_smem(sm, boff_nxt, tid, ap);
        __syncthreads();
    }

    // epilogue: write h1 as fp16 (halves agg256 gather traffic)
#pragma unroll
    for (int mt = 0; mt < 2; mt++)
#pragma unroll
        for (int nt = 0; nt < 8; nt++) {
            int r = row0 + warp_m * 32 + mt * 16 + (lane >> 2);
            int col = warp_n * 64 + nt * 8 + (lane & 3) * 2;
            if (r < Nn)
                *(__half2*)(g_h1h + (size_t)r * H1 + col) =
                    __floats2half2_rn(acc[mt][nt][0], acc[mt][nt][1]);
            if (r + 8 < Nn)
                *(__half2*)(g_h1h + (size_t)(r + 8) * H1 + col) =
                    __floats2half2_rn(acc[mt][nt][2], acc[mt][nt][3]);
        }
}

// ---------------- GEMM2: g_x2 [Nn,256] x W2 [256,32] -> g_h2 ----------------
__global__ void k_gemm2(const float* __restrict__ W) {
    __shared__ float sA[32][64];
    __shared__ float sW[64][32];
    int tid = threadIdx.x;
    int r = tid >> 3;
    int c4 = (tid & 7) * 4;
    int row0 = blockIdx.x * 32;
    float acc[4] = {0.f, 0.f, 0.f, 0.f};
    for (int k0 = 0; k0 < H1; k0 += 64) {
        for (int i = tid; i < 32 * 16; i += 256) {
            int rr = i >> 4;
            int kk4 = (i & 15) * 4;
            int grow = row0 + rr;
            float4 v = make_float4(0.f, 0.f, 0.f, 0.f);
            if (grow < Nn) v = *(const float4*)(g_x2 + (size_t)grow * H1 + k0 + kk4);
            *(float4*)(&sA[rr][kk4]) = v;
        }
        for (int i = tid; i < 512; i += 256) {
            int kk = i >> 3;
            int cc4 = (i & 7) * 4;
            *(float4*)(&sW[kk][cc4]) = *(const float4*)(W + (size_t)(k0 + kk) * H2 + cc4);
        }
        __syncthreads();
#pragma unroll
        for (int kk = 0; kk < 64; kk++) {
            float a = sA[r][kk];
            acc[0] += a * sW[kk][c4 + 0];
            acc[1] += a * sW[kk][c4 + 1];
            acc[2] += a * sW[kk][c4 + 2];
            acc[3] += a * sW[kk][c4 + 3];
        }
        __syncthreads();
    }
    int row = row0 + r;
    if (row < Nn) {
        float4 v = make_float4(acc[0], acc[1], acc[2], acc[3]);
        *(float4*)(g_h2 + (size_t)row * H2 + c4) = v;
    }
}

// ---------------- GEMM3: g_x3 [Nn,32] x W3 [32,16] -> g_h3 ------------------
__global__ void k_gemm3(const float* __restrict__ W) {
    __shared__ float sW[32 * 16];
    int tid = threadIdx.x;
    for (int i = tid; i < 32 * 16; i += 256) sW[i] = W[i];
    __syncthreads();
    int row = blockIdx.x * 256 + tid;
    if (row >= Nn) return;
    float acc[16];
#pragma unroll
    for (int c = 0; c < 16; c++) acc[c] = 0.f;
    const float4* ap = (const float4*)(g_x3 + (size_t)row * H2);
#pragma unroll
    for (int k4 = 0; k4 < 8; k4++) {
        float4 a = ap[k4];
        int k = k4 * 4;
#pragma unroll
        for (int c = 0; c < 16; c++) {
            acc[c] += a.x * sW[(k + 0) * 16 + c];
            acc[c] += a.y * sW[(k + 1) * 16 + c];
            acc[c] += a.z * sW[(k + 2) * 16 + c];
            acc[c] += a.w * sW[(k + 3) * 16 + c];
        }
    }
    float* op = g_h3 + (size_t)row * Cc;
#pragma unroll
    for (int c4 = 0; c4 < 4; c4++) {
        float4 v = make_float4(acc[c4 * 4 + 0], acc[c4 * 4 + 1], acc[c4 * 4 + 2], acc[c4 * 4 + 3]);
        *(float4*)(op + c4 * 4) = v;
    }
}

// ---------------- Aggregation ------------------------------------------------
// Layer 1: gather fp16 h1 rows (1 LDG.128 per lane per neighbor), fp32 math.
__global__ void k_agg256(const float* __restrict__ bias) {
    int warp = threadIdx.x >> 5;
    int lane = threadIdx.x & 31;
    int node = blockIdx.x * 8 + warp;
    if (node >= Nn) return;
    float wd = g_dinv[node];
    const uint4* hp = (const uint4*)(g_h1h);
    float acc[8] = {};
    h8_fma(hp[(size_t)node * 32 + lane], wd, acc);
    int beg = g_rowstart[node];
    int cnt = g_deg[node];
    int j = 0;
    for (; j + 2 <= cnt; j += 2) {
        int s0 = g_col[beg + j];
        int s1 = g_col[beg + j + 1];
        float w0 = g_dinv[s0];
        float w1 = g_dinv[s1];
        uint4 u = hp[(size_t)s0 * 32 + lane];
        uint4 v = hp[(size_t)s1 * 32 + lane];
        h8_fma(u, w0, acc);
        h8_fma(v, w1, acc);
    }
    if (j < cnt) {
        int s = g_col[beg + j];
        h8_fma(hp[(size_t)s * 32 + lane], g_dinv[s], acc);
    }
    const float4* bp = (const float4*)(bias + lane * 8);
    float4 b0 = bp[0], b1 = bp[1];
    float4 r0 = make_float4(fmaxf(acc[0] * wd + b0.x, 0.f), fmaxf(acc[1] * wd + b0.y, 0.f),
                            fmaxf(acc[2] * wd + b0.z, 0.f), fmaxf(acc[3] * wd + b0.w, 0.f));
    float4 r1 = make_float4(fmaxf(acc[4] * wd + b1.x, 0.f), fmaxf(acc[5] * wd + b1.y, 0.f),
                            fmaxf(acc[6] * wd + b1.z, 0.f), fmaxf(acc[7] * wd + b1.w, 0.f));
    float* op = g_x2 + (size_t)node * 256 + lane * 8;
    *(float4*)op = r0;
    *(float4*)(op + 4) = r1;
}

__global__ void k_agg32(const float* __restrict__ bias) {
    int warp = threadIdx.x >> 5;
    int lane = threadIdx.x & 31;
    int node = blockIdx.x * 8 + warp;
    if (node >= Nn) return;
    float wd = g_dinv[node];
    float acc = wd * g_h2[(size_t)node * 32 + lane];
    int beg = g_rowstart[node];
    int cnt = g_deg[node];
    int j = 0;
    for (; j + 2 <= cnt; j += 2) {
        int s0 = g_col[beg + j];
        int s1 = g_col[beg + j + 1];
        float w0 = g_dinv[s0];
        float w1 = g_dinv[s1];
        float u = g_h2[(size_t)s0 * 32 + lane];
        float v = g_h2[(size_t)s1 * 32 + lane];
        acc += w0 * u + w1 * v;
    }
    if (j < cnt) {
        int s = g_col[beg + j];
        acc += g_dinv[s] * g_h2[(size_t)s * 32 + lane];
    }
    float r = acc * wd + bias[lane];
    g_x3[(size_t)node * 32 + lane] = fmaxf(r, 0.f);
}

__global__ void k_agg16(const float* __restrict__ bias, float* __restrict__ out) {
    int tid = threadIdx.x;
    int local = tid & 15;
    int node = blockIdx.x * 16 + (tid >> 4);
    if (node >= Nn) return;
    float wd = g_dinv[node];
    float acc = wd * g_h3[(size_t)node * 16 + local];
    int beg = g_rowstart[node];
    int cnt = g_deg[node];
    for (int j = 0; j < cnt; j++) {
        int s = g_col[beg + j];
        acc += g_dinv[s] * g_h3[(size_t)s * 16 + local];
    }
    out[(size_t)node * 16 + local] = acc * wd + bias[local];
}

// ---------------- stream/event singletons (created once, reused) -------------
static cudaStream_t get_side_stream() {
    static cudaStream_t s = [] {
        cudaStream_t t;
        cudaStreamCreateWithFlags(&t, cudaStreamNonBlocking);
        return t;
    }();
    return s;
}
static cudaEvent_t get_event(int which) {
    static cudaEvent_t e0 = [] {
        cudaEvent_t e;
        cudaEventCreateWithFlags(&e, cudaEventDisableTiming);
        return e;
    }();
    static cudaEvent_t e1 = [] {
        cudaEvent_t e;
        cudaEventCreateWithFlags(&e, cudaEventDisableTiming);
        return e;
    }();
    return which ? e1 : e0;
}

// ---------------- launch -----------------------------------------------------
extern "C" void kernel_launch(void* const* d_in, const int* in_sizes, int n_in,
                              void* d_out, int out_size) {
    const float* x   = (const float*)d_in[0];
    const void*  ei  = (const void*)d_in[1];
    const float* W1  = (const float*)d_in[2];
    const float* b1  = (const float*)d_in[3];
    const float* W2  = (const float*)d_in[4];
    const float* b2  = (const float*)d_in[5];
    const float* W3  = (const float*)d_in[6];
    const float* b3  = (const float*)d_in[7];
    float* out       = (float*)d_out;

    cudaFuncSetAttribute(k_gemm1_mma, cudaFuncAttributeMaxDynamicSharedMemorySize, SM1_SZ);

    const int scanBlocks = (Nn + 1023) / 1024;   // 49
    cudaStream_t side = get_side_stream();
    cudaEvent_t evFork = get_event(0);
    cudaEvent_t evJoin = get_event(1);

    // fork: CSR build on side stream, gemm1 path on main stream
    cudaEventRecord(evFork, 0);
    cudaStreamWaitEvent(side, evFork, 0);

    k_detect<<<1, 32, 0, side>>>((const unsigned int*)ei);
    k_zero_deg<<<(Nn + 255) / 256, 256, 0, side>>>();
    k_count<<<(Ee + 255) / 256, 256, 0, side>>>(ei);
    k_scan1<<<scanBlocks, 1024, 0, side>>>();
    k_scan2<<<1, 32, 0, side>>>(scanBlocks);
    k_scan3<<<(Nn + 255) / 256, 256, 0, side>>>();
    k_scatter<<<(Ee + 255) / 256, 256, 0, side>>>(ei);
    cudaEventRecord(evJoin, side);

    k_cvtW<<<(F_IN * H1 + 255) / 256, 256>>>(W1);
    k_gemm1_mma<<<(Nn + 127) / 128, 512, SM1_SZ>>>(x);

    // join before aggregation (needs CSR + h1)
    cudaStreamWaitEvent(0, evJoin, 0);

    k_agg256<<<(Nn + 7) / 8, 256>>>(b1);
    k_gemm2<<<(Nn + 31) / 32, 256>>>(W2);
    k_agg32<<<(Nn + 7) / 8, 256>>>(b2);
    k_gemm3<<<(Nn + 255) / 256, 256>>>(W3);
    k_agg16<<<(Nn + 15) / 16, 256>>>(b3, out);
}

// round 12
// speedup vs baseline: 1.4502x; 1.0887x over previous
#include <cuda_runtime.h>
#include <cuda_bf16.h>
#include <cuda_fp16.h>
#include <cstdint>

#define Nn   50000
#define Ee   800000
#define F_IN 512
#define H1   256
#define H2   32
#define Cc   16

// ---------------- scratch (device globals; no allocations allowed) ----------
static __device__ __half g_h1h[(size_t)Nn * H1];   // x @ W1 in fp16
static __device__ float g_x2[(size_t)Nn * H1];
static __device__ float g_h2[(size_t)Nn * H2];
static __device__ float g_x3[(size_t)Nn * H2];
static __device__ float g_h3[(size_t)Nn * Cc];
static __device__ float g_dinv[Nn];
static __device__ int   g_deg[Nn];
static __device__ int   g_incl[Nn];
static __device__ int   g_rowstart[Nn];
static __device__ int   g_fill[Nn];
static __device__ int   g_col[Ee];
static __device__ int   g_blocksums[64];
static __device__ int   g_is64;
// W1^T split-fp16: [256 n][512 k]
static __device__ __half g_Bh[(size_t)H1 * F_IN];
static __device__ __half g_Bl[(size_t)H1 * F_IN];

// ---------------- helpers ----------------------------------------------------
__device__ __forceinline__ uint32_t smem_u32(const void* p) {
    uint32_t a;
    asm("{ .reg .u64 t; cvta.to.shared.u64 t, %1; cvt.u32.u64 %0, t; }" : "=r"(a) : "l"(p));
    return a;
}
__device__ __forceinline__ void ldm_x4(unsigned* r, uint32_t addr) {
    asm volatile("ldmatrix.sync.aligned.m8n8.x4.shared.b16 {%0,%1,%2,%3}, [%4];"
                 : "=r"(r[0]), "=r"(r[1]), "=r"(r[2]), "=r"(r[3]) : "r"(addr));
}
__device__ __forceinline__ void mma_f16(float* c, const unsigned* a, const unsigned* b) {
    asm volatile(
        "mma.sync.aligned.m16n8k16.row.col.f32.f16.f16.f32 "
        "{%0,%1,%2,%3},{%4,%5,%6,%7},{%8,%9},{%0,%1,%2,%3};"
        : "+f"(c[0]), "+f"(c[1]), "+f"(c[2]), "+f"(c[3])
        : "r"(a[0]), "r"(a[1]), "r"(a[2]), "r"(a[3]), "r"(b[0]), "r"(b[1]));
}
__device__ __forceinline__ void cpa16(uint32_t dst, const void* src) {
    asm volatile("cp.async.cg.shared.global [%0], [%1], 16;" :: "r"(dst), "l"(src));
}
#define CPA_COMMIT() asm volatile("cp.async.commit_group;" ::: "memory")
#define CPA_WAIT1()  asm volatile("cp.async.wait_group 1;" ::: "memory")

// fp16 row-slice fused accumulate: acc[0..7] += w * h8(u)
__device__ __forceinline__ void h8_fma(uint4 u, float w, float* acc) {
    const __half2* h = (const __half2*)&u;
#pragma unroll
    for (int i = 0; i < 4; i++) {
        float2 f = __half22float2(h[i]);
        acc[2 * i]     += w * f.x;
        acc[2 * i + 1] += w * f.y;
    }
}

// ---------------- edge-index dtype detection --------------------------------
__global__ void k_detect(const unsigned int* __restrict__ w) {
    if (threadIdx.x == 0 && blockIdx.x == 0) {
        int is64 = 1;
        for (int i = 1; i < 512; i += 2) {
            if (w[i] != 0u) { is64 = 0; break; }
        }
        g_is64 = is64;
    }
}
__device__ __forceinline__ int load_idx(const void* __restrict__ ei, long long idx) {
    if (g_is64) return (int)((const long long*)ei)[idx];
    return ((const int*)ei)[idx];
}

// ---------------- CSR build --------------------------------------------------
__global__ void k_zero_deg() {
    int i = blockIdx.x * blockDim.x + threadIdx.x;
    if (i < Nn) g_deg[i] = 0;
}
__global__ void k_count(const void* __restrict__ ei) {
    int e = blockIdx.x * blockDim.x + threadIdx.x;
    if (e < Ee) atomicAdd(&g_deg[load_idx(ei, (long long)Ee + e)], 1);
}
__global__ void k_scan1() {
    __shared__ int s[1024];
    int t = threadIdx.x;
    int i = blockIdx.x * 1024 + t;
    s[t] = (i < Nn) ? g_deg[i] : 0;
    __syncthreads();
    for (int off = 1; off < 1024; off <<= 1) {
        int add = (t >= off) ? s[t - off] : 0;
        __syncthreads();
        s[t] += add;
        __syncthreads();
    }
    if (i < Nn) g_incl[i] = s[t];
    if (t == 1023) g_blocksums[blockIdx.x] = s[1023];
}
__global__ void k_scan2(int nblocks) {
    if (threadIdx.x == 0) {
        int run = 0;
        for (int i = 0; i < nblocks; i++) { int v = g_blocksums[i]; g_blocksums[i] = run; run += v; }
    }
}
__global__ void k_scan3() {
    int i = blockIdx.x * blockDim.x + threadIdx.x;
    if (i < Nn) {
        int deg = g_deg[i];
        int start = g_incl[i] - deg + g_blocksums[i >> 10];
        g_rowstart[i] = start;
        g_fill[i] = start;
        g_dinv[i] = rsqrtf((float)(deg + 1));
    }
}
__global__ void k_scatter(const void* __restrict__ ei) {
    int e = blockIdx.x * blockDim.x + threadIdx.x;
    if (e < Ee) {
        int s = load_idx(ei, e);
        int d = load_idx(ei, (long long)Ee + e);
        int pos = atomicAdd(&g_fill[d], 1);
        g_col[pos] = s;
    }
}

// ---------------- W1 transpose + split-fp16 ----------------------------------
__global__ void k_cvtW(const float* __restrict__ W1) {
    int i = blockIdx.x * blockDim.x + threadIdx.x;
    if (i < F_IN * H1) {
        int k = i >> 8;
        int n = i & 255;
        float v = W1[i];
        __half h = __float2half_rn(v);
        __half l = __float2half_rn(v - __half2float(h));
        g_Bh[(size_t)n * F_IN + k] = h;
        g_Bl[(size_t)n * F_IN + k] = l;
    }
}

// ---------------- GEMM1: mma.sync fp16 (A plain, B split hi/lo) -------------
// Block 128x256, 512 threads = 16 warps (4x4), warp 32x64. K chunks of 64,
// double-buffered. Stage (80KB): A[16K] BH[32K] BL[32K].
#define ST_A  0
#define ST_BH 16384
#define ST_BL 49152
#define ST_SZ 81920
#define SM1_SZ (2 * ST_SZ)

struct APref { float4 v[2][2]; };

__device__ __forceinline__ void loadA_regs(const float* __restrict__ A, int row0,
                                           int k0, int tid, APref& ap) {
#pragma unroll
    for (int j = 0; j < 2; j++) {
        int i = tid + j * 512;
        int r = i >> 3;
        int seg = i & 7;
        int gr = row0 + r;
        if (gr >= Nn) gr = Nn - 1;
        const float4* p = (const float4*)(A + (size_t)gr * F_IN + k0 + seg * 8);
        ap.v[j][0] = p[0];
        ap.v[j][1] = p[1];
    }
}
__device__ __forceinline__ void storeA_smem(char* sm, int boff, int tid, const APref& ap) {
#pragma unroll
    for (int j = 0; j < 2; j++) {
        int i = tid + j * 512;
        int r = i >> 3;
        int seg = i & 7;
        float4 v0 = ap.v[j][0], v1 = ap.v[j][1];
        uint4 h;
        __half2 h0 = __floats2half2_rn(v0.x, v0.y);
        __half2 h1 = __floats2half2_rn(v0.z, v0.w);
        __half2 h2 = __floats2half2_rn(v1.x, v1.y);
        __half2 h3 = __floats2half2_rn(v1.z, v1.w);
        h.x = *(unsigned*)&h0; h.y = *(unsigned*)&h1;
        h.z = *(unsigned*)&h2; h.w = *(unsigned*)&h3;
        int ps = seg ^ (r & 7);
        *(uint4*)(sm + boff + ST_A + (r * 8 + ps) * 16) = h;
    }
}
__device__ __forceinline__ void issueB_cpasync(uint32_t sbase, int boff, int k0, int tid) {
#pragma unroll
    for (int j = 0; j < 4; j++) {
        int i = tid + j * 512;
        int n = i >> 3;
        int seg = i & 7;
        int ps = seg ^ (n & 7);
        size_t src = ((size_t)n * F_IN + k0 + seg * 8) * 2;
        uint32_t doff = (uint32_t)((n * 8 + ps) * 16);
        cpa16(sbase + boff + ST_BH + doff, (const char*)g_Bh + src);
        cpa16(sbase + boff + ST_BL + doff, (const char*)g_Bl + src);
    }
}

__global__ void __launch_bounds__(512, 1) k_gemm1_mma(const float* __restrict__ A) {
    extern __shared__ char sm[];
    uint32_t sbase = smem_u32(sm);
    int tid = threadIdx.x;
    int wid = tid >> 5;
    int lane = tid & 31;
    int warp_m = wid & 3;
    int warp_n = wid >> 2;
    int row0 = blockIdx.x * 128;

    float acc[2][8][4];
#pragma unroll
    for (int mt = 0; mt < 2; mt++)
#pragma unroll
        for (int nt = 0; nt < 8; nt++)
#pragma unroll
            for (int q = 0; q < 4; q++) acc[mt][nt][q] = 0.f;

    APref ap;
    loadA_regs(A, row0, 0, tid, ap);
    issueB_cpasync(sbase, 0, 0, tid);
    CPA_COMMIT();
    storeA_smem(sm, 0, tid, ap);

#pragma unroll 1
    for (int ck = 0; ck < 8; ck++) {
        int cur = ck & 1;
        int boff_cur = cur * ST_SZ;
        int boff_nxt = (cur ^ 1) * ST_SZ;
        if (ck < 7) {
            loadA_regs(A, row0, (ck + 1) * 64, tid, ap);
            issueB_cpasync(sbase, boff_nxt, (ck + 1) * 64, tid);
        }
        CPA_COMMIT();
        CPA_WAIT1();
        __syncthreads();

        uint32_t baseA  = sbase + boff_cur + ST_A;
        uint32_t baseBh = sbase + boff_cur + ST_BH;
        uint32_t baseBl = sbase + boff_cur + ST_BL;
#pragma unroll
        for (int s = 0; s < 4; s++) {
            unsigned ah[2][4];
#pragma unroll
            for (int mt = 0; mt < 2; mt++) {
                int q = lane >> 3;
                int r = warp_m * 32 + mt * 16 + (q & 1) * 8 + (lane & 7);
                int seg = s * 2 + (q >> 1);
                uint32_t off = (uint32_t)(r * 8 + (seg ^ (r & 7))) * 16;
                ldm_x4(ah[mt], baseA + off);
            }
#pragma unroll
            for (int jp = 0; jp < 4; jp++) {
                unsigned bh4[4], bl4[4];
                int q = lane >> 3;
                int n = warp_n * 64 + (jp * 2 + (q >> 1)) * 8 + (lane & 7);
                int seg = s * 2 + (q & 1);
                uint32_t off = (uint32_t)(n * 8 + (seg ^ (n & 7))) * 16;
                ldm_x4(bh4, baseBh + off);
                ldm_x4(bl4, baseBl + off);
                mma_f16(acc[0][jp * 2],     ah[0], &bh4[0]);
                mma_f16(acc[1][jp * 2],     ah[1], &bh4[0]);
                mma_f16(acc[0][jp * 2 + 1], ah[0], &bh4[2]);
                mma_f16(acc[1][jp * 2 + 1], ah[1], &bh4[2]);
                mma_f16(acc[0][jp * 2],     ah[0], &bl4[0]);
                mma_f16(acc[1][jp * 2],     ah[1], &bl4[0]);
                mma_f16(acc[0][jp * 2 + 1], ah[0], &bl4[2]);
                mma_f16(acc[1][jp * 2 + 1], ah[1], &bl4[2]);
            }
        }
        if (ck < 7) storeA_smem(sm, boff_nxt, tid, ap);
        __syncthreads();
    }

    // epilogue: write h1 as fp16
#pragma unroll
    for (int mt = 0; mt < 2; mt++)
#pragma unroll
        for (int nt = 0; nt < 8; nt++) {
            int r = row0 + warp_m * 32 + mt * 16 + (lane >> 2);
            int col = warp_n * 64 + nt * 8 + (lane & 3) * 2;
            if (r < Nn)
                *(__half2*)(g_h1h + (size_t)r * H1 + col) =
                    __floats2half2_rn(acc[mt][nt][0], acc[mt][nt][1]);
            if (r + 8 < Nn)
                *(__half2*)(g_h1h + (size_t)(r + 8) * H1 + col) =
                    __floats2half2_rn(acc[mt][nt][2], acc[mt][nt][3]);
        }
}

// ---------------- GEMM2: g_x2 [Nn,256] x W2 [256,32] -> g_h2 ----------------
__global__ void k_gemm2(const float* __restrict__ W) {
    __shared__ float sA[32][64];
    __shared__ float sW[64][32];
    int tid = threadIdx.x;
    int r = tid >> 3;
    int c4 = (tid & 7) * 4;
    int row0 = blockIdx.x * 32;
    float acc[4] = {0.f, 0.f, 0.f, 0.f};
    for (int k0 = 0; k0 < H1; k0 += 64) {
        for (int i = tid; i < 32 * 16; i += 256) {
            int rr = i >> 4;
            int kk4 = (i & 15) * 4;
            int grow = row0 + rr;
            float4 v = make_float4(0.f, 0.f, 0.f, 0.f);
            if (grow < Nn) v = *(const float4*)(g_x2 + (size_t)grow * H1 + k0 + kk4);
            *(float4*)(&sA[rr][kk4]) = v;
        }
        for (int i = tid; i < 512; i += 256) {
            int kk = i >> 3;
            int cc4 = (i & 7) * 4;
            *(float4*)(&sW[kk][cc4]) = *(const float4*)(W + (size_t)(k0 + kk) * H2 + cc4);
        }
        __syncthreads();
#pragma unroll
        for (int kk = 0; kk < 64; kk++) {
            float a = sA[r][kk];
            acc[0] += a * sW[kk][c4 + 0];
            acc[1] += a * sW[kk][c4 + 1];
            acc[2] += a * sW[kk][c4 + 2];
            acc[3] += a * sW[kk][c4 + 3];
        }
        __syncthreads();
    }
    int row = row0 + r;
    if (row < Nn) {
        float4 v = make_float4(acc[0], acc[1], acc[2], acc[3]);
        *(float4*)(g_h2 + (size_t)row * H2 + c4) = v;
    }
}

// ---------------- GEMM3: g_x3 [Nn,32] x W3 [32,16] -> g_h3 ------------------
__global__ void k_gemm3(const float* __restrict__ W) {
    __shared__ float sW[32 * 16];
    int tid = threadIdx.x;
    for (int i = tid; i < 32 * 16; i += 256) sW[i] = W[i];
    __syncthreads();
    int row = blockIdx.x * 256 + tid;
    if (row >= Nn) return;
    float acc[16];
#pragma unroll
    for (int c = 0; c < 16; c++) acc[c] = 0.f;
    const float4* ap = (const float4*)(g_x3 + (size_t)row * H2);
#pragma unroll
    for (int k4 = 0; k4 < 8; k4++) {
        float4 a = ap[k4];
        int k = k4 * 4;
#pragma unroll
        for (int c = 0; c < 16; c++) {
            acc[c] += a.x * sW[(k + 0) * 16 + c];
            acc[c] += a.y * sW[(k + 1) * 16 + c];
            acc[c] += a.z * sW[(k + 2) * 16 + c];
            acc[c] += a.w * sW[(k + 3) * 16 + c];
        }
    }
    float* op = g_h3 + (size_t)row * Cc;
#pragma unroll
    for (int c4 = 0; c4 < 4; c4++) {
        float4 v = make_float4(acc[c4 * 4 + 0], acc[c4 * 4 + 1], acc[c4 * 4 + 2], acc[c4 * 4 + 3]);
        *(float4*)(op + c4 * 4) = v;
    }
}

// ---------------- Aggregation ------------------------------------------------
__global__ void k_agg256(const float* __restrict__ bias) {
    int warp = threadIdx.x >> 5;
    int lane = threadIdx.x & 31;
    int node = blockIdx.x * 8 + warp;
    if (node >= Nn) return;
    float wd = g_dinv[node];
    const uint4* hp = (const uint4*)(g_h1h);
    float acc[8] = {};
    h8_fma(hp[(size_t)node * 32 + lane], wd, acc);
    int beg = g_rowstart[node];
    int cnt = g_deg[node];
    int j = 0;
    for (; j + 2 <= cnt; j += 2) {
        int s0 = g_col[beg + j];
        int s1 = g_col[beg + j + 1];
        float w0 = g_dinv[s0];
        float w1 = g_dinv[s1];
        uint4 u = hp[(size_t)s0 * 32 + lane];
        uint4 v = hp[(size_t)s1 * 32 + lane];
        h8_fma(u, w0, acc);
        h8_fma(v, w1, acc);
    }
    if (j < cnt) {
        int s = g_col[beg + j];
        h8_fma(hp[(size_t)s * 32 + lane], g_dinv[s], acc);
    }
    const float4* bp = (const float4*)(bias + lane * 8);
    float4 b0 = bp[0], b1 = bp[1];
    float4 r0 = make_float4(fmaxf(acc[0] * wd + b0.x, 0.f), fmaxf(acc[1] * wd + b0.y, 0.f),
                            fmaxf(acc[2] * wd + b0.z, 0.f), fmaxf(acc[3] * wd + b0.w, 0.f));
    float4 r1 = make_float4(fmaxf(acc[4] * wd + b1.x, 0.f), fmaxf(acc[5] * wd + b1.y, 0.f),
                            fmaxf(acc[6] * wd + b1.z, 0.f), fmaxf(acc[7] * wd + b1.w, 0.f));
    float* op = g_x2 + (size_t)node * 256 + lane * 8;
    *(float4*)op = r0;
    *(float4*)(op + 4) = r1;
}

__global__ void k_agg32(const float* __restrict__ bias) {
    int warp = threadIdx.x >> 5;
    int lane = threadIdx.x & 31;
    int node = blockIdx.x * 8 + warp;
    if (node >= Nn) return;
    float wd = g_dinv[node];
    float acc = wd * g_h2[(size_t)node * 32 + lane];
    int beg = g_rowstart[node];
    int cnt = g_deg[node];
    int j = 0;
    for (; j + 2 <= cnt; j += 2) {
        int s0 = g_col[beg + j];
        int s1 = g_col[beg + j + 1];
        float w0 = g_dinv[s0];
        float w1 = g_dinv[s1];
        float u = g_h2[(size_t)s0 * 32 + lane];
        float v = g_h2[(size_t)s1 * 32 + lane];
        acc += w0 * u + w1 * v;
    }
    if (j < cnt) {
        int s = g_col[beg + j];
        acc += g_dinv[s] * g_h2[(size_t)s * 32 + lane];
    }
    float r = acc * wd + bias[lane];
    g_x3[(size_t)node * 32 + lane] = fmaxf(r, 0.f);
}

__global__ void k_agg16(const float* __restrict__ bias, float* __restrict__ out) {
    int tid = threadIdx.x;
    int local = tid & 15;
    int node = blockIdx.x * 16 + (tid >> 4);
    if (node >= Nn) return;
    float wd = g_dinv[node];
    float acc = wd * g_h3[(size_t)node * 16 + local];
    int beg = g_rowstart[node];
    int cnt = g_deg[node];
    for (int j = 0; j < cnt; j++) {
        int s = g_col[beg + j];
        acc += g_dinv[s] * g_h3[(size_t)s * 16 + local];
    }
    out[(size_t)node * 16 + local] = acc * wd + bias[local];
}

// ---------------- stream/event singletons (created once, reused) -------------
static cudaStream_t get_side_stream() {
    static cudaStream_t s = [] {
        cudaStream_t t;
        cudaStreamCreateWithFlags(&t, cudaStreamNonBlocking);
        return t;
    }();
    return s;
}
static cudaEvent_t get_event(int which) {
    static cudaEvent_t e0 = [] {
        cudaEvent_t e;
        cudaEventCreateWithFlags(&e, cudaEventDisableTiming);
        return e;
    }();
    static cudaEvent_t e1 = [] {
        cudaEvent_t e;
        cudaEventCreateWithFlags(&e, cudaEventDisableTiming);
        return e;
    }();
    return which ? e1 : e0;
}

// ---------------- launch -----------------------------------------------------
extern "C" void kernel_launch(void* const* d_in, const int* in_sizes, int n_in,
                              void* d_out, int out_size) {
    const float* x   = (const float*)d_in[0];
    const void*  ei  = (const void*)d_in[1];
    const float* W1  = (const float*)d_in[2];
    const float* b1  = (const float*)d_in[3];
    const float* W2  = (const float*)d_in[4];
    const float* b2  = (const float*)d_in[5];
    const float* W3  = (const float*)d_in[6];
    const float* b3  = (const float*)d_in[7];
    float* out       = (float*)d_out;

    cudaFuncSetAttribute(k_gemm1_mma, cudaFuncAttributeMaxDynamicSharedMemorySize, SM1_SZ);

    const int scanBlocks = (Nn + 1023) / 1024;   // 49
    cudaStream_t side = get_side_stream();
    cudaEvent_t evFork = get_event(0);
    cudaEvent_t evJoin = get_event(1);

    // fork: CSR build on side stream, gemm1 path on main stream
    cudaEventRecord(evFork, 0);
    cudaStreamWaitEvent(side, evFork, 0);

    k_detect<<<1, 32, 0, side>>>((const unsigned int*)ei);
    k_zero_deg<<<(Nn + 255) / 256, 256, 0, side>>>();
    k_count<<<(Ee + 255) / 256, 256, 0, side>>>(ei);
    k_scan1<<<scanBlocks, 1024, 0, side>>>();
    k_scan2<<<1, 32, 0, side>>>(scanBlocks);
    k_scan3<<<(Nn + 255) / 256, 256, 0, side>>>();
    k_scatter<<<(Ee + 255) / 256, 256, 0, side>>>(ei);
    cudaEventRecord(evJoin, side);

    k_cvtW<<<(F_IN * H1 + 255) / 256, 256>>>(W1);
    k_gemm1_mma<<<(Nn + 127) / 128, 512, SM1_SZ>>>(x);

    // join before aggregation (needs CSR + h1)
    cudaStreamWaitEvent(0, evJoin, 0);

    k_agg256<<<(Nn + 7) / 8, 256>>>(b1);
    k_gemm2<<<(Nn + 31) / 32, 256>>>(W2);
    k_agg32<<<(Nn + 7) / 8, 256>>>(b2);
    k_gemm3<<<(Nn + 255) / 256, 256>>>(W3);
    k_agg16<<<(Nn + 15) / 16, 256>>>(b3, out);
}

// round 13
// speedup vs baseline: 1.5666x; 1.0803x over previous
#include <cuda_runtime.h>
#include <cuda_bf16.h>
#include <cuda_fp16.h>
#include <cstdint>

#define Nn   50000
#define Ee   800000
#define F_IN 512
#define H1   256
#define H2   32
#define Cc   16

// ---------------- scratch (device globals; no allocations allowed) ----------
static __device__ __half g_h1h[(size_t)Nn * H1];   // x @ W1 in fp16
static __device__ float g_x2[(size_t)Nn * H1];
static __device__ float g_h2[(size_t)Nn * H2];
static __device__ float g_x3[(size_t)Nn * H2];
static __device__ float g_h3[(size_t)Nn * Cc];
static __device__ float g_dinv[Nn];
static __device__ int   g_deg[Nn];
static __device__ int   g_incl[Nn];
static __device__ int   g_rowstart[Nn];
static __device__ int   g_fill[Nn];
static __device__ int   g_col[Ee];
static __device__ int   g_blocksums[64];
static __device__ int   g_is64;
// W1^T fp16: [256 n][512 k]
static __device__ __half g_B[(size_t)H1 * F_IN];

// ---------------- helpers ----------------------------------------------------
__device__ __forceinline__ uint32_t smem_u32(const void* p) {
    uint32_t a;
    asm("{ .reg .u64 t; cvta.to.shared.u64 t, %1; cvt.u32.u64 %0, t; }" : "=r"(a) : "l"(p));
    return a;
}
__device__ __forceinline__ void ldm_x4(unsigned* r, uint32_t addr) {
    asm volatile("ldmatrix.sync.aligned.m8n8.x4.shared.b16 {%0,%1,%2,%3}, [%4];"
                 : "=r"(r[0]), "=r"(r[1]), "=r"(r[2]), "=r"(r[3]) : "r"(addr));
}
__device__ __forceinline__ void mma_f16(float* c, const unsigned* a, const unsigned* b) {
    asm volatile(
        "mma.sync.aligned.m16n8k16.row.col.f32.f16.f16.f32 "
        "{%0,%1,%2,%3},{%4,%5,%6,%7},{%8,%9},{%0,%1,%2,%3};"
        : "+f"(c[0]), "+f"(c[1]), "+f"(c[2]), "+f"(c[3])
        : "r"(a[0]), "r"(a[1]), "r"(a[2]), "r"(a[3]), "r"(b[0]), "r"(b[1]));
}
__device__ __forceinline__ void cpa16(uint32_t dst, const void* src) {
    asm volatile("cp.async.cg.shared.global [%0], [%1], 16;" :: "r"(dst), "l"(src));
}
#define CPA_COMMIT() asm volatile("cp.async.commit_group;" ::: "memory")
#define CPA_WAIT1()  asm volatile("cp.async.wait_group 1;" ::: "memory")

// fp16 row-slice fused accumulate: acc[0..7] += w * h8(u)
__device__ __forceinline__ void h8_fma(uint4 u, float w, float* acc) {
    const __half2* h = (const __half2*)&u;
#pragma unroll
    for (int i = 0; i < 4; i++) {
        float2 f = __half22float2(h[i]);
        acc[2 * i]     += w * f.x;
        acc[2 * i + 1] += w * f.y;
    }
}

// ---------------- edge-index dtype detection --------------------------------
__global__ void k_detect(const unsigned int* __restrict__ w) {
    if (threadIdx.x == 0 && blockIdx.x == 0) {
        int is64 = 1;
        for (int i = 1; i < 512; i += 2) {
            if (w[i] != 0u) { is64 = 0; break; }
        }
        g_is64 = is64;
    }
}
__device__ __forceinline__ int load_idx(const void* __restrict__ ei, long long idx) {
    if (g_is64) return (int)((const long long*)ei)[idx];
    return ((const int*)ei)[idx];
}

// ---------------- CSR build --------------------------------------------------
__global__ void k_zero_deg() {
    int i = blockIdx.x * blockDim.x + threadIdx.x;
    if (i < Nn) g_deg[i] = 0;
}
__global__ void k_count(const void* __restrict__ ei) {
    int e = blockIdx.x * blockDim.x + threadIdx.x;
    if (e < Ee) atomicAdd(&g_deg[load_idx(ei, (long long)Ee + e)], 1);
}
__global__ void k_scan1() {
    __shared__ int s[1024];
    int t = threadIdx.x;
    int i = blockIdx.x * 1024 + t;
    s[t] = (i < Nn) ? g_deg[i] : 0;
    __syncthreads();
    for (int off = 1; off < 1024; off <<= 1) {
        int add = (t >= off) ? s[t - off] : 0;
        __syncthreads();
        s[t] += add;
        __syncthreads();
    }
    if (i < Nn) g_incl[i] = s[t];
    if (t == 1023) g_blocksums[blockIdx.x] = s[1023];
}
__global__ void k_scan2(int nblocks) {
    if (threadIdx.x == 0) {
        int run = 0;
        for (int i = 0; i < nblocks; i++) { int v = g_blocksums[i]; g_blocksums[i] = run; run += v; }
    }
}
__global__ void k_scan3() {
    int i = blockIdx.x * blockDim.x + threadIdx.x;
    if (i < Nn) {
        int deg = g_deg[i];
        int start = g_incl[i] - deg + g_blocksums[i >> 10];
        g_rowstart[i] = start;
        g_fill[i] = start;
        g_dinv[i] = rsqrtf((float)(deg + 1));
    }
}
__global__ void k_scatter(const void* __restrict__ ei) {
    int e = blockIdx.x * blockDim.x + threadIdx.x;
    if (e < Ee) {
        int s = load_idx(ei, e);
        int d = load_idx(ei, (long long)Ee + e);
        int pos = atomicAdd(&g_fill[d], 1);
        g_col[pos] = s;
    }
}

// ---------------- W1 transpose -> fp16 ----------------------------------------
__global__ void k_cvtW(const float* __restrict__ W1) {
    int i = blockIdx.x * blockDim.x + threadIdx.x;
    if (i < F_IN * H1) {
        int k = i >> 8;
        int n = i & 255;
        g_B[(size_t)n * F_IN + k] = __float2half_rn(W1[i]);
    }
}

// ---------------- GEMM1: plain fp16 mma.sync, double-buffered ----------------
// Block 128x256, 512 threads = 16 warps (4x4), warp 32x64. K chunks of 64.
// Stage (48KB): A[16K] B[32K].
#define ST_A  0
#define ST_B  16384
#define ST_SZ 49152
#define SM1_SZ (2 * ST_SZ)

struct APref { float4 v[2][2]; };

__device__ __forceinline__ void loadA_regs(const float* __restrict__ A, int row0,
                                           int k0, int tid, APref& ap) {
#pragma unroll
    for (int j = 0; j < 2; j++) {
        int i = tid + j * 512;
        int r = i >> 3;
        int seg = i & 7;
        int gr = row0 + r;
        if (gr >= Nn) gr = Nn - 1;
        const float4* p = (const float4*)(A + (size_t)gr * F_IN + k0 + seg * 8);
        ap.v[j][0] = p[0];
        ap.v[j][1] = p[1];
    }
}
__device__ __forceinline__ void storeA_smem(char* sm, int boff, int tid, const APref& ap) {
#pragma unroll
    for (int j = 0; j < 2; j++) {
        int i = tid + j * 512;
        int r = i >> 3;
        int seg = i & 7;
        float4 v0 = ap.v[j][0], v1 = ap.v[j][1];
        uint4 h;
        __half2 h0 = __floats2half2_rn(v0.x, v0.y);
        __half2 h1 = __floats2half2_rn(v0.z, v0.w);
        __half2 h2 = __floats2half2_rn(v1.x, v1.y);
        __half2 h3 = __floats2half2_rn(v1.z, v1.w);
        h.x = *(unsigned*)&h0; h.y = *(unsigned*)&h1;
        h.z = *(unsigned*)&h2; h.w = *(unsigned*)&h3;
        int ps = seg ^ (r & 7);
        *(uint4*)(sm + boff + ST_A + (r * 8 + ps) * 16) = h;
    }
}
__device__ __forceinline__ void issueB_cpasync(uint32_t sbase, int boff, int k0, int tid) {
#pragma unroll
    for (int j = 0; j < 4; j++) {
        int i = tid + j * 512;
        int n = i >> 3;
        int seg = i & 7;
        int ps = seg ^ (n & 7);
        size_t src = ((size_t)n * F_IN + k0 + seg * 8) * 2;
        uint32_t doff = (uint32_t)((n * 8 + ps) * 16);
        cpa16(sbase + boff + ST_B + doff, (const char*)g_B + src);
    }
}

__global__ void __launch_bounds__(512, 1) k_gemm1_mma(const float* __restrict__ A) {
    extern __shared__ char sm[];
    uint32_t sbase = smem_u32(sm);
    int tid = threadIdx.x;
    int wid = tid >> 5;
    int lane = tid & 31;
    int warp_m = wid & 3;
    int warp_n = wid >> 2;
    int row0 = blockIdx.x * 128;

    float acc[2][8][4];
#pragma unroll
    for (int mt = 0; mt < 2; mt++)
#pragma unroll
        for (int nt = 0; nt < 8; nt++)
#pragma unroll
            for (int q = 0; q < 4; q++) acc[mt][nt][q] = 0.f;

    APref ap;
    loadA_regs(A, row0, 0, tid, ap);
    issueB_cpasync(sbase, 0, 0, tid);
    CPA_COMMIT();
    storeA_smem(sm, 0, tid, ap);

#pragma unroll 1
    for (int ck = 0; ck < 8; ck++) {
        int cur = ck & 1;
        int boff_cur = cur * ST_SZ;
        int boff_nxt = (cur ^ 1) * ST_SZ;
        if (ck < 7) {
            loadA_regs(A, row0, (ck + 1) * 64, tid, ap);
            issueB_cpasync(sbase, boff_nxt, (ck + 1) * 64, tid);
        }
        CPA_COMMIT();
        CPA_WAIT1();
        __syncthreads();

        uint32_t baseA = sbase + boff_cur + ST_A;
        uint32_t baseB = sbase + boff_cur + ST_B;
#pragma unroll
        for (int s = 0; s < 4; s++) {
            unsigned ah[2][4];
#pragma unroll
            for (int mt = 0; mt < 2; mt++) {
                int q = lane >> 3;
                int r = warp_m * 32 + mt * 16 + (q & 1) * 8 + (lane & 7);
                int seg = s * 2 + (q >> 1);
                uint32_t off = (uint32_t)(r * 8 + (seg ^ (r & 7))) * 16;
                ldm_x4(ah[mt], baseA + off);
            }
#pragma unroll
            for (int jp = 0; jp < 4; jp++) {
                unsigned b4[4];
                int q = lane >> 3;
                int n = warp_n * 64 + (jp * 2 + (q >> 1)) * 8 + (lane & 7);
                int seg = s * 2 + (q & 1);
                uint32_t off = (uint32_t)(n * 8 + (seg ^ (n & 7))) * 16;
                ldm_x4(b4, baseB + off);
                mma_f16(acc[0][jp * 2],     ah[0], &b4[0]);
                mma_f16(acc[1][jp * 2],     ah[1], &b4[0]);
                mma_f16(acc[0][jp * 2 + 1], ah[0], &b4[2]);
                mma_f16(acc[1][jp * 2 + 1], ah[1], &b4[2]);
            }
        }
        if (ck < 7) storeA_smem(sm, boff_nxt, tid, ap);
        __syncthreads();
    }

    // epilogue: write h1 as fp16
#pragma unroll
    for (int mt = 0; mt < 2; mt++)
#pragma unroll
        for (int nt = 0; nt < 8; nt++) {
            int r = row0 + warp_m * 32 + mt * 16 + (lane >> 2);
            int col = warp_n * 64 + nt * 8 + (lane & 3) * 2;
            if (r < Nn)
                *(__half2*)(g_h1h + (size_t)r * H1 + col) =
                    __floats2half2_rn(acc[mt][nt][0], acc[mt][nt][1]);
            if (r + 8 < Nn)
                *(__half2*)(g_h1h + (size_t)(r + 8) * H1 + col) =
                    __floats2half2_rn(acc[mt][nt][2], acc[mt][nt][3]);
        }
}

// ---------------- GEMM2: g_x2 [Nn,256] x W2 [256,32] -> g_h2 ----------------
__global__ void k_gemm2(const float* __restrict__ W) {
    __shared__ float sA[32][64];
    __shared__ float sW[64][32];
    int tid = threadIdx.x;
    int r = tid >> 3;
    int c4 = (tid & 7) * 4;
    int row0 = blockIdx.x * 32;
    float acc[4] = {0.f, 0.f, 0.f, 0.f};
    for (int k0 = 0; k0 < H1; k0 += 64) {
        for (int i = tid; i < 32 * 16; i += 256) {
            int rr = i >> 4;
            int kk4 = (i & 15) * 4;
            int grow = row0 + rr;
            float4 v = make_float4(0.f, 0.f, 0.f, 0.f);
            if (grow < Nn) v = *(const float4*)(g_x2 + (size_t)grow * H1 + k0 + kk4);
            *(float4*)(&sA[rr][kk4]) = v;
        }
        for (int i = tid; i < 512; i += 256) {
            int kk = i >> 3;
            int cc4 = (i & 7) * 4;
            *(float4*)(&sW[kk][cc4]) = *(const float4*)(W + (size_t)(k0 + kk) * H2 + cc4);
        }
        __syncthreads();
#pragma unroll
        for (int kk = 0; kk < 64; kk++) {
            float a = sA[r][kk];
            acc[0] += a * sW[kk][c4 + 0];
            acc[1] += a * sW[kk][c4 + 1];
            acc[2] += a * sW[kk][c4 + 2];
            acc[3] += a * sW[kk][c4 + 3];
        }
        __syncthreads();
    }
    int row = row0 + r;
    if (row < Nn) {
        float4 v = make_float4(acc[0], acc[1], acc[2], acc[3]);
        *(float4*)(g_h2 + (size_t)row * H2 + c4) = v;
    }
}

// ---------------- GEMM3: g_x3 [Nn,32] x W3 [32,16] -> g_h3 ------------------
__global__ void k_gemm3(const float* __restrict__ W) {
    __shared__ float sW[32 * 16];
    int tid = threadIdx.x;
    for (int i = tid; i < 32 * 16; i += 256) sW[i] = W[i];
    __syncthreads();
    int row = blockIdx.x * 256 + tid;
    if (row >= Nn) return;
    float acc[16];
#pragma unroll
    for (int c = 0; c < 16; c++) acc[c] = 0.f;
    const float4* ap = (const float4*)(g_x3 + (size_t)row * H2);
#pragma unroll
    for (int k4 = 0; k4 < 8; k4++) {
        float4 a = ap[k4];
        int k = k4 * 4;
#pragma unroll
        for (int c = 0; c < 16; c++) {
            acc[c] += a.x * sW[(k + 0) * 16 + c];
            acc[c] += a.y * sW[(k + 1) * 16 + c];
            acc[c] += a.z * sW[(k + 2) * 16 + c];
            acc[c] += a.w * sW[(k + 3) * 16 + c];
        }
    }
    float* op = g_h3 + (size_t)row * Cc;
#pragma unroll
    for (int c4 = 0; c4 < 4; c4++) {
        float4 v = make_float4(acc[c4 * 4 + 0], acc[c4 * 4 + 1], acc[c4 * 4 + 2], acc[c4 * 4 + 3]);
        *(float4*)(op + c4 * 4) = v;
    }
}

// ---------------- Aggregation ------------------------------------------------
__global__ void k_agg256(const float* __restrict__ bias) {
    int warp = threadIdx.x >> 5;
    int lane = threadIdx.x & 31;
    int node = blockIdx.x * 8 + warp;
    if (node >= Nn) return;
    float wd = g_dinv[node];
    const uint4* hp = (const uint4*)(g_h1h);
    float acc[8] = {};
    h8_fma(hp[(size_t)node * 32 + lane], wd, acc);
    int beg = g_rowstart[node];
    int cnt = g_deg[node];
    int j = 0;
    for (; j + 2 <= cnt; j += 2) {
        int s0 = g_col[beg + j];
        int s1 = g_col[beg + j + 1];
        float w0 = g_dinv[s0];
        float w1 = g_dinv[s1];
        uint4 u = hp[(size_t)s0 * 32 + lane];
        uint4 v = hp[(size_t)s1 * 32 + lane];
        h8_fma(u, w0, acc);
        h8_fma(v, w1, acc);
    }
    if (j < cnt) {
        int s = g_col[beg + j];
        h8_fma(hp[(size_t)s * 32 + lane], g_dinv[s], acc);
    }
    const float4* bp = (const float4*)(bias + lane * 8);
    float4 b0 = bp[0], b1 = bp[1];
    float4 r0 = make_float4(fmaxf(acc[0] * wd + b0.x, 0.f), fmaxf(acc[1] * wd + b0.y, 0.f),
                            fmaxf(acc[2] * wd + b0.z, 0.f), fmaxf(acc[3] * wd + b0.w, 0.f));
    float4 r1 = make_float4(fmaxf(acc[4] * wd + b1.x, 0.f), fmaxf(acc[5] * wd + b1.y, 0.f),
                            fmaxf(acc[6] * wd + b1.z, 0.f), fmaxf(acc[7] * wd + b1.w, 0.f));
    float* op = g_x2 + (size_t)node * 256 + lane * 8;
    *(float4*)op = r0;
    *(float4*)(op + 4) = r1;
}

__global__ void k_agg32(const float* __restrict__ bias) {
    int warp = threadIdx.x >> 5;
    int lane = threadIdx.x & 31;
    int node = blockIdx.x * 8 + warp;
    if (node >= Nn) return;
    float wd = g_dinv[node];
    float acc = wd * g_h2[(size_t)node * 32 + lane];
    int beg = g_rowstart[node];
    int cnt = g_deg[node];
    int j = 0;
    for (; j + 2 <= cnt; j += 2) {
        int s0 = g_col[beg + j];
        int s1 = g_col[beg + j + 1];
        float w0 = g_dinv[s0];
        float w1 = g_dinv[s1];
        float u = g_h2[(size_t)s0 * 32 + lane];
        float v = g_h2[(size_t)s1 * 32 + lane];
        acc += w0 * u + w1 * v;
    }
    if (j < cnt) {
        int s = g_col[beg + j];
        acc += g_dinv[s] * g_h2[(size_t)s * 32 + lane];
    }
    float r = acc * wd + bias[lane];
    g_x3[(size_t)node * 32 + lane] = fmaxf(r, 0.f);
}

__global__ void k_agg16(const float* __restrict__ bias, float* __restrict__ out) {
    int tid = threadIdx.x;
    int local = tid & 15;
    int node = blockIdx.x * 16 + (tid >> 4);
    if (node >= Nn) return;
    float wd = g_dinv[node];
    float acc = wd * g_h3[(size_t)node * 16 + local];
    int beg = g_rowstart[node];
    int cnt = g_deg[node];
    for (int j = 0; j < cnt; j++) {
        int s = g_col[beg + j];
        acc += g_dinv[s] * g_h3[(size_t)s * 16 + local];
    }
    out[(size_t)node * 16 + local] = acc * wd + bias[local];
}

// ---------------- stream/event singletons (created once, reused) -------------
static cudaStream_t get_side_stream() {
    static cudaStream_t s = [] {
        cudaStream_t t;
        cudaStreamCreateWithFlags(&t, cudaStreamNonBlocking);
        return t;
    }();
    return s;
}
static cudaEvent_t get_event(int which) {
    static cudaEvent_t e0 = [] {
        cudaEvent_t e;
        cudaEventCreateWithFlags(&e, cudaEventDisableTiming);
        return e;
    }();
    static cudaEvent_t e1 = [] {
        cudaEvent_t e;
        cudaEventCreateWithFlags(&e, cudaEventDisableTiming);
        return e;
    }();
    return which ? e1 : e0;
}

// ---------------- launch -----------------------------------------------------
extern "C" void kernel_launch(void* const* d_in, const int* in_sizes, int n_in,
                              void* d_out, int out_size) {
    const float* x   = (const float*)d_in[0];
    const void*  ei  = (const void*)d_in[1];
    const float* W1  = (const float*)d_in[2];
    const float* b1  = (const float*)d_in[3];
    const float* W2  = (const float*)d_in[4];
    const float* b2  = (const float*)d_in[5];
    const float* W3  = (const float*)d_in[6];
    const float* b3  = (const float*)d_in[7];
    float* out       = (float*)d_out;

    cudaFuncSetAttribute(k_gemm1_mma, cudaFuncAttributeMaxDynamicSharedMemorySize, SM1_SZ);

    const int scanBlocks = (Nn + 1023) / 1024;   // 49
    cudaStream_t side = get_side_stream();
    cudaEvent_t evFork = get_event(0);
    cudaEvent_t evJoin = get_event(1);

    // fork: CSR build on side stream, gemm1 path on main stream
    cudaEventRecord(evFork, 0);
    cudaStreamWaitEvent(side, evFork, 0);

    k_detect<<<1, 32, 0, side>>>((const unsigned int*)ei);
    k_zero_deg<<<(Nn + 255) / 256, 256, 0, side>>>();
    k_count<<<(Ee + 255) / 256, 256, 0, side>>>(ei);
    k_scan1<<<scanBlocks, 1024, 0, side>>>();
    k_scan2<<<1, 32, 0, side>>>(scanBlocks);
    k_scan3<<<(Nn + 255) / 256, 256, 0, side>>>();
    k_scatter<<<(Ee + 255) / 256, 256, 0, side>>>(ei);
    cudaEventRecord(evJoin, side);

    k_cvtW<<<(F_IN * H1 + 255) / 256, 256>>>(W1);
    k_gemm1_mma<<<(Nn + 127) / 128, 512, SM1_SZ>>>(x);

    // join before aggregation (needs CSR + h1)
    cudaStreamWaitEvent(0, evJoin, 0);

    k_agg256<<<(Nn + 7) / 8, 256>>>(b1);
    k_gemm2<<<(Nn + 31) / 32, 256>>>(W2);
    k_agg32<<<(Nn + 7) / 8, 256>>>(b2);
    k_gemm3<<<(Nn + 255) / 256, 256>>>(W3);
    k_agg16<<<(Nn + 15) / 16, 256>>>(b3, out);
}

// round 14
// speedup vs baseline: 1.6727x; 1.0677x over previous
#include <cuda_runtime.h>
#include <cuda_bf16.h>
#include <cuda_fp16.h>
#include <cstdint>

#define Nn   50000
#define Ee   800000
#define F_IN 512
#define H1   256
#define H2   32
#define Cc   16

// ---------------- scratch (device globals; no allocations allowed) ----------
static __device__ __half g_h1h[(size_t)Nn * H1];   // x @ W1 in fp16
static __device__ __half g_x2h[(size_t)Nn * H1];   // relu(agg1+b1) in fp16
static __device__ float g_h2[(size_t)Nn * H2];
static __device__ float g_x3[(size_t)Nn * H2];
static __device__ float g_h3[(size_t)Nn * Cc];
static __device__ float g_dinv[Nn];
static __device__ int   g_deg[Nn];
static __device__ int   g_incl[Nn];
static __device__ int   g_rowstart[Nn];
static __device__ int   g_fill[Nn];
static __device__ int   g_col[Ee];
static __device__ int   g_blocksums[64];
static __device__ int   g_is64;
// W1^T fp16: [256 n][512 k]
static __device__ __half g_B[(size_t)H1 * F_IN];

// ---------------- helpers ----------------------------------------------------
__device__ __forceinline__ uint32_t smem_u32(const void* p) {
    uint32_t a;
    asm("{ .reg .u64 t; cvta.to.shared.u64 t, %1; cvt.u32.u64 %0, t; }" : "=r"(a) : "l"(p));
    return a;
}
__device__ __forceinline__ void ldm_x4(unsigned* r, uint32_t addr) {
    asm volatile("ldmatrix.sync.aligned.m8n8.x4.shared.b16 {%0,%1,%2,%3}, [%4];"
                 : "=r"(r[0]), "=r"(r[1]), "=r"(r[2]), "=r"(r[3]) : "r"(addr));
}
__device__ __forceinline__ void mma_f16(float* c, const unsigned* a, const unsigned* b) {
    asm volatile(
        "mma.sync.aligned.m16n8k16.row.col.f32.f16.f16.f32 "
        "{%0,%1,%2,%3},{%4,%5,%6,%7},{%8,%9},{%0,%1,%2,%3};"
        : "+f"(c[0]), "+f"(c[1]), "+f"(c[2]), "+f"(c[3])
        : "r"(a[0]), "r"(a[1]), "r"(a[2]), "r"(a[3]), "r"(b[0]), "r"(b[1]));
}
__device__ __forceinline__ void cpa16(uint32_t dst, const void* src) {
    asm volatile("cp.async.cg.shared.global [%0], [%1], 16;" :: "r"(dst), "l"(src));
}
#define CPA_COMMIT() asm volatile("cp.async.commit_group;" ::: "memory")
#define CPA_WAIT1()  asm volatile("cp.async.wait_group 1;" ::: "memory")

// fp16 row-slice fused accumulate: acc[0..7] += w * h8(u)
__device__ __forceinline__ void h8_fma(uint4 u, float w, float* acc) {
    const __half2* h = (const __half2*)&u;
#pragma unroll
    for (int i = 0; i < 4; i++) {
        float2 f = __half22float2(h[i]);
        acc[2 * i]     += w * f.x;
        acc[2 * i + 1] += w * f.y;
    }
}

// ---------------- edge-index dtype detection --------------------------------
__global__ void k_detect(const unsigned int* __restrict__ w) {
    if (threadIdx.x == 0 && blockIdx.x == 0) {
        int is64 = 1;
        for (int i = 1; i < 512; i += 2) {
            if (w[i] != 0u) { is64 = 0; break; }
        }
        g_is64 = is64;
    }
}
__device__ __forceinline__ int load_idx(const void* __restrict__ ei, long long idx) {
    if (g_is64) return (int)((const long long*)ei)[idx];
    return ((const int*)ei)[idx];
}

// ---------------- CSR build --------------------------------------------------
__global__ void k_zero_deg() {
    int i = blockIdx.x * blockDim.x + threadIdx.x;
    if (i < Nn) g_deg[i] = 0;
}
__global__ void k_count(const void* __restrict__ ei) {
    int e = blockIdx.x * blockDim.x + threadIdx.x;
    if (e < Ee) atomicAdd(&g_deg[load_idx(ei, (long long)Ee + e)], 1);
}
__global__ void k_scan1() {
    __shared__ int s[1024];
    int t = threadIdx.x;
    int i = blockIdx.x * 1024 + t;
    s[t] = (i < Nn) ? g_deg[i] : 0;
    __syncthreads();
    for (int off = 1; off < 1024; off <<= 1) {
        int add = (t >= off) ? s[t - off] : 0;
        __syncthreads();
        s[t] += add;
        __syncthreads();
    }
    if (i < Nn) g_incl[i] = s[t];
    if (t == 1023) g_blocksums[blockIdx.x] = s[1023];
}
__global__ void k_scan2(int nblocks) {
    if (threadIdx.x == 0) {
        int run = 0;
        for (int i = 0; i < nblocks; i++) { int v = g_blocksums[i]; g_blocksums[i] = run; run += v; }
    }
}
__global__ void k_scan3() {
    int i = blockIdx.x * blockDim.x + threadIdx.x;
    if (i < Nn) {
        int deg = g_deg[i];
        int start = g_incl[i] - deg + g_blocksums[i >> 10];
        g_rowstart[i] = start;
        g_fill[i] = start;
        g_dinv[i] = rsqrtf((float)(deg + 1));
    }
}
__global__ void k_scatter(const void* __restrict__ ei) {
    int e = blockIdx.x * blockDim.x + threadIdx.x;
    if (e < Ee) {
        int s = load_idx(ei, e);
        int d = load_idx(ei, (long long)Ee + e);
        int pos = atomicAdd(&g_fill[d], 1);
        g_col[pos] = s;
    }
}

// ---------------- W1 transpose -> fp16 ----------------------------------------
__global__ void k_cvtW(const float* __restrict__ W1) {
    int i = blockIdx.x * blockDim.x + threadIdx.x;
    if (i < F_IN * H1) {
        int k = i >> 8;
        int n = i & 255;
        g_B[(size_t)n * F_IN + k] = __float2half_rn(W1[i]);
    }
}

// ---------------- GEMM1: plain fp16 mma.sync, 2 CTA/SM -----------------------
// Block 64x256, 256 threads = 8 warps (2x4), warp 32x64. K chunks of 64,
// double-buffered. Stage (40KB): A[8K] B[32K]. 2 CTAs resident per SM.
#define ST_A  0
#define ST_B  8192
#define ST_SZ 40960
#define SM1_SZ (2 * ST_SZ)

struct APref { float4 v[2][2]; };

__device__ __forceinline__ void loadA_regs(const float* __restrict__ A, int row0,
                                           int k0, int tid, APref& ap) {
#pragma unroll
    for (int j = 0; j < 2; j++) {
        int i = tid + j * 256;          // 0..511 over 64 rows x 8 segs
        int r = i >> 3;
        int seg = i & 7;
        int gr = row0 + r;
        if (gr >= Nn) gr = Nn - 1;
        const float4* p = (const float4*)(A + (size_t)gr * F_IN + k0 + seg * 8);
        ap.v[j][0] = p[0];
        ap.v[j][1] = p[1];
    }
}
__device__ __forceinline__ void storeA_smem(char* sm, int boff, int tid, const APref& ap) {
#pragma unroll
    for (int j = 0; j < 2; j++) {
        int i = tid + j * 256;
        int r = i >> 3;
        int seg = i & 7;
        float4 v0 = ap.v[j][0], v1 = ap.v[j][1];
        uint4 h;
        __half2 h0 = __floats2half2_rn(v0.x, v0.y);
        __half2 h1 = __floats2half2_rn(v0.z, v0.w);
        __half2 h2 = __floats2half2_rn(v1.x, v1.y);
        __half2 h3 = __floats2half2_rn(v1.z, v1.w);
        h.x = *(unsigned*)&h0; h.y = *(unsigned*)&h1;
        h.z = *(unsigned*)&h2; h.w = *(unsigned*)&h3;
        int ps = seg ^ (r & 7);
        *(uint4*)(sm + boff + ST_A + (r * 8 + ps) * 16) = h;
    }
}
__device__ __forceinline__ void issueB_cpasync(uint32_t sbase, int boff, int k0, int tid) {
#pragma unroll
    for (int j = 0; j < 8; j++) {
        int i = tid + j * 256;          // 0..2047 over 256 n x 8 segs
        int n = i >> 3;
        int seg = i & 7;
        int ps = seg ^ (n & 7);
        size_t src = ((size_t)n * F_IN + k0 + seg * 8) * 2;
        uint32_t doff = (uint32_t)((n * 8 + ps) * 16);
        cpa16(sbase + boff + ST_B + doff, (const char*)g_B + src);
    }
}

__global__ void __launch_bounds__(256, 2) k_gemm1_mma(const float* __restrict__ A) {
    extern __shared__ char sm[];
    uint32_t sbase = smem_u32(sm);
    int tid = threadIdx.x;
    int wid = tid >> 5;
    int lane = tid & 31;
    int warp_m = wid & 1;           // 2 row slices of 32
    int warp_n = wid >> 1;          // 4 col slices of 64
    int row0 = blockIdx.x * 64;

    float acc[2][8][4];
#pragma unroll
    for (int mt = 0; mt < 2; mt++)
#pragma unroll
        for (int nt = 0; nt < 8; nt++)
#pragma unroll
            for (int q = 0; q < 4; q++) acc[mt][nt][q] = 0.f;

    APref ap;
    loadA_regs(A, row0, 0, tid, ap);
    issueB_cpasync(sbase, 0, 0, tid);
    CPA_COMMIT();
    storeA_smem(sm, 0, tid, ap);

#pragma unroll 1
    for (int ck = 0; ck < 8; ck++) {
        int cur = ck & 1;
        int boff_cur = cur * ST_SZ;
        int boff_nxt = (cur ^ 1) * ST_SZ;
        if (ck < 7) {
            loadA_regs(A, row0, (ck + 1) * 64, tid, ap);
            issueB_cpasync(sbase, boff_nxt, (ck + 1) * 64, tid);
        }
        CPA_COMMIT();
        CPA_WAIT1();
        __syncthreads();

        uint32_t baseA = sbase + boff_cur + ST_A;
        uint32_t baseB = sbase + boff_cur + ST_B;
#pragma unroll
        for (int s = 0; s < 4; s++) {
            unsigned ah[2][4];
#pragma unroll
            for (int mt = 0; mt < 2; mt++) {
                int q = lane >> 3;
                int r = warp_m * 32 + mt * 16 + (q & 1) * 8 + (lane & 7);
                int seg = s * 2 + (q >> 1);
                uint32_t off = (uint32_t)(r * 8 + (seg ^ (r & 7))) * 16;
                ldm_x4(ah[mt], baseA + off);
            }
#pragma unroll
            for (int jp = 0; jp < 4; jp++) {
                unsigned b4[4];
                int q = lane >> 3;
                int n = warp_n * 64 + (jp * 2 + (q >> 1)) * 8 + (lane & 7);
                int seg = s * 2 + (q & 1);
                uint32_t off = (uint32_t)(n * 8 + (seg ^ (n & 7))) * 16;
                ldm_x4(b4, baseB + off);
                mma_f16(acc[0][jp * 2],     ah[0], &b4[0]);
                mma_f16(acc[1][jp * 2],     ah[1], &b4[0]);
                mma_f16(acc[0][jp * 2 + 1], ah[0], &b4[2]);
                mma_f16(acc[1][jp * 2 + 1], ah[1], &b4[2]);
            }
        }
        if (ck < 7) storeA_smem(sm, boff_nxt, tid, ap);
        __syncthreads();
    }

    // epilogue: write h1 as fp16
#pragma unroll
    for (int mt = 0; mt < 2; mt++)
#pragma unroll
        for (int nt = 0; nt < 8; nt++) {
            int r = row0 + warp_m * 32 + mt * 16 + (lane >> 2);
            int col = warp_n * 64 + nt * 8 + (lane & 3) * 2;
            if (r < Nn)
                *(__half2*)(g_h1h + (size_t)r * H1 + col) =
                    __floats2half2_rn(acc[mt][nt][0], acc[mt][nt][1]);
            if (r + 8 < Nn)
                *(__half2*)(g_h1h + (size_t)(r + 8) * H1 + col) =
                    __floats2half2_rn(acc[mt][nt][2], acc[mt][nt][3]);
        }
}

// ---------------- GEMM2: g_x2h [Nn,256] fp16 x W2 [256,32] -> g_h2 ----------
__global__ void k_gemm2(const float* __restrict__ W) {
    __shared__ float sA[32][64];
    __shared__ float sW[64][32];
    int tid = threadIdx.x;
    int r = tid >> 3;
    int c4 = (tid & 7) * 4;
    int row0 = blockIdx.x * 32;
    float acc[4] = {0.f, 0.f, 0.f, 0.f};
    for (int k0 = 0; k0 < H1; k0 += 64) {
        // stage 32 rows x 64 k from fp16 x2 (8 uint4 per row)
        for (int i = tid; i < 32 * 8; i += 256) {
            int rr = i >> 3;
            int kk8 = (i & 7) * 8;
            int grow = row0 + rr;
            if (grow >= Nn) grow = Nn - 1;
            uint4 u = *(const uint4*)(g_x2h + (size_t)grow * H1 + k0 + kk8);
            const __half2* h = (const __half2*)&u;
            float2 f0 = __half22float2(h[0]);
            float2 f1 = __half22float2(h[1]);
            float2 f2 = __half22float2(h[2]);
            float2 f3 = __half22float2(h[3]);
            *(float4*)(&sA[rr][kk8])     = make_float4(f0.x, f0.y, f1.x, f1.y);
            *(float4*)(&sA[rr][kk8 + 4]) = make_float4(f2.x, f2.y, f3.x, f3.y);
        }
        for (int i = tid; i < 512; i += 256) {
            int kk = i >> 3;
            int cc4 = (i & 7) * 4;
            *(float4*)(&sW[kk][cc4]) = *(const float4*)(W + (size_t)(k0 + kk) * H2 + cc4);
        }
        __syncthreads();
#pragma unroll
        for (int kk = 0; kk < 64; kk++) {
            float a = sA[r][kk];
            acc[0] += a * sW[kk][c4 + 0];
            acc[1] += a * sW[kk][c4 + 1];
            acc[2] += a * sW[kk][c4 + 2];
            acc[3] += a * sW[kk][c4 + 3];
        }
        __syncthreads();
    }
    int row = row0 + r;
    if (row < Nn) {
        float4 v = make_float4(acc[0], acc[1], acc[2], acc[3]);
        *(float4*)(g_h2 + (size_t)row * H2 + c4) = v;
    }
}

// ---------------- GEMM3: g_x3 [Nn,32] x W3 [32,16] -> g_h3 ------------------
__global__ void k_gemm3(const float* __restrict__ W) {
    __shared__ float sW[32 * 16];
    int tid = threadIdx.x;
    for (int i = tid; i < 32 * 16; i += 256) sW[i] = W[i];
    __syncthreads();
    int row = blockIdx.x * 256 + tid;
    if (row >= Nn) return;
    float acc[16];
#pragma unroll
    for (int c = 0; c < 16; c++) acc[c] = 0.f;
    const float4* ap = (const float4*)(g_x3 + (size_t)row * H2);
#pragma unroll
    for (int k4 = 0; k4 < 8; k4++) {
        float4 a = ap[k4];
        int k = k4 * 4;
#pragma unroll
        for (int c = 0; c < 16; c++) {
            acc[c] += a.x * sW[(k + 0) * 16 + c];
            acc[c] += a.y * sW[(k + 1) * 16 + c];
            acc[c] += a.z * sW[(k + 2) * 16 + c];
            acc[c] += a.w * sW[(k + 3) * 16 + c];
        }
    }
    float* op = g_h3 + (size_t)row * Cc;
#pragma unroll
    for (int c4 = 0; c4 < 4; c4++) {
        float4 v = make_float4(acc[c4 * 4 + 0], acc[c4 * 4 + 1], acc[c4 * 4 + 2], acc[c4 * 4 + 3]);
        *(float4*)(op + c4 * 4) = v;
    }
}

// ---------------- Aggregation ------------------------------------------------
__global__ void k_agg256(const float* __restrict__ bias) {
    int warp = threadIdx.x >> 5;
    int lane = threadIdx.x & 31;
    int node = blockIdx.x * 8 + warp;
    if (node >= Nn) return;
    float wd = g_dinv[node];
    const uint4* hp = (const uint4*)(g_h1h);
    float acc[8] = {};
    h8_fma(hp[(size_t)node * 32 + lane], wd, acc);
    int beg = g_rowstart[node];
    int cnt = g_deg[node];
    int j = 0;
    for (; j + 2 <= cnt; j += 2) {
        int s0 = g_col[beg + j];
        int s1 = g_col[beg + j + 1];
        float w0 = g_dinv[s0];
        float w1 = g_dinv[s1];
        uint4 u = hp[(size_t)s0 * 32 + lane];
        uint4 v = hp[(size_t)s1 * 32 + lane];
        h8_fma(u, w0, acc);
        h8_fma(v, w1, acc);
    }
    if (j < cnt) {
        int s = g_col[beg + j];
        h8_fma(hp[(size_t)s * 32 + lane], g_dinv[s], acc);
    }
    const float4* bp = (const float4*)(bias + lane * 8);
    float4 b0 = bp[0], b1 = bp[1];
    float r0 = fmaxf(acc[0] * wd + b0.x, 0.f), r1 = fmaxf(acc[1] * wd + b0.y, 0.f);
    float r2 = fmaxf(acc[2] * wd + b0.z, 0.f), r3 = fmaxf(acc[3] * wd + b0.w, 0.f);
    float r4 = fmaxf(acc[4] * wd + b1.x, 0.f), r5 = fmaxf(acc[5] * wd + b1.y, 0.f);
    float r6 = fmaxf(acc[6] * wd + b1.z, 0.f), r7 = fmaxf(acc[7] * wd + b1.w, 0.f);
    // write x2 as fp16 (halves gemm2 read traffic)
    uint4 o;
    __half2 o0 = __floats2half2_rn(r0, r1);
    __half2 o1 = __floats2half2_rn(r2, r3);
    __half2 o2 = __floats2half2_rn(r4, r5);
    __half2 o3 = __floats2half2_rn(r6, r7);
    o.x = *(unsigned*)&o0; o.y = *(unsigned*)&o1;
    o.z = *(unsigned*)&o2; o.w = *(unsigned*)&o3;
    *(uint4*)(g_x2h + (size_t)node * 256 + lane * 8) = o;
}

__global__ void k_agg32(const float* __restrict__ bias) {
    int warp = threadIdx.x >> 5;
    int lane = threadIdx.x & 31;
    int node = blockIdx.x * 8 + warp;
    if (node >= Nn) return;
    float wd = g_dinv[node];
    float acc = wd * g_h2[(size_t)node * 32 + lane];
    int beg = g_rowstart[node];
    int cnt = g_deg[node];
    int j = 0;
    for (; j + 2 <= cnt; j += 2) {
        int s0 = g_col[beg + j];
        int s1 = g_col[beg + j + 1];
        float w0 = g_dinv[s0];
        float w1 = g_dinv[s1];
        float u = g_h2[(size_t)s0 * 32 + lane];
        float v = g_h2[(size_t)s1 * 32 + lane];
        acc += w0 * u + w1 * v;
    }
    if (j < cnt) {
        int s = g_col[beg + j];
        acc += g_dinv[s] * g_h2[(size_t)s * 32 + lane];
    }
    float r = acc * wd + bias[lane];
    g_x3[(size_t)node * 32 + lane] = fmaxf(r, 0.f);
}

__global__ void k_agg16(const float* __restrict__ bias, float* __restrict__ out) {
    int tid = threadIdx.x;
    int local = tid & 15;
    int node = blockIdx.x * 16 + (tid >> 4);
    if (node >= Nn) return;
    float wd = g_dinv[node];
    float acc = wd * g_h3[(size_t)node * 16 + local];
    int beg = g_rowstart[node];
    int cnt = g_deg[node];
    for (int j = 0; j < cnt; j++) {
        int s = g_col[beg + j];
        acc += g_dinv[s] * g_h3[(size_t)s * 16 + local];
    }
    out[(size_t)node * 16 + local] = acc * wd + bias[local];
}

// ---------------- stream/event singletons (created once, reused) -------------
static cudaStream_t get_side_stream() {
    static cudaStream_t s = [] {
        cudaStream_t t;
        cudaStreamCreateWithFlags(&t, cudaStreamNonBlocking);
        return t;
    }();
    return s;
}
static cudaEvent_t get_event(int which) {
    static cudaEvent_t e0 = [] {
        cudaEvent_t e;
        cudaEventCreateWithFlags(&e, cudaEventDisableTiming);
        return e;
    }();
    static cudaEvent_t e1 = [] {
        cudaEvent_t e;
        cudaEventCreateWithFlags(&e, cudaEventDisableTiming);
        return e;
    }();
    return which ? e1 : e0;
}

// ---------------- launch -----------------------------------------------------
extern "C" void kernel_launch(void* const* d_in, const int* in_sizes, int n_in,
                              void* d_out, int out_size) {
    const float* x   = (const float*)d_in[0];
    const void*  ei  = (const void*)d_in[1];
    const float* W1  = (const float*)d_in[2];
    const float* b1  = (const float*)d_in[3];
    const float* W2  = (const float*)d_in[4];
    const float* b2  = (const float*)d_in[5];
    const float* W3  = (const float*)d_in[6];
    const float* b3  = (const float*)d_in[7];
    float* out       = (float*)d_out;

    cudaFuncSetAttribute(k_gemm1_mma, cudaFuncAttributeMaxDynamicSharedMemorySize, SM1_SZ);

    const int scanBlocks = (Nn + 1023) / 1024;   // 49
    cudaStream_t side = get_side_stream();
    cudaEvent_t evFork = get_event(0);
    cudaEvent_t evJoin = get_event(1);

    // fork: CSR build on side stream, gemm1 path on main stream
    cudaEventRecord(evFork, 0);
    cudaStreamWaitEvent(side, evFork, 0);

    k_detect<<<1, 32, 0, side>>>((const unsigned int*)ei);
    k_zero_deg<<<(Nn + 255) / 256, 256, 0, side>>>();
    k_count<<<(Ee + 255) / 256, 256, 0, side>>>(ei);
    k_scan1<<<scanBlocks, 1024, 0, side>>>();
    k_scan2<<<1, 32, 0, side>>>(scanBlocks);
    k_scan3<<<(Nn + 255) / 256, 256, 0, side>>>();
    k_scatter<<<(Ee + 255) / 256, 256, 0, side>>>(ei);
    cudaEventRecord(evJoin, side);

    k_cvtW<<<(F_IN * H1 + 255) / 256, 256>>>(W1);
    k_gemm1_mma<<<(Nn + 63) / 64, 256, SM1_SZ>>>(x);

    // join before aggregation (needs CSR + h1)
    cudaStreamWaitEvent(0, evJoin, 0);

    k_agg256<<<(Nn + 7) / 8, 256>>>(b1);
    k_gemm2<<<(Nn + 31) / 32, 256>>>(W2);
    k_agg32<<<(Nn + 7) / 8, 256>>>(b2);
    k_gemm3<<<(Nn + 255) / 256, 256>>>(W3);
    k_agg16<<<(Nn + 15) / 16, 256>>>(b3, out);
}

// round 15
// speedup vs baseline: 1.6800x; 1.0044x over previous
#include <cuda_runtime.h>
#include <cuda_bf16.h>
#include <cuda_fp16.h>
#include <cstdint>

#define Nn   50000
#define Ee   800000
#define F_IN 512
#define H1   256
#define H2   32
#define Cc   16

// ---------------- scratch (device globals; no allocations allowed) ----------
static __device__ __half g_h1h[(size_t)Nn * H1];   // x @ W1 (fp16)
static __device__ __half g_x2h[(size_t)Nn * H1];   // relu(agg1+b1) (fp16)
static __device__ __half g_h2h[(size_t)Nn * H2];   // x2 @ W2 (fp16)
static __device__ float g_x3[(size_t)Nn * H2];
static __device__ __half g_h3h[(size_t)Nn * Cc];   // x3 @ W3 (fp16)
static __device__ float g_dinv[Nn];
static __device__ int   g_deg[Nn];
static __device__ int   g_incl[Nn];
static __device__ int   g_rowstart[Nn];
static __device__ int   g_fill[Nn];
static __device__ int   g_col[Ee];
static __device__ int   g_blocksums[64];
static __device__ int   g_is64;
// W1^T fp16: [256 n][512 k]
static __device__ __half g_B[(size_t)H1 * F_IN];

// ---------------- helpers ----------------------------------------------------
__device__ __forceinline__ uint32_t smem_u32(const void* p) {
    uint32_t a;
    asm("{ .reg .u64 t; cvta.to.shared.u64 t, %1; cvt.u32.u64 %0, t; }" : "=r"(a) : "l"(p));
    return a;
}
__device__ __forceinline__ void ldm_x4(unsigned* r, uint32_t addr) {
    asm volatile("ldmatrix.sync.aligned.m8n8.x4.shared.b16 {%0,%1,%2,%3}, [%4];"
                 : "=r"(r[0]), "=r"(r[1]), "=r"(r[2]), "=r"(r[3]) : "r"(addr));
}
__device__ __forceinline__ void mma_f16(float* c, const unsigned* a, const unsigned* b) {
    asm volatile(
        "mma.sync.aligned.m16n8k16.row.col.f32.f16.f16.f32 "
        "{%0,%1,%2,%3},{%4,%5,%6,%7},{%8,%9},{%0,%1,%2,%3};"
        : "+f"(c[0]), "+f"(c[1]), "+f"(c[2]), "+f"(c[3])
        : "r"(a[0]), "r"(a[1]), "r"(a[2]), "r"(a[3]), "r"(b[0]), "r"(b[1]));
}
__device__ __forceinline__ void cpa16(uint32_t dst, const void* src) {
    asm volatile("cp.async.cg.shared.global [%0], [%1], 16;" :: "r"(dst), "l"(src));
}
#define CPA_COMMIT() asm volatile("cp.async.commit_group;" ::: "memory")
#define CPA_WAIT1()  asm volatile("cp.async.wait_group 1;" ::: "memory")

// fp16 row-slice fused accumulate: acc[0..7] += w * h8(u)
__device__ __forceinline__ void h8_fma(uint4 u, float w, float* acc) {
    const __half2* h = (const __half2*)&u;
#pragma unroll
    for (int i = 0; i < 4; i++) {
        float2 f = __half22float2(h[i]);
        acc[2 * i]     += w * f.x;
        acc[2 * i + 1] += w * f.y;
    }
}

// ---------------- edge-index dtype detection --------------------------------
__global__ void k_detect(const unsigned int* __restrict__ w) {
    if (threadIdx.x == 0 && blockIdx.x == 0) {
        int is64 = 1;
        for (int i = 1; i < 512; i += 2) {
            if (w[i] != 0u) { is64 = 0; break; }
        }
        g_is64 = is64;
    }
}
__device__ __forceinline__ int load_idx(const void* __restrict__ ei, long long idx) {
    if (g_is64) return (int)((const long long*)ei)[idx];
    return ((const int*)ei)[idx];
}

// ---------------- CSR build --------------------------------------------------
__global__ void k_zero_deg() {
    int i = blockIdx.x * blockDim.x + threadIdx.x;
    if (i < Nn) g_deg[i] = 0;
}
__global__ void k_count(const void* __restrict__ ei) {
    int e = blockIdx.x * blockDim.x + threadIdx.x;
    if (e < Ee) atomicAdd(&g_deg[load_idx(ei, (long long)Ee + e)], 1);
}
__global__ void k_scan1() {
    __shared__ int s[1024];
    int t = threadIdx.x;
    int i = blockIdx.x * 1024 + t;
    s[t] = (i < Nn) ? g_deg[i] : 0;
    __syncthreads();
    for (int off = 1; off < 1024; off <<= 1) {
        int add = (t >= off) ? s[t - off] : 0;
        __syncthreads();
        s[t] += add;
        __syncthreads();
    }
    if (i < Nn) g_incl[i] = s[t];
    if (t == 1023) g_blocksums[blockIdx.x] = s[1023];
}
__global__ void k_scan2(int nblocks) {
    if (threadIdx.x == 0) {
        int run = 0;
        for (int i = 0; i < nblocks; i++) { int v = g_blocksums[i]; g_blocksums[i] = run; run += v; }
    }
}
__global__ void k_scan3() {
    int i = blockIdx.x * blockDim.x + threadIdx.x;
    if (i < Nn) {
        int deg = g_deg[i];
        int start = g_incl[i] - deg + g_blocksums[i >> 10];
        g_rowstart[i] = start;
        g_fill[i] = start;
        g_dinv[i] = rsqrtf((float)(deg + 1));
    }
}
__global__ void k_scatter(const void* __restrict__ ei) {
    int e = blockIdx.x * blockDim.x + threadIdx.x;
    if (e < Ee) {
        int s = load_idx(ei, e);
        int d = load_idx(ei, (long long)Ee + e);
        int pos = atomicAdd(&g_fill[d], 1);
        g_col[pos] = s;
    }
}

// ---------------- W1 transpose -> fp16 ----------------------------------------
__global__ void k_cvtW(const float* __restrict__ W1) {
    int i = blockIdx.x * blockDim.x + threadIdx.x;
    if (i < F_IN * H1) {
        int k = i >> 8;
        int n = i & 255;
        g_B[(size_t)n * F_IN + k] = __float2half_rn(W1[i]);
    }
}

// ---------------- GEMM1: plain fp16 mma.sync, 2 CTA/SM -----------------------
#define ST_A  0
#define ST_B  8192
#define ST_SZ 40960
#define SM1_SZ (2 * ST_SZ)

struct APref { float4 v[2][2]; };

__device__ __forceinline__ void loadA_regs(const float* __restrict__ A, int row0,
                                           int k0, int tid, APref& ap) {
#pragma unroll
    for (int j = 0; j < 2; j++) {
        int i = tid + j * 256;
        int r = i >> 3;
        int seg = i & 7;
        int gr = row0 + r;
        if (gr >= Nn) gr = Nn - 1;
        const float4* p = (const float4*)(A + (size_t)gr * F_IN + k0 + seg * 8);
        ap.v[j][0] = p[0];
        ap.v[j][1] = p[1];
    }
}
__device__ __forceinline__ void storeA_smem(char* sm, int boff, int tid, const APref& ap) {
#pragma unroll
    for (int j = 0; j < 2; j++) {
        int i = tid + j * 256;
        int r = i >> 3;
        int seg = i & 7;
        float4 v0 = ap.v[j][0], v1 = ap.v[j][1];
        uint4 h;
        __half2 h0 = __floats2half2_rn(v0.x, v0.y);
        __half2 h1 = __floats2half2_rn(v0.z, v0.w);
        __half2 h2 = __floats2half2_rn(v1.x, v1.y);
        __half2 h3 = __floats2half2_rn(v1.z, v1.w);
        h.x = *(unsigned*)&h0; h.y = *(unsigned*)&h1;
        h.z = *(unsigned*)&h2; h.w = *(unsigned*)&h3;
        int ps = seg ^ (r & 7);
        *(uint4*)(sm + boff + ST_A + (r * 8 + ps) * 16) = h;
    }
}
__device__ __forceinline__ void issueB_cpasync(uint32_t sbase, int boff, int k0, int tid) {
#pragma unroll
    for (int j = 0; j < 8; j++) {
        int i = tid + j * 256;
        int n = i >> 3;
        int seg = i & 7;
        int ps = seg ^ (n & 7);
        size_t src = ((size_t)n * F_IN + k0 + seg * 8) * 2;
        uint32_t doff = (uint32_t)((n * 8 + ps) * 16);
        cpa16(sbase + boff + ST_B + doff, (const char*)g_B + src);
    }
}

__global__ void __launch_bounds__(256, 2) k_gemm1_mma(const float* __restrict__ A) {
    extern __shared__ char sm[];
    uint32_t sbase = smem_u32(sm);
    int tid = threadIdx.x;
    int wid = tid >> 5;
    int lane = tid & 31;
    int warp_m = wid & 1;
    int warp_n = wid >> 1;
    int row0 = blockIdx.x * 64;

    float acc[2][8][4];
#pragma unroll
    for (int mt = 0; mt < 2; mt++)
#pragma unroll
        for (int nt = 0; nt < 8; nt++)
#pragma unroll
            for (int q = 0; q < 4; q++) acc[mt][nt][q] = 0.f;

    APref ap;
    loadA_regs(A, row0, 0, tid, ap);
    issueB_cpasync(sbase, 0, 0, tid);
    CPA_COMMIT();
    storeA_smem(sm, 0, tid, ap);

#pragma unroll 1
    for (int ck = 0; ck < 8; ck++) {
        int cur = ck & 1;
        int boff_cur = cur * ST_SZ;
        int boff_nxt = (cur ^ 1) * ST_SZ;
        if (ck < 7) {
            loadA_regs(A, row0, (ck + 1) * 64, tid, ap);
            issueB_cpasync(sbase, boff_nxt, (ck + 1) * 64, tid);
        }
        CPA_COMMIT();
        CPA_WAIT1();
        __syncthreads();

        uint32_t baseA = sbase + boff_cur + ST_A;
        uint32_t baseB = sbase + boff_cur + ST_B;
#pragma unroll
        for (int s = 0; s < 4; s++) {
            unsigned ah[2][4];
#pragma unroll
            for (int mt = 0; mt < 2; mt++) {
                int q = lane >> 3;
                int r = warp_m * 32 + mt * 16 + (q & 1) * 8 + (lane & 7);
                int seg = s * 2 + (q >> 1);
                uint32_t off = (uint32_t)(r * 8 + (seg ^ (r & 7))) * 16;
                ldm_x4(ah[mt], baseA + off);
            }
#pragma unroll
            for (int jp = 0; jp < 4; jp++) {
                unsigned b4[4];
                int q = lane >> 3;
                int n = warp_n * 64 + (jp * 2 + (q >> 1)) * 8 + (lane & 7);
                int seg = s * 2 + (q & 1);
                uint32_t off = (uint32_t)(n * 8 + (seg ^ (n & 7))) * 16;
                ldm_x4(b4, baseB + off);
                mma_f16(acc[0][jp * 2],     ah[0], &b4[0]);
                mma_f16(acc[1][jp * 2],     ah[1], &b4[0]);
                mma_f16(acc[0][jp * 2 + 1], ah[0], &b4[2]);
                mma_f16(acc[1][jp * 2 + 1], ah[1], &b4[2]);
            }
        }
        if (ck < 7) storeA_smem(sm, boff_nxt, tid, ap);
        __syncthreads();
    }

#pragma unroll
    for (int mt = 0; mt < 2; mt++)
#pragma unroll
        for (int nt = 0; nt < 8; nt++) {
            int r = row0 + warp_m * 32 + mt * 16 + (lane >> 2);
            int col = warp_n * 64 + nt * 8 + (lane & 3) * 2;
            if (r < Nn)
                *(__half2*)(g_h1h + (size_t)r * H1 + col) =
                    __floats2half2_rn(acc[mt][nt][0], acc[mt][nt][1]);
            if (r + 8 < Nn)
                *(__half2*)(g_h1h + (size_t)(r + 8) * H1 + col) =
                    __floats2half2_rn(acc[mt][nt][2], acc[mt][nt][3]);
        }
}

// ---------------- GEMM2: g_x2h [Nn,256] fp16 x W2 [256,32] -> g_h2h ---------
__global__ void k_gemm2(const float* __restrict__ W) {
    __shared__ float sA[32][64];
    __shared__ float sW[64][32];
    int tid = threadIdx.x;
    int r = tid >> 3;
    int c4 = (tid & 7) * 4;
    int row0 = blockIdx.x * 32;
    float acc[4] = {0.f, 0.f, 0.f, 0.f};
    for (int k0 = 0; k0 < H1; k0 += 64) {
        for (int i = tid; i < 32 * 8; i += 256) {
            int rr = i >> 3;
            int kk8 = (i & 7) * 8;
            int grow = row0 + rr;
            if (grow >= Nn) grow = Nn - 1;
            uint4 u = *(const uint4*)(g_x2h + (size_t)grow * H1 + k0 + kk8);
            const __half2* h = (const __half2*)&u;
            float2 f0 = __half22float2(h[0]);
            float2 f1 = __half22float2(h[1]);
            float2 f2 = __half22float2(h[2]);
            float2 f3 = __half22float2(h[3]);
            *(float4*)(&sA[rr][kk8])     = make_float4(f0.x, f0.y, f1.x, f1.y);
            *(float4*)(&sA[rr][kk8 + 4]) = make_float4(f2.x, f2.y, f3.x, f3.y);
        }
        for (int i = tid; i < 512; i += 256) {
            int kk = i >> 3;
            int cc4 = (i & 7) * 4;
            *(float4*)(&sW[kk][cc4]) = *(const float4*)(W + (size_t)(k0 + kk) * H2 + cc4);
        }
        __syncthreads();
#pragma unroll
        for (int kk = 0; kk < 64; kk++) {
            float a = sA[r][kk];
            acc[0] += a * sW[kk][c4 + 0];
            acc[1] += a * sW[kk][c4 + 1];
            acc[2] += a * sW[kk][c4 + 2];
            acc[3] += a * sW[kk][c4 + 3];
        }
        __syncthreads();
    }
    int row = row0 + r;
    if (row < Nn) {
        __half2 o0 = __floats2half2_rn(acc[0], acc[1]);
        __half2 o1 = __floats2half2_rn(acc[2], acc[3]);
        uint2 o;
        o.x = *(unsigned*)&o0;
        o.y = *(unsigned*)&o1;
        *(uint2*)(g_h2h + (size_t)row * H2 + c4) = o;
    }
}

// ---------------- GEMM3: g_x3 [Nn,32] x W3 [32,16] -> g_h3h -----------------
__global__ void k_gemm3(const float* __restrict__ W) {
    __shared__ float sW[32 * 16];
    int tid = threadIdx.x;
    for (int i = tid; i < 32 * 16; i += 256) sW[i] = W[i];
    __syncthreads();
    int row = blockIdx.x * 256 + tid;
    if (row >= Nn) return;
    float acc[16];
#pragma unroll
    for (int c = 0; c < 16; c++) acc[c] = 0.f;
    const float4* ap = (const float4*)(g_x3 + (size_t)row * H2);
#pragma unroll
    for (int k4 = 0; k4 < 8; k4++) {
        float4 a = ap[k4];
        int k = k4 * 4;
#pragma unroll
        for (int c = 0; c < 16; c++) {
            acc[c] += a.x * sW[(k + 0) * 16 + c];
            acc[c] += a.y * sW[(k + 1) * 16 + c];
            acc[c] += a.z * sW[(k + 2) * 16 + c];
            acc[c] += a.w * sW[(k + 3) * 16 + c];
        }
    }
    // write fp16 (16 halfs = 2x uint4)
    uint4 o0, o1;
    __half2 p0 = __floats2half2_rn(acc[0], acc[1]);
    __half2 p1 = __floats2half2_rn(acc[2], acc[3]);
    __half2 p2 = __floats2half2_rn(acc[4], acc[5]);
    __half2 p3 = __floats2half2_rn(acc[6], acc[7]);
    __half2 p4 = __floats2half2_rn(acc[8], acc[9]);
    __half2 p5 = __floats2half2_rn(acc[10], acc[11]);
    __half2 p6 = __floats2half2_rn(acc[12], acc[13]);
    __half2 p7 = __floats2half2_rn(acc[14], acc[15]);
    o0.x = *(unsigned*)&p0; o0.y = *(unsigned*)&p1;
    o0.z = *(unsigned*)&p2; o0.w = *(unsigned*)&p3;
    o1.x = *(unsigned*)&p4; o1.y = *(unsigned*)&p5;
    o1.z = *(unsigned*)&p6; o1.w = *(unsigned*)&p7;
    uint4* op = (uint4*)(g_h3h + (size_t)row * Cc);
    op[0] = o0;
    op[1] = o1;
}

// ---------------- Aggregation ------------------------------------------------
__global__ void k_agg256(const float* __restrict__ bias) {
    int warp = threadIdx.x >> 5;
    int lane = threadIdx.x & 31;
    int node = blockIdx.x * 8 + warp;
    if (node >= Nn) return;
    float wd = g_dinv[node];
    const uint4* hp = (const uint4*)(g_h1h);
    float acc[8] = {};
    h8_fma(hp[(size_t)node * 32 + lane], wd, acc);
    int beg = g_rowstart[node];
    int cnt = g_deg[node];
    int j = 0;
    for (; j + 2 <= cnt; j += 2) {
        int s0 = g_col[beg + j];
        int s1 = g_col[beg + j + 1];
        float w0 = g_dinv[s0];
        float w1 = g_dinv[s1];
        uint4 u = hp[(size_t)s0 * 32 + lane];
        uint4 v = hp[(size_t)s1 * 32 + lane];
        h8_fma(u, w0, acc);
        h8_fma(v, w1, acc);
    }
    if (j < cnt) {
        int s = g_col[beg + j];
        h8_fma(hp[(size_t)s * 32 + lane], g_dinv[s], acc);
    }
    const float4* bp = (const float4*)(bias + lane * 8);
    float4 b0 = bp[0], b1 = bp[1];
    float r0 = fmaxf(acc[0] * wd + b0.x, 0.f), r1 = fmaxf(acc[1] * wd + b0.y, 0.f);
    float r2 = fmaxf(acc[2] * wd + b0.z, 0.f), r3 = fmaxf(acc[3] * wd + b0.w, 0.f);
    float r4 = fmaxf(acc[4] * wd + b1.x, 0.f), r5 = fmaxf(acc[5] * wd + b1.y, 0.f);
    float r6 = fmaxf(acc[6] * wd + b1.z, 0.f), r7 = fmaxf(acc[7] * wd + b1.w, 0.f);
    uint4 o;
    __half2 o0 = __floats2half2_rn(r0, r1);
    __half2 o1 = __floats2half2_rn(r2, r3);
    __half2 o2 = __floats2half2_rn(r4, r5);
    __half2 o3 = __floats2half2_rn(r6, r7);
    o.x = *(unsigned*)&o0; o.y = *(unsigned*)&o1;
    o.z = *(unsigned*)&o2; o.w = *(unsigned*)&o3;
    *(uint4*)(g_x2h + (size_t)node * 256 + lane * 8) = o;
}

// Layer 2 aggregation: gather fp16 h2, fp32 math, write fp32 x3.
__global__ void k_agg32(const float* __restrict__ bias) {
    int warp = threadIdx.x >> 5;
    int lane = threadIdx.x & 31;
    int node = blockIdx.x * 8 + warp;
    if (node >= Nn) return;
    float wd = g_dinv[node];
    float acc = wd * __half2float(g_h2h[(size_t)node * 32 + lane]);
    int beg = g_rowstart[node];
    int cnt = g_deg[node];
    int j = 0;
    for (; j + 2 <= cnt; j += 2) {
        int s0 = g_col[beg + j];
        int s1 = g_col[beg + j + 1];
        float w0 = g_dinv[s0];
        float w1 = g_dinv[s1];
        float u = __half2float(g_h2h[(size_t)s0 * 32 + lane]);
        float v = __half2float(g_h2h[(size_t)s1 * 32 + lane]);
        acc += w0 * u + w1 * v;
    }
    if (j < cnt) {
        int s = g_col[beg + j];
        acc += g_dinv[s] * __half2float(g_h2h[(size_t)s * 32 + lane]);
    }
    float r = acc * wd + bias[lane];
    g_x3[(size_t)node * 32 + lane] = fmaxf(r, 0.f);
}

// Layer 3 aggregation: gather fp16 h3, write fp32 out.
__global__ void k_agg16(const float* __restrict__ bias, float* __restrict__ out) {
    int tid = threadIdx.x;
    int local = tid & 15;
    int node = blockIdx.x * 16 + (tid >> 4);
    if (node >= Nn) return;
    float wd = g_dinv[node];
    float acc = wd * __half2float(g_h3h[(size_t)node * 16 + local]);
    int beg = g_rowstart[node];
    int cnt = g_deg[node];
    int j = 0;
    for (; j + 2 <= cnt; j += 2) {
        int s0 = g_col[beg + j];
        int s1 = g_col[beg + j + 1];
        float u = __half2float(g_h3h[(size_t)s0 * 16 + local]);
        float v = __half2float(g_h3h[(size_t)s1 * 16 + local]);
        acc += g_dinv[s0] * u + g_dinv[s1] * v;
    }
    if (j < cnt) {
        int s = g_col[beg + j];
        acc += g_dinv[s] * __half2float(g_h3h[(size_t)s * 16 + local]);
    }
    out[(size_t)node * 16 + local] = acc * wd + bias[local];
}

// ---------------- stream/event singletons (created once, reused) -------------
static cudaStream_t get_side_stream() {
    static cudaStream_t s = [] {
        cudaStream_t t;
        cudaStreamCreateWithFlags(&t, cudaStreamNonBlocking);
        return t;
    }();
    return s;
}
static cudaEvent_t get_event(int which) {
    static cudaEvent_t e0 = [] {
        cudaEvent_t e;
        cudaEventCreateWithFlags(&e, cudaEventDisableTiming);
        return e;
    }();
    static cudaEvent_t e1 = [] {
        cudaEvent_t e;
        cudaEventCreateWithFlags(&e, cudaEventDisableTiming);
        return e;
    }();
    return which ? e1 : e0;
}

// ---------------- launch -----------------------------------------------------
extern "C" void kernel_launch(void* const* d_in, const int* in_sizes, int n_in,
                              void* d_out, int out_size) {
    const float* x   = (const float*)d_in[0];
    const void*  ei  = (const void*)d_in[1];
    const float* W1  = (const float*)d_in[2];
    const float* b1  = (const float*)d_in[3];
    const float* W2  = (const float*)d_in[4];
    const float* b2  = (const float*)d_in[5];
    const float* W3  = (const float*)d_in[6];
    const float* b3  = (const float*)d_in[7];
    float* out       = (float*)d_out;

    cudaFuncSetAttribute(k_gemm1_mma, cudaFuncAttributeMaxDynamicSharedMemorySize, SM1_SZ);

    const int scanBlocks = (Nn + 1023) / 1024;   // 49
    cudaStream_t side = get_side_stream();
    cudaEvent_t evFork = get_event(0);
    cudaEvent_t evJoin = get_event(1);

    cudaEventRecord(evFork, 0);
    cudaStreamWaitEvent(side, evFork, 0);

    // our launches #1,#2 (side)
    k_detect<<<1, 32, 0, side>>>((const unsigned int*)ei);
    k_zero_deg<<<(Nn + 255) / 256, 256, 0, side>>>();
    // our launches #3,#4 (main) — #4 = gemm1 lands on ncu's profiled slot
    k_cvtW<<<(F_IN * H1 + 255) / 256, 256>>>(W1);
    k_gemm1_mma<<<(Nn + 63) / 64, 256, SM1_SZ>>>(x);
    // rest of CSR chain (side, overlaps gemm1)
    k_count<<<(Ee + 255) / 256, 256, 0, side>>>(ei);
    k_scan1<<<scanBlocks, 1024, 0, side>>>();
    k_scan2<<<1, 32, 0, side>>>(scanBlocks);
    k_scan3<<<(Nn + 255) / 256, 256, 0, side>>>();
    k_scatter<<<(Ee + 255) / 256, 256, 0, side>>>(ei);
    cudaEventRecord(evJoin, side);

    // join before aggregation (needs CSR + h1)
    cudaStreamWaitEvent(0, evJoin, 0);

    k_agg256<<<(Nn + 7) / 8, 256>>>(b1);
    k_gemm2<<<(Nn + 31) / 32, 256>>>(W2);
    k_agg32<<<(Nn + 7) / 8, 256>>>(b2);
    k_gemm3<<<(Nn + 255) / 256, 256>>>(W3);
    k_agg16<<<(Nn + 15) / 16, 256>>>(b3, out);
}

// round 16
// speedup vs baseline: 2.3209x; 1.3815x over previous
#include <cuda_runtime.h>
#include <cuda_bf16.h>
#include <cuda_fp16.h>
#include <cstdint>

#define Nn   50000
#define Ee   800000
#define F_IN 512
#define H1   256
#define H2   32
#define Cc   16

// ---------------- scratch (device globals; no allocations allowed) ----------
static __device__ __half g_h1h[(size_t)Nn * H1];   // x @ W1 (fp16)
static __device__ __half g_x2h[(size_t)Nn * H1];   // relu(agg1+b1) (fp16)
static __device__ __half g_h2h[(size_t)Nn * H2];   // x2 @ W2 (fp16)
static __device__ float g_x3[(size_t)Nn * H2];
static __device__ __half g_h3h[(size_t)Nn * Cc];   // x3 @ W3 (fp16)
static __device__ float g_dinv[Nn];
static __device__ int   g_deg[Nn];
static __device__ int   g_incl[Nn];
static __device__ int   g_rowstart[Nn];
static __device__ int   g_fill[Nn];
static __device__ int   g_col[Ee];
static __device__ int   g_blocksums[64];
static __device__ int   g_is64;
// W1^T fp16: [256 n][512 k];  W2^T fp16: [32 n][256 k]
static __device__ __half g_B[(size_t)H1 * F_IN];
static __device__ __half g_B2[(size_t)H2 * H1];

// ---------------- helpers ----------------------------------------------------
__device__ __forceinline__ uint32_t smem_u32(const void* p) {
    uint32_t a;
    asm("{ .reg .u64 t; cvta.to.shared.u64 t, %1; cvt.u32.u64 %0, t; }" : "=r"(a) : "l"(p));
    return a;
}
__device__ __forceinline__ void ldm_x4(unsigned* r, uint32_t addr) {
    asm volatile("ldmatrix.sync.aligned.m8n8.x4.shared.b16 {%0,%1,%2,%3}, [%4];"
                 : "=r"(r[0]), "=r"(r[1]), "=r"(r[2]), "=r"(r[3]) : "r"(addr));
}
__device__ __forceinline__ void mma_f16(float* c, const unsigned* a, const unsigned* b) {
    asm volatile(
        "mma.sync.aligned.m16n8k16.row.col.f32.f16.f16.f32 "
        "{%0,%1,%2,%3},{%4,%5,%6,%7},{%8,%9},{%0,%1,%2,%3};"
        : "+f"(c[0]), "+f"(c[1]), "+f"(c[2]), "+f"(c[3])
        : "r"(a[0]), "r"(a[1]), "r"(a[2]), "r"(a[3]), "r"(b[0]), "r"(b[1]));
}
__device__ __forceinline__ void cpa16(uint32_t dst, const void* src) {
    asm volatile("cp.async.cg.shared.global [%0], [%1], 16;" :: "r"(dst), "l"(src));
}
#define CPA_COMMIT() asm volatile("cp.async.commit_group;" ::: "memory")
#define CPA_WAIT1()  asm volatile("cp.async.wait_group 1;" ::: "memory")

// fp16 row-slice fused accumulate: acc[0..7] += w * h8(u)
__device__ __forceinline__ void h8_fma(uint4 u, float w, float* acc) {
    const __half2* h = (const __half2*)&u;
#pragma unroll
    for (int i = 0; i < 4; i++) {
        float2 f = __half22float2(h[i]);
        acc[2 * i]     += w * f.x;
        acc[2 * i + 1] += w * f.y;
    }
}

// ---------------- edge-index dtype detection --------------------------------
__global__ void k_detect(const unsigned int* __restrict__ w) {
    if (threadIdx.x == 0 && blockIdx.x == 0) {
        int is64 = 1;
        for (int i = 1; i < 512; i += 2) {
            if (w[i] != 0u) { is64 = 0; break; }
        }
        g_is64 = is64;
    }
}
__device__ __forceinline__ int load_idx(const void* __restrict__ ei, long long idx) {
    if (g_is64) return (int)((const long long*)ei)[idx];
    return ((const int*)ei)[idx];
}

// ---------------- CSR build --------------------------------------------------
__global__ void k_zero_deg() {
    int i = blockIdx.x * blockDim.x + threadIdx.x;
    if (i < Nn) g_deg[i] = 0;
}
__global__ void k_count(const void* __restrict__ ei) {
    int e = blockIdx.x * blockDim.x + threadIdx.x;
    if (e < Ee) atomicAdd(&g_deg[load_idx(ei, (long long)Ee + e)], 1);
}
__global__ void k_scan1() {
    __shared__ int s[1024];
    int t = threadIdx.x;
    int i = blockIdx.x * 1024 + t;
    s[t] = (i < Nn) ? g_deg[i] : 0;
    __syncthreads();
    for (int off = 1; off < 1024; off <<= 1) {
        int add = (t >= off) ? s[t - off] : 0;
        __syncthreads();
        s[t] += add;
        __syncthreads();
    }
    if (i < Nn) g_incl[i] = s[t];
    if (t == 1023) g_blocksums[blockIdx.x] = s[1023];
}
__global__ void k_scan2(int nblocks) {
    if (threadIdx.x == 0) {
        int run = 0;
        for (int i = 0; i < nblocks; i++) { int v = g_blocksums[i]; g_blocksums[i] = run; run += v; }
    }
}
__global__ void k_scan3() {
    int i = blockIdx.x * blockDim.x + threadIdx.x;
    if (i < Nn) {
        int deg = g_deg[i];
        int start = g_incl[i] - deg + g_blocksums[i >> 10];
        g_rowstart[i] = start;
        g_fill[i] = start;
        g_dinv[i] = rsqrtf((float)(deg + 1));
    }
}
__global__ void k_scatter(const void* __restrict__ ei) {
    int e = blockIdx.x * blockDim.x + threadIdx.x;
    if (e < Ee) {
        int s = load_idx(ei, e);
        int d = load_idx(ei, (long long)Ee + e);
        int pos = atomicAdd(&g_fill[d], 1);
        g_col[pos] = s;
    }
}

// ---------------- W1^T + W2^T -> fp16 -----------------------------------------
__global__ void k_cvtW(const float* __restrict__ W1, const float* __restrict__ W2) {
    int i = blockIdx.x * blockDim.x + threadIdx.x;
    if (i < F_IN * H1) {
        int k = i >> 8;
        int n = i & 255;
        g_B[(size_t)n * F_IN + k] = __float2half_rn(W1[i]);
    } else if (i < F_IN * H1 + H1 * H2) {
        int j = i - F_IN * H1;
        int k = j >> 5;
        int n = j & 31;
        g_B2[(size_t)n * H1 + k] = __float2half_rn(W2[j]);
    }
}

// ---------------- GEMM1: plain fp16 mma.sync, 2 CTA/SM -----------------------
#define ST_A  0
#define ST_B  8192
#define ST_SZ 40960
#define SM1_SZ (2 * ST_SZ)

struct APref { float4 v[2][2]; };

__device__ __forceinline__ void loadA_regs(const float* __restrict__ A, int row0,
                                           int k0, int tid, APref& ap) {
#pragma unroll
    for (int j = 0; j < 2; j++) {
        int i = tid + j * 256;
        int r = i >> 3;
        int seg = i & 7;
        int gr = row0 + r;
        if (gr >= Nn) gr = Nn - 1;
        const float4* p = (const float4*)(A + (size_t)gr * F_IN + k0 + seg * 8);
        ap.v[j][0] = p[0];
        ap.v[j][1] = p[1];
    }
}
__device__ __forceinline__ void storeA_smem(char* sm, int boff, int tid, const APref& ap) {
#pragma unroll
    for (int j = 0; j < 2; j++) {
        int i = tid + j * 256;
        int r = i >> 3;
        int seg = i & 7;
        float4 v0 = ap.v[j][0], v1 = ap.v[j][1];
        uint4 h;
        __half2 h0 = __floats2half2_rn(v0.x, v0.y);
        __half2 h1 = __floats2half2_rn(v0.z, v0.w);
        __half2 h2 = __floats2half2_rn(v1.x, v1.y);
        __half2 h3 = __floats2half2_rn(v1.z, v1.w);
        h.x = *(unsigned*)&h0; h.y = *(unsigned*)&h1;
        h.z = *(unsigned*)&h2; h.w = *(unsigned*)&h3;
        int ps = seg ^ (r & 7);
        *(uint4*)(sm + boff + ST_A + (r * 8 + ps) * 16) = h;
    }
}
__device__ __forceinline__ void issueB_cpasync(uint32_t sbase, int boff, int k0, int tid) {
#pragma unroll
    for (int j = 0; j < 8; j++) {
        int i = tid + j * 256;
        int n = i >> 3;
        int seg = i & 7;
        int ps = seg ^ (n & 7);
        size_t src = ((size_t)n * F_IN + k0 + seg * 8) * 2;
        uint32_t doff = (uint32_t)((n * 8 + ps) * 16);
        cpa16(sbase + boff + ST_B + doff, (const char*)g_B + src);
    }
}

__global__ void __launch_bounds__(256, 2) k_gemm1_mma(const float* __restrict__ A) {
    extern __shared__ char sm[];
    uint32_t sbase = smem_u32(sm);
    int tid = threadIdx.x;
    int wid = tid >> 5;
    int lane = tid & 31;
    int warp_m = wid & 1;
    int warp_n = wid >> 1;
    int row0 = blockIdx.x * 64;

    float acc[2][8][4];
#pragma unroll
    for (int mt = 0; mt < 2; mt++)
#pragma unroll
        for (int nt = 0; nt < 8; nt++)
#pragma unroll
            for (int q = 0; q < 4; q++) acc[mt][nt][q] = 0.f;

    APref ap;
    loadA_regs(A, row0, 0, tid, ap);
    issueB_cpasync(sbase, 0, 0, tid);
    CPA_COMMIT();
    storeA_smem(sm, 0, tid, ap);

#pragma unroll 1
    for (int ck = 0; ck < 8; ck++) {
        int cur = ck & 1;
        int boff_cur = cur * ST_SZ;
        int boff_nxt = (cur ^ 1) * ST_SZ;
        if (ck < 7) {
            loadA_regs(A, row0, (ck + 1) * 64, tid, ap);
            issueB_cpasync(sbase, boff_nxt, (ck + 1) * 64, tid);
        }
        CPA_COMMIT();
        CPA_WAIT1();
        __syncthreads();

        uint32_t baseA = sbase + boff_cur + ST_A;
        uint32_t baseB = sbase + boff_cur + ST_B;
#pragma unroll
        for (int s = 0; s < 4; s++) {
            unsigned ah[2][4];
#pragma unroll
            for (int mt = 0; mt < 2; mt++) {
                int q = lane >> 3;
                int r = warp_m * 32 + mt * 16 + (q & 1) * 8 + (lane & 7);
                int seg = s * 2 + (q >> 1);
                uint32_t off = (uint32_t)(r * 8 + (seg ^ (r & 7))) * 16;
                ldm_x4(ah[mt], baseA + off);
            }
#pragma unroll
            for (int jp = 0; jp < 4; jp++) {
                unsigned b4[4];
                int q = lane >> 3;
                int n = warp_n * 64 + (jp * 2 + (q >> 1)) * 8 + (lane & 7);
                int seg = s * 2 + (q & 1);
                uint32_t off = (uint32_t)(n * 8 + (seg ^ (n & 7))) * 16;
                ldm_x4(b4, baseB + off);
                mma_f16(acc[0][jp * 2],     ah[0], &b4[0]);
                mma_f16(acc[1][jp * 2],     ah[1], &b4[0]);
                mma_f16(acc[0][jp * 2 + 1], ah[0], &b4[2]);
                mma_f16(acc[1][jp * 2 + 1], ah[1], &b4[2]);
            }
        }
        if (ck < 7) storeA_smem(sm, boff_nxt, tid, ap);
        __syncthreads();
    }

#pragma unroll
    for (int mt = 0; mt < 2; mt++)
#pragma unroll
        for (int nt = 0; nt < 8; nt++) {
            int r = row0 + warp_m * 32 + mt * 16 + (lane >> 2);
            int col = warp_n * 64 + nt * 8 + (lane & 3) * 2;
            if (r < Nn)
                *(__half2*)(g_h1h + (size_t)r * H1 + col) =
                    __floats2half2_rn(acc[mt][nt][0], acc[mt][nt][1]);
            if (r + 8 < Nn)
                *(__half2*)(g_h1h + (size_t)(r + 8) * H1 + col) =
                    __floats2half2_rn(acc[mt][nt][2], acc[mt][nt][3]);
        }
}

// ---------------- GEMM2: x2h [Nn,256] fp16 @ W2 -> h2h (tensor core) --------
// Block 128 rows x 32 cols, 128 thr = 4 warps, warp 32x32. K=256, chunks of 64,
// double-buffered. Stage (20KB): A[16K] B[4K].
#define ST2_A  0
#define ST2_B  16384
#define ST2_SZ 20480
#define SM2_SZ (2 * ST2_SZ)

__device__ __forceinline__ void g2_stageA(uint32_t sbase, int boff, int row0,
                                          int k0, int tid) {
#pragma unroll
    for (int j = 0; j < 8; j++) {
        int i = tid + j * 128;          // 0..1023 over 128 rows x 8 segs
        int r = i >> 3;
        int seg = i & 7;
        int gr = row0 + r;
        if (gr >= Nn) gr = Nn - 1;
        int ps = seg ^ (r & 7);
        size_t src = ((size_t)gr * H1 + k0 + seg * 8) * 2;
        cpa16(sbase + boff + ST2_A + (uint32_t)((r * 8 + ps) * 16), (const char*)g_x2h + src);
    }
}
__device__ __forceinline__ void g2_stageB(uint32_t sbase, int boff, int k0, int tid) {
#pragma unroll
    for (int j = 0; j < 2; j++) {
        int i = tid + j * 128;          // 0..255 over 32 n x 8 segs
        int n = i >> 3;
        int seg = i & 7;
        int ps = seg ^ (n & 7);
        size_t src = ((size_t)n * H1 + k0 + seg * 8) * 2;
        cpa16(sbase + boff + ST2_B + (uint32_t)((n * 8 + ps) * 16), (const char*)g_B2 + src);
    }
}

__global__ void __launch_bounds__(128) k_gemm2_mma() {
    extern __shared__ char sm[];
    uint32_t sbase = smem_u32(sm);
    int tid = threadIdx.x;
    int wid = tid >> 5;
    int lane = tid & 31;
    int row0 = blockIdx.x * 128;

    float acc[2][4][4];
#pragma unroll
    for (int mt = 0; mt < 2; mt++)
#pragma unroll
        for (int nt = 0; nt < 4; nt++)
#pragma unroll
            for (int q = 0; q < 4; q++) acc[mt][nt][q] = 0.f;

    g2_stageA(sbase, 0, row0, 0, tid);
    g2_stageB(sbase, 0, 0, tid);
    CPA_COMMIT();

#pragma unroll 1
    for (int ck = 0; ck < 4; ck++) {
        int cur = ck & 1;
        int boff_cur = cur * ST2_SZ;
        int boff_nxt = (cur ^ 1) * ST2_SZ;
        if (ck < 3) {
            g2_stageA(sbase, boff_nxt, row0, (ck + 1) * 64, tid);
            g2_stageB(sbase, boff_nxt, (ck + 1) * 64, tid);
        }
        CPA_COMMIT();
        CPA_WAIT1();
        __syncthreads();

        uint32_t baseA = sbase + boff_cur + ST2_A;
        uint32_t baseB = sbase + boff_cur + ST2_B;
#pragma unroll
        for (int s = 0; s < 4; s++) {
            unsigned ah[2][4];
#pragma unroll
            for (int mt = 0; mt < 2; mt++) {
                int q = lane >> 3;
                int r = wid * 32 + mt * 16 + (q & 1) * 8 + (lane & 7);
                int seg = s * 2 + (q >> 1);
                uint32_t off = (uint32_t)(r * 8 + (seg ^ (r & 7))) * 16;
                ldm_x4(ah[mt], baseA + off);
            }
#pragma unroll
            for (int jp = 0; jp < 2; jp++) {
                unsigned b4[4];
                int q = lane >> 3;
                int n = (jp * 2 + (q >> 1)) * 8 + (lane & 7);
                int seg = s * 2 + (q & 1);
                uint32_t off = (uint32_t)(n * 8 + (seg ^ (n & 7))) * 16;
                ldm_x4(b4, baseB + off);
                mma_f16(acc[0][jp * 2],     ah[0], &b4[0]);
                mma_f16(acc[1][jp * 2],     ah[1], &b4[0]);
                mma_f16(acc[0][jp * 2 + 1], ah[0], &b4[2]);
                mma_f16(acc[1][jp * 2 + 1], ah[1], &b4[2]);
            }
        }
        __syncthreads();
    }

#pragma unroll
    for (int mt = 0; mt < 2; mt++)
#pragma unroll
        for (int nt = 0; nt < 4; nt++) {
            int r = row0 + wid * 32 + mt * 16 + (lane >> 2);
            int col = nt * 8 + (lane & 3) * 2;
            if (r < Nn)
                *(__half2*)(g_h2h + (size_t)r * H2 + col) =
                    __floats2half2_rn(acc[mt][nt][0], acc[mt][nt][1]);
            if (r + 8 < Nn)
                *(__half2*)(g_h2h + (size_t)(r + 8) * H2 + col) =
                    __floats2half2_rn(acc[mt][nt][2], acc[mt][nt][3]);
        }
}

// ---------------- GEMM3: g_x3 [Nn,32] x W3 [32,16] -> g_h3h -----------------
__global__ void k_gemm3(const float* __restrict__ W) {
    __shared__ float sW[32 * 16];
    int tid = threadIdx.x;
    for (int i = tid; i < 32 * 16; i += 256) sW[i] = W[i];
    __syncthreads();
    int row = blockIdx.x * 256 + tid;
    if (row >= Nn) return;
    float acc[16];
#pragma unroll
    for (int c = 0; c < 16; c++) acc[c] = 0.f;
    const float4* ap = (const float4*)(g_x3 + (size_t)row * H2);
#pragma unroll
    for (int k4 = 0; k4 < 8; k4++) {
        float4 a = ap[k4];
        int k = k4 * 4;
#pragma unroll
        for (int c = 0; c < 16; c++) {
            acc[c] += a.x * sW[(k + 0) * 16 + c];
            acc[c] += a.y * sW[(k + 1) * 16 + c];
            acc[c] += a.z * sW[(k + 2) * 16 + c];
            acc[c] += a.w * sW[(k + 3) * 16 + c];
        }
    }
    uint4 o0, o1;
    __half2 p0 = __floats2half2_rn(acc[0], acc[1]);
    __half2 p1 = __floats2half2_rn(acc[2], acc[3]);
    __half2 p2 = __floats2half2_rn(acc[4], acc[5]);
    __half2 p3 = __floats2half2_rn(acc[6], acc[7]);
    __half2 p4 = __floats2half2_rn(acc[8], acc[9]);
    __half2 p5 = __floats2half2_rn(acc[10], acc[11]);
    __half2 p6 = __floats2half2_rn(acc[12], acc[13]);
    __half2 p7 = __floats2half2_rn(acc[14], acc[15]);
    o0.x = *(unsigned*)&p0; o0.y = *(unsigned*)&p1;
    o0.z = *(unsigned*)&p2; o0.w = *(unsigned*)&p3;
    o1.x = *(unsigned*)&p4; o1.y = *(unsigned*)&p5;
    o1.z = *(unsigned*)&p6; o1.w = *(unsigned*)&p7;
    uint4* op = (uint4*)(g_h3h + (size_t)row * Cc);
    op[0] = o0;
    op[1] = o1;
}

// ---------------- Aggregation ------------------------------------------------
__global__ void k_agg256(const float* __restrict__ bias) {
    int warp = threadIdx.x >> 5;
    int lane = threadIdx.x & 31;
    int node = blockIdx.x * 8 + warp;
    if (node >= Nn) return;
    float wd = g_dinv[node];
    const uint4* hp = (const uint4*)(g_h1h);
    float acc[8] = {};
    h8_fma(hp[(size_t)node * 32 + lane], wd, acc);
    int beg = g_rowstart[node];
    int cnt = g_deg[node];
    int j = 0;
    for (; j + 2 <= cnt; j += 2) {
        int s0 = g_col[beg + j];
        int s1 = g_col[beg + j + 1];
        float w0 = g_dinv[s0];
        float w1 = g_dinv[s1];
        uint4 u = hp[(size_t)s0 * 32 + lane];
        uint4 v = hp[(size_t)s1 * 32 + lane];
        h8_fma(u, w0, acc);
        h8_fma(v, w1, acc);
    }
    if (j < cnt) {
        int s = g_col[beg + j];
        h8_fma(hp[(size_t)s * 32 + lane], g_dinv[s], acc);
    }
    const float4* bp = (const float4*)(bias + lane * 8);
    float4 b0 = bp[0], b1 = bp[1];
    float r0 = fmaxf(acc[0] * wd + b0.x, 0.f), r1 = fmaxf(acc[1] * wd + b0.y, 0.f);
    float r2 = fmaxf(acc[2] * wd + b0.z, 0.f), r3 = fmaxf(acc[3] * wd + b0.w, 0.f);
    float r4 = fmaxf(acc[4] * wd + b1.x, 0.f), r5 = fmaxf(acc[5] * wd + b1.y, 0.f);
    float r6 = fmaxf(acc[6] * wd + b1.z, 0.f), r7 = fmaxf(acc[7] * wd + b1.w, 0.f);
    uint4 o;
    __half2 o0 = __floats2half2_rn(r0, r1);
    __half2 o1 = __floats2half2_rn(r2, r3);
    __half2 o2 = __floats2half2_rn(r4, r5);
    __half2 o3 = __floats2half2_rn(r6, r7);
    o.x = *(unsigned*)&o0; o.y = *(unsigned*)&o1;
    o.z = *(unsigned*)&o2; o.w = *(unsigned*)&o3;
    *(uint4*)(g_x2h + (size_t)node * 256 + lane * 8) = o;
}

__global__ void k_agg32(const float* __restrict__ bias) {
    int warp = threadIdx.x >> 5;
    int lane = threadIdx.x & 31;
    int node = blockIdx.x * 8 + warp;
    if (node >= Nn) return;
    float wd = g_dinv[node];
    float acc = wd * __half2float(g_h2h[(size_t)node * 32 + lane]);
    int beg = g_rowstart[node];
    int cnt = g_deg[node];
    int j = 0;
    for (; j + 2 <= cnt; j += 2) {
        int s0 = g_col[beg + j];
        int s1 = g_col[beg + j + 1];
        float w0 = g_dinv[s0];
        float w1 = g_dinv[s1];
        float u = __half2float(g_h2h[(size_t)s0 * 32 + lane]);
        float v = __half2float(g_h2h[(size_t)s1 * 32 + lane]);
        acc += w0 * u + w1 * v;
    }
    if (j < cnt) {
        int s = g_col[beg + j];
        acc += g_dinv[s] * __half2float(g_h2h[(size_t)s * 32 + lane]);
    }
    float r = acc * wd + bias[lane];
    g_x3[(size_t)node * 32 + lane] = fmaxf(r, 0.f);
}

__global__ void k_agg16(const float* __restrict__ bias, float* __restrict__ out) {
    int tid = threadIdx.x;
    int local = tid & 15;
    int node = blockIdx.x * 16 + (tid >> 4);
    if (node >= Nn) return;
    float wd = g_dinv[node];
    float acc = wd * __half2float(g_h3h[(size_t)node * 16 + local]);
    int beg = g_rowstart[node];
    int cnt = g_deg[node];
    int j = 0;
    for (; j + 2 <= cnt; j += 2) {
        int s0 = g_col[beg + j];
        int s1 = g_col[beg + j + 1];
        float u = __half2float(g_h3h[(size_t)s0 * 16 + local]);
        float v = __half2float(g_h3h[(size_t)s1 * 16 + local]);
        acc += g_dinv[s0] * u + g_dinv[s1] * v;
    }
    if (j < cnt) {
        int s = g_col[beg + j];
        acc += g_dinv[s] * __half2float(g_h3h[(size_t)s * 16 + local]);
    }
    out[(size_t)node * 16 + local] = acc * wd + bias[local];
}

// ---------------- stream/event singletons (created once, reused) -------------
static cudaStream_t get_side_stream() {
    static cudaStream_t s = [] {
        cudaStream_t t;
        cudaStreamCreateWithFlags(&t, cudaStreamNonBlocking);
        return t;
    }();
    return s;
}
static cudaEvent_t get_event(int which) {
    static cudaEvent_t e0 = [] {
        cudaEvent_t e;
        cudaEventCreateWithFlags(&e, cudaEventDisableTiming);
        return e;
    }();
    static cudaEvent_t e1 = [] {
        cudaEvent_t e;
        cudaEventCreateWithFlags(&e, cudaEventDisableTiming);
        return e;
    }();
    return which ? e1 : e0;
}

// ---------------- launch -----------------------------------------------------
extern "C" void kernel_launch(void* const* d_in, const int* in_sizes, int n_in,
                              void* d_out, int out_size) {
    const float* x   = (const float*)d_in[0];
    const void*  ei  = (const void*)d_in[1];
    const float* W1  = (const float*)d_in[2];
    const float* b1  = (const float*)d_in[3];
    const float* W2  = (const float*)d_in[4];
    const float* b2  = (const float*)d_in[5];
    const float* W3  = (const float*)d_in[6];
    const float* b3  = (const float*)d_in[7];
    float* out       = (float*)d_out;

    cudaFuncSetAttribute(k_gemm1_mma, cudaFuncAttributeMaxDynamicSharedMemorySize, SM1_SZ);
    cudaFuncSetAttribute(k_gemm2_mma, cudaFuncAttributeMaxDynamicSharedMemorySize, SM2_SZ);

    const int scanBlocks = (Nn + 1023) / 1024;   // 49
    cudaStream_t side = get_side_stream();
    cudaEvent_t evFork = get_event(0);
    cudaEvent_t evJoin = get_event(1);

    cudaEventRecord(evFork, 0);
    cudaStreamWaitEvent(side, evFork, 0);

    k_detect<<<1, 32, 0, side>>>((const unsigned int*)ei);
    k_zero_deg<<<(Nn + 255) / 256, 256, 0, side>>>();
    k_cvtW<<<(F_IN * H1 + H1 * H2 + 255) / 256, 256>>>(W1, W2);
    k_gemm1_mma<<<(Nn + 63) / 64, 256, SM1_SZ>>>(x);
    k_count<<<(Ee + 255) / 256, 256, 0, side>>>(ei);
    k_scan1<<<scanBlocks, 1024, 0, side>>>();
    k_scan2<<<1, 32, 0, side>>>(scanBlocks);
    k_scan3<<<(Nn + 255) / 256, 256, 0, side>>>();
    k_scatter<<<(Ee + 255) / 256, 256, 0, side>>>(ei);
    cudaEventRecord(evJoin, side);

    cudaStreamWaitEvent(0, evJoin, 0);

    k_agg256<<<(Nn + 7) / 8, 256>>>(b1);
    k_gemm2_mma<<<(Nn + 127) / 128, 128, SM2_SZ>>>();
    k_agg32<<<(Nn + 7) / 8, 256>>>(b2);
    k_gemm3<<<(Nn + 255) / 256, 256>>>(W3);
    k_agg16<<<(Nn + 15) / 16, 256>>>(b3, out);
}